// round 4
// baseline (speedup 1.0000x reference)
#include <cuda_runtime.h>
#include <cstdint>
#include <cstddef>

// ---------------------------------------------------------------------------
// MultiheadedAttention2 (batch-axis softmax quirk) — tf32 mma.sync v4:
//   * 512-thread / 16-warp GEMM CTA (4 warps per SMSP for latency hiding)
//   * operands pre-rounded to exact tf32, K permuted -> LDS.128 fragments
//   * 4-stage cp.async pipeline, ONE barrier per k-tile
// ---------------------------------------------------------------------------

#define B_SZ 8
#define T_SZ 2048
#define E_SZ 512
#define HE_SZ 4096
#define SCALE_F 0.04419417382415922f  // 512^-0.5

#define STAGES 4
#define STAGE_FLOATS 9216          // A: 128*36 + B: 128*36
#define SMEM_BYTES (STAGES * STAGE_FLOATS * 4)  // 147456

// Scratch (device globals; allocation-free rule)
__device__ float g_q[(size_t)B_SZ * T_SZ * HE_SZ];     // rounded+permuted(HE)
__device__ float g_k[(size_t)B_SZ * T_SZ * HE_SZ];     // rounded+permuted(HE)
__device__ float g_v[(size_t)B_SZ * T_SZ * HE_SZ];     // plain fp32
__device__ float g_vT[(size_t)B_SZ * HE_SZ * T_SZ];    // rounded+permuted(T)
__device__ float g_att[(size_t)B_SZ * T_SZ * T_SZ];    // logits then att (r+p)
__device__ float g_att2[(size_t)B_SZ * T_SZ * HE_SZ];  // rounded+permuted(HE)
__device__ float g_rkey[(size_t)B_SZ * T_SZ * E_SZ];
__device__ float g_rqry[(size_t)B_SZ * T_SZ * E_SZ];
__device__ float g_rval[(size_t)B_SZ * T_SZ * E_SZ];
__device__ float g_rWk[(size_t)HE_SZ * E_SZ];
__device__ float g_rWq[(size_t)HE_SZ * E_SZ];
__device__ float g_rWv[(size_t)HE_SZ * E_SZ];
__device__ float g_rWo[(size_t)E_SZ * HE_SZ];

static __device__ __forceinline__ float f2tf32f(float x) {
    uint32_t u;
    asm volatile("cvt.rna.tf32.f32 %0, %1;" : "=r"(u) : "f"(x));
    return __uint_as_float(u);
}

static __device__ __forceinline__ void mma_tf32(float* c, const float* a, const float* b) {
    asm volatile(
        "mma.sync.aligned.m16n8k8.row.col.f32.tf32.tf32.f32 "
        "{%0,%1,%2,%3}, {%4,%5,%6,%7}, {%8,%9}, {%0,%1,%2,%3};\n"
        : "+f"(c[0]), "+f"(c[1]), "+f"(c[2]), "+f"(c[3])
        : "r"(__float_as_uint(a[0])), "r"(__float_as_uint(a[1])),
          "r"(__float_as_uint(a[2])), "r"(__float_as_uint(a[3])),
          "r"(__float_as_uint(b[0])), "r"(__float_as_uint(b[1])));
}

static __device__ __forceinline__ void cp_async16(float* smem_dst, const float* gptr) {
    uint32_t s = (uint32_t)__cvta_generic_to_shared(smem_dst);
    asm volatile("cp.async.cg.shared.global [%0], [%1], 16;\n" :: "r"(s), "l"(gptr));
}
static __device__ __forceinline__ void cp_commit() {
    asm volatile("cp.async.commit_group;\n");
}
template <int N>
static __device__ __forceinline__ void cp_wait() {
    asm volatile("cp.async.wait_group %0;\n" :: "n"(N));
}

// ---------------------------------------------------------------------------
// GEMM: C[M,N] = alpha * A @ B^T (+ bias). A [M,K], B [N,K], row-major,
// ALREADY rounded to tf32 + K-permuted within 32-groups (pos(k)=(k&3)*8+(k>>2)).
// PERM_OUT: C written rounded + N-permuted (feeds a later GEMM as operand).
// 512 threads: 16 warps = 4(M) x 4(N), warp tile 32x32.
// ---------------------------------------------------------------------------
template <bool PERM_OUT, bool HAS_BIAS>
__global__ __launch_bounds__(512, 1)
void gemm_tf32(const float* __restrict__ A, const float* __restrict__ Bm,
               const float* __restrict__ bias, float* __restrict__ C,
               int M, int N, int K, float alpha,
               long long sA, long long sB, long long sC)
{
    extern __shared__ float smem[];

    const float* Ab = A + (long long)blockIdx.z * sA;
    const float* Bb = Bm + (long long)blockIdx.z * sB;
    float* Cb = C + (long long)blockIdx.z * sC;

    const int bm = blockIdx.y * 128;
    const int bn = blockIdx.x * 128;
    const int tid = threadIdx.x;
    const int lane = tid & 31;
    const int warp = tid >> 5;        // 0..15
    const int wm = (warp & 3) * 32;   // 4 warps down M
    const int wn = (warp >> 2) * 32;  // 4 warps across N
    const int gr = lane >> 2;         // 0..7
    const int gc = lane & 3;          // 0..3

    float acc[2][4][4];
#pragma unroll
    for (int i = 0; i < 2; ++i)
#pragma unroll
        for (int j = 0; j < 4; ++j)
#pragma unroll
            for (int r = 0; r < 4; ++r) acc[i][j][r] = 0.f;

    const int ldrow = tid >> 3;        // 0..63
    const int ldcol = (tid & 7) << 2;  // 0..28

    const int nk = K >> 5;

    auto load_tile = [&](int kt, int stage) {
        float* sA = smem + stage * STAGE_FLOATS;
        float* sB = sA + 4608;
        const int k0g = kt << 5;
#pragma unroll
        for (int p = 0; p < 2; ++p) {
            const int r = ldrow + p * 64;
            cp_async16(sA + r * 36 + ldcol, Ab + (size_t)(bm + r) * K + (k0g + ldcol));
            cp_async16(sB + r * 36 + ldcol, Bb + (size_t)(bn + r) * K + (k0g + ldcol));
        }
    };

#pragma unroll
    for (int s = 0; s < STAGES - 1; ++s) {
        if (s < nk) load_tile(s, s);
        cp_commit();
    }

    for (int kt = 0; kt < nk; ++kt) {
        const int stage = kt & (STAGES - 1);
        cp_wait<STAGES - 2>();
        __syncthreads();   // single barrier per tile (orders stage reuse too)

        const int pf = kt + STAGES - 1;
        if (pf < nk) load_tile(pf, pf & (STAGES - 1));
        cp_commit();

        const float* sA = smem + stage * STAGE_FLOATS;
        const float* sB = sA + 4608;

        // Permuted layout: float4 at [row][gc*8 + h*4] holds k = 16h + {0,4,8,12} + gc
#pragma unroll
        for (int h = 0; h < 2; ++h) {
            float4 av[2][2];
#pragma unroll
            for (int i = 0; i < 2; ++i) {
                const int r = wm + i * 16 + gr;
                av[i][0] = *reinterpret_cast<const float4*>(sA + (size_t)r * 36 + gc * 8 + h * 4);
                av[i][1] = *reinterpret_cast<const float4*>(sA + (size_t)(r + 8) * 36 + gc * 8 + h * 4);
            }
            float4 bv[4];
#pragma unroll
            for (int j = 0; j < 4; ++j) {
                const int cn = wn + j * 8 + gr;
                bv[j] = *reinterpret_cast<const float4*>(sB + (size_t)cn * 36 + gc * 8 + h * 4);
            }
#pragma unroll
            for (int i = 0; i < 2; ++i) {
                const float alo[4] = {av[i][0].x, av[i][1].x, av[i][0].y, av[i][1].y};
                const float ahi[4] = {av[i][0].z, av[i][1].z, av[i][0].w, av[i][1].w};
#pragma unroll
                for (int j = 0; j < 4; ++j) {
                    const float blo[2] = {bv[j].x, bv[j].y};
                    mma_tf32(acc[i][j], alo, blo);
                }
#pragma unroll
                for (int j = 0; j < 4; ++j) {
                    const float bhi[2] = {bv[j].z, bv[j].w};
                    mma_tf32(acc[i][j], ahi, bhi);
                }
            }
        }
    }

    __syncthreads();  // all tiles done before epilogue (and smem reuse)

    if (PERM_OUT) {
        // Stage C tile in smem, then emit rounded + N-permuted coalesced float4s.
        float* cs = smem;  // [128][132]
#pragma unroll
        for (int i = 0; i < 2; ++i) {
#pragma unroll
            for (int j = 0; j < 4; ++j) {
                const int r = wm + i * 16 + gr;
                const int c = wn + j * 8 + gc * 2;
                float v0 = acc[i][j][0] * alpha;
                float v1 = acc[i][j][1] * alpha;
                float v2 = acc[i][j][2] * alpha;
                float v3 = acc[i][j][3] * alpha;
                if (HAS_BIAS) {
                    const float b0 = bias[bn + c], b1 = bias[bn + c + 1];
                    v0 += b0; v1 += b1; v2 += b0; v3 += b1;
                }
                cs[(size_t)r * 132 + c] = v0;
                cs[(size_t)r * 132 + c + 1] = v1;
                cs[(size_t)(r + 8) * 132 + c] = v2;
                cs[(size_t)(r + 8) * 132 + c + 1] = v3;
            }
        }
        __syncthreads();
        const int orow = tid >> 2;          // 0..127
        const int oquad = tid & 3;
        const int ohalf = oquad & 1;
        const int mb = oquad >> 1;
#pragma unroll
        for (int f = 0; f < 8; ++f) {
            const int m = mb + f * 2;               // 0..15
            const int colb = ohalf * 4 + m * 8;     // permuted output col base
            const int srcbase = (m >> 2) * 32 + ohalf * 16 + (m & 3);
            float4 o;
            o.x = f2tf32f(cs[(size_t)orow * 132 + srcbase]);
            o.y = f2tf32f(cs[(size_t)orow * 132 + srcbase + 4]);
            o.z = f2tf32f(cs[(size_t)orow * 132 + srcbase + 8]);
            o.w = f2tf32f(cs[(size_t)orow * 132 + srcbase + 12]);
            *reinterpret_cast<float4*>(Cb + (size_t)(bm + orow) * N + bn + colb) = o;
        }
    } else {
#pragma unroll
        for (int i = 0; i < 2; ++i) {
#pragma unroll
            for (int j = 0; j < 4; ++j) {
                const int row = bm + wm + i * 16 + gr;
                const int col = bn + wn + j * 8 + gc * 2;
                float v0 = acc[i][j][0] * alpha;
                float v1 = acc[i][j][1] * alpha;
                float v2 = acc[i][j][2] * alpha;
                float v3 = acc[i][j][3] * alpha;
                if (HAS_BIAS) {
                    const float b0 = bias[col], b1 = bias[col + 1];
                    v0 += b0; v1 += b1; v2 += b0; v3 += b1;
                }
                Cb[(size_t)row * N + col] = v0;
                Cb[(size_t)row * N + col + 1] = v1;
                Cb[(size_t)(row + 8) * N + col] = v2;
                Cb[(size_t)(row + 8) * N + col + 1] = v3;
            }
        }
    }
}

// Round to tf32 + permute K within 32-groups (flat; rows are multiples of 32).
__global__ void round_perm(const float* __restrict__ in, float* __restrict__ out, long long n4)
{
    const long long i = (long long)blockIdx.x * blockDim.x + threadIdx.x;
    if (i >= n4) return;
    const long long q = i * 4;
    const long long base = q & ~31LL;
    const int p = (int)(q & 31);
    const int src = (p & 7) * 4 + (p >> 3);
    float4 o;
    o.x = f2tf32f(in[base + src]);
    o.y = f2tf32f(in[base + src + 4]);
    o.z = f2tf32f(in[base + src + 8]);
    o.w = f2tf32f(in[base + src + 12]);
    *reinterpret_cast<float4*>(out + q) = o;
}

// Softmax across batch axis (8 entries), output rounded + s-permuted.
__global__ void softmax_b8(float* __restrict__ d, int plane)
{
    const int i = blockIdx.x * blockDim.x + threadIdx.x;  // float4 index
    if (i >= plane / 4) return;
    const int s = i * 4;
    float4 v[B_SZ];
    float4 m = make_float4(-1e30f, -1e30f, -1e30f, -1e30f);
#pragma unroll
    for (int b = 0; b < B_SZ; ++b) {
        v[b] = *reinterpret_cast<const float4*>(d + (size_t)b * plane + s);
        m.x = fmaxf(m.x, v[b].x); m.y = fmaxf(m.y, v[b].y);
        m.z = fmaxf(m.z, v[b].z); m.w = fmaxf(m.w, v[b].w);
    }
    float4 sum = make_float4(0.f, 0.f, 0.f, 0.f);
#pragma unroll
    for (int b = 0; b < B_SZ; ++b) {
        v[b].x = __expf(v[b].x - m.x); sum.x += v[b].x;
        v[b].y = __expf(v[b].y - m.y); sum.y += v[b].y;
        v[b].z = __expf(v[b].z - m.z); sum.z += v[b].z;
        v[b].w = __expf(v[b].w - m.w); sum.w += v[b].w;
    }
    sum.x = 1.f / sum.x; sum.y = 1.f / sum.y; sum.z = 1.f / sum.z; sum.w = 1.f / sum.w;
    const int base = s & ~31;
    const int p0 = (s & 31) >> 2;  // pos(s+e) = e*8 + p0
#pragma unroll
    for (int b = 0; b < B_SZ; ++b) {
        float* o = d + (size_t)b * plane + base + p0;
        o[0] = f2tf32f(v[b].x * sum.x);
        o[8] = f2tf32f(v[b].y * sum.y);
        o[16] = f2tf32f(v[b].z * sum.z);
        o[24] = f2tf32f(v[b].w * sum.w);
    }
}

// vT[b][h][perm(s)] = rna(v[b][s][h]).  32x32 tiles, block (32,8).
__global__ void transpose_rp(const float* __restrict__ v, float* __restrict__ vT)
{
    __shared__ float sm[32][33];
    const int b = blockIdx.z;
    const int h0 = blockIdx.x * 32;
    const int s0 = blockIdx.y * 32;
    const int tx = threadIdx.x, ty = threadIdx.y;
#pragma unroll
    for (int q = 0; q < 4; ++q)
        sm[ty + q * 8][tx] = v[((size_t)b * T_SZ + s0 + ty + q * 8) * HE_SZ + h0 + tx];
    __syncthreads();
    const int ps = (tx & 3) * 8 + (tx >> 2);  // pos(tx)
#pragma unroll
    for (int q = 0; q < 4; ++q)
        vT[(size_t)b * HE_SZ * T_SZ + (size_t)(h0 + ty + q * 8) * T_SZ + s0 + ps] =
            f2tf32f(sm[tx][ty + q * 8]);
}

extern "C" void kernel_launch(void* const* d_in, const int* in_sizes, int n_in,
                              void* d_out, int out_size)
{
    (void)in_sizes; (void)n_in; (void)out_size;
    const float* key   = (const float*)d_in[0];
    const float* value = (const float*)d_in[1];
    const float* query = (const float*)d_in[2];
    const float* Wk = (const float*)d_in[3];
    const float* bk = (const float*)d_in[4];
    const float* Wv = (const float*)d_in[5];
    const float* bv = (const float*)d_in[6];
    const float* Wq = (const float*)d_in[7];
    const float* bq = (const float*)d_in[8];
    const float* Wo = (const float*)d_in[9];
    const float* bo = (const float*)d_in[10];
    float* out = (float*)d_out;

    float *q, *k, *v, *vT, *att, *att2;
    float *rkey, *rqry, *rval, *rWk, *rWq, *rWv, *rWo;
    cudaGetSymbolAddress((void**)&q, g_q);
    cudaGetSymbolAddress((void**)&k, g_k);
    cudaGetSymbolAddress((void**)&v, g_v);
    cudaGetSymbolAddress((void**)&vT, g_vT);
    cudaGetSymbolAddress((void**)&att, g_att);
    cudaGetSymbolAddress((void**)&att2, g_att2);
    cudaGetSymbolAddress((void**)&rkey, g_rkey);
    cudaGetSymbolAddress((void**)&rqry, g_rqry);
    cudaGetSymbolAddress((void**)&rval, g_rval);
    cudaGetSymbolAddress((void**)&rWk, g_rWk);
    cudaGetSymbolAddress((void**)&rWq, g_rWq);
    cudaGetSymbolAddress((void**)&rWv, g_rWv);
    cudaGetSymbolAddress((void**)&rWo, g_rWo);

    cudaFuncSetAttribute((const void*)gemm_tf32<false, false>,
                         cudaFuncAttributeMaxDynamicSharedMemorySize, SMEM_BYTES);
    cudaFuncSetAttribute((const void*)gemm_tf32<false, true>,
                         cudaFuncAttributeMaxDynamicSharedMemorySize, SMEM_BYTES);
    cudaFuncSetAttribute((const void*)gemm_tf32<true, false>,
                         cudaFuncAttributeMaxDynamicSharedMemorySize, SMEM_BYTES);
    cudaFuncSetAttribute((const void*)gemm_tf32<true, true>,
                         cudaFuncAttributeMaxDynamicSharedMemorySize, SMEM_BYTES);

    const int MT = B_SZ * T_SZ;  // 16384
    const dim3 blk(512);

    // 0) round + permute all raw GEMM operands
    {
        const long long nin = (long long)MT * E_SZ / 4;
        round_perm<<<(unsigned)((nin + 255) / 256), 256>>>(key, rkey, nin);
        round_perm<<<(unsigned)((nin + 255) / 256), 256>>>(query, rqry, nin);
        round_perm<<<(unsigned)((nin + 255) / 256), 256>>>(value, rval, nin);
        const long long nw = (long long)HE_SZ * E_SZ / 4;
        round_perm<<<(unsigned)((nw + 255) / 256), 256>>>(Wk, rWk, nw);
        round_perm<<<(unsigned)((nw + 255) / 256), 256>>>(Wq, rWq, nw);
        round_perm<<<(unsigned)((nw + 255) / 256), 256>>>(Wv, rWv, nw);
        round_perm<<<(unsigned)((nw + 255) / 256), 256>>>(Wo, rWo, nw);
    }
    // 1) projections: [16384,512] @ [4096,512]^T + bias
    {
        dim3 grid(HE_SZ / 128, MT / 128, 1);
        gemm_tf32<true, true><<<grid, blk, SMEM_BYTES>>>(rkey, rWk, bk, k, MT, HE_SZ, E_SZ, 1.f, 0, 0, 0);
        gemm_tf32<true, true><<<grid, blk, SMEM_BYTES>>>(rqry, rWq, bq, q, MT, HE_SZ, E_SZ, 1.f, 0, 0, 0);
        gemm_tf32<false, true><<<grid, blk, SMEM_BYTES>>>(rval, rWv, bv, v, MT, HE_SZ, E_SZ, 1.f, 0, 0, 0);
    }
    // 2) transpose v -> vT (rounded + permuted along s)
    {
        dim3 grid(HE_SZ / 32, T_SZ / 32, B_SZ);
        transpose_rp<<<grid, dim3(32, 8)>>>(v, vT);
    }
    // 3) logits: per batch [2048,4096] @ [2048,4096]^T * SCALE (plain out)
    {
        dim3 grid(T_SZ / 128, T_SZ / 128, B_SZ);
        const long long sqk = (long long)T_SZ * HE_SZ;
        const long long sp = (long long)T_SZ * T_SZ;
        gemm_tf32<false, false><<<grid, blk, SMEM_BYTES>>>(q, k, nullptr, att, T_SZ, T_SZ, HE_SZ,
                                                           SCALE_F, sqk, sqk, sp);
    }
    // 4) batch-axis softmax (rounded + permuted out)
    {
        const int plane = T_SZ * T_SZ;
        softmax_b8<<<(plane / 4) / 256, 256>>>(att, plane);
    }
    // 5) attend: per batch [2048,2048] @ ([4096,2048])^T -> att2 (perm out)
    {
        dim3 grid(HE_SZ / 128, T_SZ / 128, B_SZ);
        const long long sp = (long long)T_SZ * T_SZ;
        const long long sv = (long long)T_SZ * HE_SZ;
        gemm_tf32<true, false><<<grid, blk, SMEM_BYTES>>>(att, vT, nullptr, att2, T_SZ, HE_SZ, T_SZ,
                                                          1.f, sp, sv, sv);
    }
    // 6) output projection: [16384,4096] @ [512,4096]^T + bias (plain out)
    {
        dim3 grid(E_SZ / 128, MT / 128, 1);
        gemm_tf32<false, true><<<grid, blk, SMEM_BYTES>>>(att2, rWo, bo, out, MT, E_SZ, HE_SZ, 1.f, 0, 0, 0);
    }
}

// round 5
// speedup vs baseline: 4.3687x; 4.3687x over previous
#include <cuda_runtime.h>
#include <cstdint>
#include <cstddef>

// ---------------------------------------------------------------------------
// MultiheadedAttention2 (batch-axis softmax) — v5: algebraic FLOP reduction.
//   prod = query@(Wq^T Wk)@key^T + u[t] + w[s] + c          (u,w,c exact fp32)
//   att  = softmax_b(prod*SCALE)
//   out  = att@(value@P^T) + rowsum(att) (x) (Wo bv) + bo,   P = Wo Wv
// 825 GF -> ~90 GF. GEMMs: tf32 mma.sync (R2 variant: 256 thr, 4-stage
// cp.async, cvt at fragment load), with fused epilogues.
// ---------------------------------------------------------------------------

#define B_SZ 8
#define T_SZ 2048
#define E_SZ 512
#define HE_SZ 4096
#define SCALE_F 0.04419417382415922f  // 512^-0.5

#define STAGES 4
#define STAGE_FLOATS 9216
#define SMEM_BYTES (STAGES * STAGE_FLOATS * 4)  // 147456

// Scratch (device globals; allocation-free rule)
__device__ float g_att[(size_t)B_SZ * T_SZ * T_SZ];     // logits -> att
__device__ float g_vpT[(size_t)B_SZ * E_SZ * T_SZ];     // (value@P^T)^T per batch
__device__ float g_qM[(size_t)B_SZ * T_SZ * E_SZ];      // query @ M
__device__ float g_WqT[(size_t)E_SZ * HE_SZ];
__device__ float g_M[(size_t)E_SZ * E_SZ];
__device__ float g_P[(size_t)E_SZ * E_SZ];
__device__ float g_a1[E_SZ];      // Wq^T bk
__device__ float g_a2[E_SZ];      // Wk^T bq
__device__ float g_wv[E_SZ];      // Wo bv
__device__ float g_c[1];          // bq . bk
__device__ float g_u[(size_t)B_SZ * T_SZ];
__device__ float g_w[(size_t)B_SZ * T_SZ];
__device__ float g_rs[(size_t)B_SZ * T_SZ];

static __device__ __forceinline__ uint32_t f2tf32(float x) {
    uint32_t u;
    asm volatile("cvt.rna.tf32.f32 %0, %1;" : "=r"(u) : "f"(x));
    return u;
}

static __device__ __forceinline__ void mma_tf32(float* c, const uint32_t* a, const uint32_t* b) {
    asm volatile(
        "mma.sync.aligned.m16n8k8.row.col.f32.tf32.tf32.f32 "
        "{%0,%1,%2,%3}, {%4,%5,%6,%7}, {%8,%9}, {%0,%1,%2,%3};\n"
        : "+f"(c[0]), "+f"(c[1]), "+f"(c[2]), "+f"(c[3])
        : "r"(a[0]), "r"(a[1]), "r"(a[2]), "r"(a[3]), "r"(b[0]), "r"(b[1]));
}

static __device__ __forceinline__ void cp_async16(float* smem_dst, const float* gptr) {
    uint32_t s = (uint32_t)__cvta_generic_to_shared(smem_dst);
    asm volatile("cp.async.cg.shared.global [%0], [%1], 16;\n" :: "r"(s), "l"(gptr));
}
static __device__ __forceinline__ void cp_commit() {
    asm volatile("cp.async.commit_group;\n");
}
template <int N>
static __device__ __forceinline__ void cp_wait() {
    asm volatile("cp.async.wait_group %0;\n" :: "n"(N));
}

// ---------------------------------------------------------------------------
// GEMM: C[M,N] = f(A @ opB).  A [M,K] row-major.
//   TRANS_B: B [N,K] (opB = B^T); else B [K,N].
// EPI=0: C = alpha*acc
// EPI=1: C = alpha*(acc + rowv[row] + colv[col])      (logits: u + w(+c))
// EPI=2: C = acc + rowv[row]*colv[col] + bias[col]    (attend: rs (x) wv + bo)
// ---------------------------------------------------------------------------
template <bool TRANS_B, int EPI>
__global__ __launch_bounds__(256, 1)
void gemm_tf32(const float* __restrict__ A, const float* __restrict__ Bm,
               const float* __restrict__ rowv, const float* __restrict__ colv,
               const float* __restrict__ bias, float* __restrict__ C,
               int M, int N, int K, float alpha,
               long long sA, long long sB, long long sC,
               long long sRow, long long sCol)
{
    extern __shared__ float smem[];

    const float* Ab = A + (long long)blockIdx.z * sA;
    const float* Bb = Bm + (long long)blockIdx.z * sB;
    float* Cb = C + (long long)blockIdx.z * sC;

    const int bm = blockIdx.y * 128;
    const int bn = blockIdx.x * 128;
    const int tid = threadIdx.x;
    const int lane = tid & 31;
    const int warp = tid >> 5;
    const int wm = (warp & 3) * 32;
    const int wn = (warp >> 2) * 64;
    const int gr = lane >> 2;
    const int gc = lane & 3;

    float acc[2][8][4];
#pragma unroll
    for (int i = 0; i < 2; ++i)
#pragma unroll
        for (int j = 0; j < 8; ++j)
#pragma unroll
            for (int r = 0; r < 4; ++r) acc[i][j][r] = 0.f;

    const int ldrow = tid >> 3;
    const int ldcol = (tid & 7) << 2;
    const int nrow = tid >> 5;
    const int ncol = (tid & 31) << 2;

    const int nk = K >> 5;

    auto load_tile = [&](int kt, int stage) {
        float* sA = smem + stage * STAGE_FLOATS;
        float* sB = sA + 4608;
        const int k0g = kt << 5;
#pragma unroll
        for (int p = 0; p < 4; ++p) {
            const int r = ldrow + p * 32;
            cp_async16(sA + r * 36 + ldcol, Ab + (size_t)(bm + r) * K + (k0g + ldcol));
        }
        if (TRANS_B) {
#pragma unroll
            for (int p = 0; p < 4; ++p) {
                const int r = ldrow + p * 32;
                cp_async16(sB + r * 36 + ldcol, Bb + (size_t)(bn + r) * K + (k0g + ldcol));
            }
        } else {
#pragma unroll
            for (int p = 0; p < 4; ++p) {
                const int r = nrow + p * 8;
                cp_async16(sB + r * 136 + ncol, Bb + (size_t)(k0g + r) * N + (bn + ncol));
            }
        }
    };

#pragma unroll
    for (int s = 0; s < STAGES - 1; ++s) {
        if (s < nk) load_tile(s, s);
        cp_commit();
    }

    for (int kt = 0; kt < nk; ++kt) {
        const int stage = kt & (STAGES - 1);
        cp_wait<STAGES - 2>();
        __syncthreads();

        const int pf = kt + STAGES - 1;
        if (pf < nk) load_tile(pf, pf & (STAGES - 1));
        cp_commit();

        const float* sA = smem + stage * STAGE_FLOATS;
        const float* sB = sA + 4608;

#pragma unroll
        for (int k0 = 0; k0 < 32; k0 += 8) {
            uint32_t a[2][4];
#pragma unroll
            for (int i = 0; i < 2; ++i) {
                const int r = wm + i * 16 + gr;
                a[i][0] = f2tf32(sA[(size_t)r * 36 + k0 + gc]);
                a[i][1] = f2tf32(sA[(size_t)(r + 8) * 36 + k0 + gc]);
                a[i][2] = f2tf32(sA[(size_t)r * 36 + k0 + gc + 4]);
                a[i][3] = f2tf32(sA[(size_t)(r + 8) * 36 + k0 + gc + 4]);
            }
            uint32_t b[8][2];
            if (TRANS_B) {
#pragma unroll
                for (int j = 0; j < 8; ++j) {
                    const int cn = wn + j * 8 + gr;
                    b[j][0] = f2tf32(sB[(size_t)cn * 36 + k0 + gc]);
                    b[j][1] = f2tf32(sB[(size_t)cn * 36 + k0 + gc + 4]);
                }
            } else {
#pragma unroll
                for (int j = 0; j < 8; ++j) {
                    const int cn = wn + j * 8 + gr;
                    b[j][0] = f2tf32(sB[(size_t)(k0 + gc) * 136 + cn]);
                    b[j][1] = f2tf32(sB[(size_t)(k0 + gc + 4) * 136 + cn]);
                }
            }
#pragma unroll
            for (int i = 0; i < 2; ++i)
#pragma unroll
                for (int j = 0; j < 8; ++j) mma_tf32(acc[i][j], a[i], b[j]);
        }
        __syncthreads();
    }

    const float* rv = (EPI != 0) ? rowv + (long long)blockIdx.z * sRow : nullptr;
    const float* cv = (EPI != 0) ? colv + (long long)blockIdx.z * sCol : nullptr;

#pragma unroll
    for (int i = 0; i < 2; ++i) {
#pragma unroll
        for (int j = 0; j < 8; ++j) {
            const int row = bm + wm + i * 16 + gr;
            const int col = bn + wn + j * 8 + gc * 2;
            float v0 = acc[i][j][0], v1 = acc[i][j][1];
            float v2 = acc[i][j][2], v3 = acc[i][j][3];
            if (EPI == 0) {
                v0 *= alpha; v1 *= alpha; v2 *= alpha; v3 *= alpha;
            } else if (EPI == 1) {
                const float u0 = rv[row], u8 = rv[row + 8];
                const float w0 = cv[col], w1 = cv[col + 1];
                v0 = (v0 + u0 + w0) * alpha;
                v1 = (v1 + u0 + w1) * alpha;
                v2 = (v2 + u8 + w0) * alpha;
                v3 = (v3 + u8 + w1) * alpha;
            } else {  // EPI == 2
                const float r0 = rv[row], r8 = rv[row + 8];
                const float w0 = cv[col], w1 = cv[col + 1];
                const float b0 = bias[col], b1 = bias[col + 1];
                v0 = v0 + r0 * w0 + b0;
                v1 = v1 + r0 * w1 + b1;
                v2 = v2 + r8 * w0 + b0;
                v3 = v3 + r8 * w1 + b1;
            }
            Cb[(size_t)row * N + col] = v0;
            Cb[(size_t)row * N + col + 1] = v1;
            Cb[(size_t)(row + 8) * N + col] = v2;
            Cb[(size_t)(row + 8) * N + col + 1] = v3;
        }
    }
}

// Batch-axis softmax over 8 entries, in place, float4.
__global__ void softmax_b8(float4* __restrict__ d, int plane4)
{
    const int i = blockIdx.x * blockDim.x + threadIdx.x;
    if (i >= plane4) return;
    float4 v[B_SZ];
    float4 m = make_float4(-1e30f, -1e30f, -1e30f, -1e30f);
#pragma unroll
    for (int b = 0; b < B_SZ; ++b) {
        v[b] = d[(size_t)b * plane4 + i];
        m.x = fmaxf(m.x, v[b].x); m.y = fmaxf(m.y, v[b].y);
        m.z = fmaxf(m.z, v[b].z); m.w = fmaxf(m.w, v[b].w);
    }
    float4 s = make_float4(0.f, 0.f, 0.f, 0.f);
#pragma unroll
    for (int b = 0; b < B_SZ; ++b) {
        v[b].x = __expf(v[b].x - m.x); s.x += v[b].x;
        v[b].y = __expf(v[b].y - m.y); s.y += v[b].y;
        v[b].z = __expf(v[b].z - m.z); s.z += v[b].z;
        v[b].w = __expf(v[b].w - m.w); s.w += v[b].w;
    }
    s.x = 1.f / s.x; s.y = 1.f / s.y; s.z = 1.f / s.z; s.w = 1.f / s.w;
#pragma unroll
    for (int b = 0; b < B_SZ; ++b) {
        v[b].x *= s.x; v[b].y *= s.y; v[b].z *= s.z; v[b].w *= s.w;
        d[(size_t)b * plane4 + i] = v[b];
    }
}

// Plain 32x32 tiled transpose: outT[e][h] = in[h][e].  in [R,Cc].
__global__ void transpose32(const float* __restrict__ in, float* __restrict__ outT,
                            int R, int Cc)
{
    __shared__ float sm[32][33];
    const int r0 = blockIdx.x * 32;
    const int c0 = blockIdx.y * 32;
    const int tx = threadIdx.x, ty = threadIdx.y;
#pragma unroll
    for (int q = 0; q < 4; ++q)
        sm[ty + q * 8][tx] = in[(size_t)(r0 + ty + q * 8) * Cc + c0 + tx];
    __syncthreads();
#pragma unroll
    for (int q = 0; q < 4; ++q)
        outT[(size_t)(c0 + ty + q * 8) * R + r0 + tx] = sm[tx][ty + q * 8];
}

// out[e] = sum_h W[h*E + e] * b[h]   (column-weighted sum; coalesced over e)
__global__ void colvec(const float* __restrict__ W, const float* __restrict__ b,
                       float* __restrict__ out)
{
    const int e = blockIdx.x * blockDim.x + threadIdx.x;
    if (e >= E_SZ) return;
    float s0 = 0.f, s1 = 0.f, s2 = 0.f, s3 = 0.f;
    for (int h = 0; h < HE_SZ; h += 4) {
        s0 += W[(size_t)h * E_SZ + e] * b[h];
        s1 += W[(size_t)(h + 1) * E_SZ + e] * b[h + 1];
        s2 += W[(size_t)(h + 2) * E_SZ + e] * b[h + 2];
        s3 += W[(size_t)(h + 3) * E_SZ + e] * b[h + 3];
    }
    out[e] = (s0 + s1) + (s2 + s3);
}

// wv[e] = sum_h Wo[e*HE + h] * bv[h]   (warp per row)
__global__ void rowvec(const float* __restrict__ Wo, const float* __restrict__ bv,
                       float* __restrict__ out)
{
    const int wid = threadIdx.x >> 5;
    const int lane = threadIdx.x & 31;
    const int e = blockIdx.x * 8 + wid;
    const float4* r = reinterpret_cast<const float4*>(Wo + (size_t)e * HE_SZ);
    const float4* b4 = reinterpret_cast<const float4*>(bv);
    float s = 0.f;
#pragma unroll
    for (int i = 0; i < 32; ++i) {
        const float4 a = r[lane + i * 32];
        const float4 b = b4[lane + i * 32];
        s += a.x * b.x + a.y * b.y + a.z * b.z + a.w * b.w;
    }
#pragma unroll
    for (int o = 16; o; o >>= 1) s += __shfl_xor_sync(0xffffffffu, s, o);
    if (lane == 0) out[e] = s;
}

// g_c[0] = bq . bk
__global__ void dotscalar(const float* __restrict__ a, const float* __restrict__ b,
                          float* __restrict__ out)
{
    __shared__ float red[256];
    float s = 0.f;
    for (int i = threadIdx.x; i < HE_SZ; i += 256) s += a[i] * b[i];
    red[threadIdx.x] = s;
    __syncthreads();
    for (int o = 128; o; o >>= 1) {
        if (threadIdx.x < o) red[threadIdx.x] += red[threadIdx.x + o];
        __syncthreads();
    }
    if (threadIdx.x == 0) out[0] = red[0];
}

// out[r] = in[r,:] . vec  (+ cptr[0] if ADD_C).  Rows of length E_SZ. Warp/row.
template <bool ADD_C>
__global__ void dotvec(const float* __restrict__ in, const float* __restrict__ vec,
                       const float* __restrict__ cptr, float* __restrict__ out)
{
    const int wid = threadIdx.x >> 5;
    const int lane = threadIdx.x & 31;
    const int r = blockIdx.x * 8 + wid;
    const float4* p = reinterpret_cast<const float4*>(in + (size_t)r * E_SZ);
    const float4* v4 = reinterpret_cast<const float4*>(vec);
    float s = 0.f;
#pragma unroll
    for (int i = 0; i < 4; ++i) {
        const float4 a = p[lane + i * 32];
        const float4 b = v4[lane + i * 32];
        s += a.x * b.x + a.y * b.y + a.z * b.z + a.w * b.w;
    }
#pragma unroll
    for (int o = 16; o; o >>= 1) s += __shfl_xor_sync(0xffffffffu, s, o);
    if (lane == 0) out[r] = ADD_C ? s + cptr[0] : s;
}

// rs[r] = sum of att row r (length T_SZ).  Warp per row.
__global__ void rowsum(const float* __restrict__ att, float* __restrict__ rs)
{
    const int wid = threadIdx.x >> 5;
    const int lane = threadIdx.x & 31;
    const int r = blockIdx.x * 8 + wid;
    const float4* p = reinterpret_cast<const float4*>(att + (size_t)r * T_SZ);
    float s = 0.f;
#pragma unroll
    for (int i = 0; i < 16; ++i) {
        const float4 a = p[lane + i * 32];
        s += (a.x + a.y) + (a.z + a.w);
    }
#pragma unroll
    for (int o = 16; o; o >>= 1) s += __shfl_xor_sync(0xffffffffu, s, o);
    if (lane == 0) rs[r] = s;
}

extern "C" void kernel_launch(void* const* d_in, const int* in_sizes, int n_in,
                              void* d_out, int out_size)
{
    (void)in_sizes; (void)n_in; (void)out_size;
    const float* key   = (const float*)d_in[0];
    const float* value = (const float*)d_in[1];
    const float* query = (const float*)d_in[2];
    const float* Wk = (const float*)d_in[3];
    const float* bk = (const float*)d_in[4];
    const float* Wv = (const float*)d_in[5];
    const float* bv = (const float*)d_in[6];
    const float* Wq = (const float*)d_in[7];
    const float* bq = (const float*)d_in[8];
    const float* Wo = (const float*)d_in[9];
    const float* bo = (const float*)d_in[10];
    float* out = (float*)d_out;

    float *att, *vpT, *qM, *WqT, *Mm, *Pm, *a1, *a2, *wv, *cs, *u, *w, *rs;
    cudaGetSymbolAddress((void**)&att, g_att);
    cudaGetSymbolAddress((void**)&vpT, g_vpT);
    cudaGetSymbolAddress((void**)&qM, g_qM);
    cudaGetSymbolAddress((void**)&WqT, g_WqT);
    cudaGetSymbolAddress((void**)&Mm, g_M);
    cudaGetSymbolAddress((void**)&Pm, g_P);
    cudaGetSymbolAddress((void**)&a1, g_a1);
    cudaGetSymbolAddress((void**)&a2, g_a2);
    cudaGetSymbolAddress((void**)&wv, g_wv);
    cudaGetSymbolAddress((void**)&cs, g_c);
    cudaGetSymbolAddress((void**)&u, g_u);
    cudaGetSymbolAddress((void**)&w, g_w);
    cudaGetSymbolAddress((void**)&rs, g_rs);

    cudaFuncSetAttribute((const void*)gemm_tf32<true, 0>,
                         cudaFuncAttributeMaxDynamicSharedMemorySize, SMEM_BYTES);
    cudaFuncSetAttribute((const void*)gemm_tf32<true, 1>,
                         cudaFuncAttributeMaxDynamicSharedMemorySize, SMEM_BYTES);
    cudaFuncSetAttribute((const void*)gemm_tf32<true, 2>,
                         cudaFuncAttributeMaxDynamicSharedMemorySize, SMEM_BYTES);
    cudaFuncSetAttribute((const void*)gemm_tf32<false, 0>,
                         cudaFuncAttributeMaxDynamicSharedMemorySize, SMEM_BYTES);

    const int MT = B_SZ * T_SZ;  // 16384
    const dim3 blk(256);
    const long long sTE = (long long)T_SZ * E_SZ;
    const long long sTT = (long long)T_SZ * T_SZ;
    const long long sET = (long long)E_SZ * T_SZ;

    // --- small precomputations ---
    transpose32<<<dim3(HE_SZ / 32, E_SZ / 32), dim3(32, 8)>>>(Wq, WqT, HE_SZ, E_SZ);
    colvec<<<E_SZ / 128, 128>>>(Wq, bk, a1);
    colvec<<<E_SZ / 128, 128>>>(Wk, bq, a2);
    rowvec<<<E_SZ / 8, 256>>>(Wo, bv, wv);
    dotscalar<<<1, 256>>>(bq, bk, cs);
    dotvec<false><<<MT / 8, 256>>>(query, a1, nullptr, u);
    dotvec<true><<<MT / 8, 256>>>(key, a2, cs, w);

    // M = WqT @ Wk   (NN): [512,4096]@[4096,512]
    gemm_tf32<false, 0><<<dim3(E_SZ / 128, E_SZ / 128, 1), blk, SMEM_BYTES>>>(
        WqT, Wk, nullptr, nullptr, nullptr, Mm, E_SZ, E_SZ, HE_SZ, 1.f, 0, 0, 0, 0, 0);
    // P = Wo @ Wv    (NN): [512,4096]@[4096,512]
    gemm_tf32<false, 0><<<dim3(E_SZ / 128, E_SZ / 128, 1), blk, SMEM_BYTES>>>(
        Wo, Wv, nullptr, nullptr, nullptr, Pm, E_SZ, E_SZ, HE_SZ, 1.f, 0, 0, 0, 0, 0);
    // qM = query @ M (NN): [16384,512]@[512,512]
    gemm_tf32<false, 0><<<dim3(E_SZ / 128, MT / 128, 1), blk, SMEM_BYTES>>>(
        query, Mm, nullptr, nullptr, nullptr, qM, MT, E_SZ, E_SZ, 1.f, 0, 0, 0, 0, 0);
    // vpT = P @ value^T per batch (TRANS): C[E,T]
    gemm_tf32<true, 0><<<dim3(T_SZ / 128, E_SZ / 128, B_SZ), blk, SMEM_BYTES>>>(
        Pm, value, nullptr, nullptr, nullptr, vpT, E_SZ, T_SZ, E_SZ, 1.f, 0, sTE, sET, 0, 0);
    // logits: att = SCALE*(qM @ key^T + u + w) per batch
    gemm_tf32<true, 1><<<dim3(T_SZ / 128, T_SZ / 128, B_SZ), blk, SMEM_BYTES>>>(
        qM, key, u, w, nullptr, att, T_SZ, T_SZ, E_SZ, SCALE_F, sTE, sTE, sTT, T_SZ, T_SZ);
    // batch-axis softmax
    softmax_b8<<<(T_SZ * T_SZ / 4) / 256, 256>>>((float4*)att, T_SZ * T_SZ / 4);
    // rs = rowsum(att)
    rowsum<<<MT / 8, 256>>>(att, rs);
    // out = att @ vpT^T + rs (x) wv + bo   per batch
    gemm_tf32<true, 2><<<dim3(E_SZ / 128, T_SZ / 128, B_SZ), blk, SMEM_BYTES>>>(
        att, vpT, rs, wv, bo, out, T_SZ, E_SZ, T_SZ, 1.f, sTT, sET, sTE, T_SZ, 0);
}

// round 6
// speedup vs baseline: 5.1790x; 1.1855x over previous
#include <cuda_runtime.h>
#include <cstdint>
#include <cstddef>

// ---------------------------------------------------------------------------
// MultiheadedAttention2 (batch-axis softmax) — v6:
//   v5 algebraic form + split-K for the 512x512 weight-product GEMMs (M, P)
//   + fused softmax/rowsum.
//   prod = query@(Wq^T Wk)@key^T + u[t] + w[s] + c
//   att  = softmax_b(prod*SCALE);  rs = rowsum(att)
//   out  = att@(value@P^T) + rs (x) (Wo bv) + bo,  P = Wo Wv
// ---------------------------------------------------------------------------

#define B_SZ 8
#define T_SZ 2048
#define E_SZ 512
#define HE_SZ 4096
#define SCALE_F 0.04419417382415922f  // 512^-0.5

#define STAGES 4
#define STAGE_FLOATS 9216
#define SMEM_BYTES (STAGES * STAGE_FLOATS * 4)  // 147456

#define NSPLIT 8   // split-K factor for M/P

// Scratch (device globals; allocation-free rule)
__device__ float g_att[(size_t)B_SZ * T_SZ * T_SZ];
__device__ float g_vpT[(size_t)B_SZ * E_SZ * T_SZ];
__device__ float g_qM[(size_t)B_SZ * T_SZ * E_SZ];
__device__ float g_WqT[(size_t)E_SZ * HE_SZ];
__device__ float g_M[(size_t)E_SZ * E_SZ];
__device__ float g_P[(size_t)E_SZ * E_SZ];
__device__ float g_part[(size_t)NSPLIT * E_SZ * E_SZ];
__device__ float g_a1[E_SZ];
__device__ float g_a2[E_SZ];
__device__ float g_wv[E_SZ];
__device__ float g_c[1];
__device__ float g_u[(size_t)B_SZ * T_SZ];
__device__ float g_w[(size_t)B_SZ * T_SZ];
__device__ float g_rs[(size_t)B_SZ * T_SZ];

static __device__ __forceinline__ uint32_t f2tf32(float x) {
    uint32_t u;
    asm volatile("cvt.rna.tf32.f32 %0, %1;" : "=r"(u) : "f"(x));
    return u;
}

static __device__ __forceinline__ void mma_tf32(float* c, const uint32_t* a, const uint32_t* b) {
    asm volatile(
        "mma.sync.aligned.m16n8k8.row.col.f32.tf32.tf32.f32 "
        "{%0,%1,%2,%3}, {%4,%5,%6,%7}, {%8,%9}, {%0,%1,%2,%3};\n"
        : "+f"(c[0]), "+f"(c[1]), "+f"(c[2]), "+f"(c[3])
        : "r"(a[0]), "r"(a[1]), "r"(a[2]), "r"(a[3]), "r"(b[0]), "r"(b[1]));
}

static __device__ __forceinline__ void cp_async16(float* smem_dst, const float* gptr) {
    uint32_t s = (uint32_t)__cvta_generic_to_shared(smem_dst);
    asm volatile("cp.async.cg.shared.global [%0], [%1], 16;\n" :: "r"(s), "l"(gptr));
}
static __device__ __forceinline__ void cp_commit() {
    asm volatile("cp.async.commit_group;\n");
}
template <int N>
static __device__ __forceinline__ void cp_wait() {
    asm volatile("cp.async.wait_group %0;\n" :: "n"(N));
}

// ---------------------------------------------------------------------------
// GEMM: C[M,N] = f(A @ opB).  A row-major with row stride ldA (k-loop bound K).
//   TRANS_B: B [N,K] (opB = B^T); else B [K,N] (row stride N).
// EPI=0: C = alpha*acc
// EPI=1: C = alpha*(acc + rowv[row] + colv[col])
// EPI=2: C = acc + rowv[row]*colv[col] + bias[col]
// Per-z offsets sA/sB/sC allow batching and split-K chunk addressing.
// ---------------------------------------------------------------------------
template <bool TRANS_B, int EPI>
__global__ __launch_bounds__(256, 1)
void gemm_tf32(const float* __restrict__ A, const float* __restrict__ Bm,
               const float* __restrict__ rowv, const float* __restrict__ colv,
               const float* __restrict__ bias, float* __restrict__ C,
               int M, int N, int K, long long ldA, float alpha,
               long long sA, long long sB, long long sC,
               long long sRow, long long sCol)
{
    extern __shared__ float smem[];

    const float* Ab = A + (long long)blockIdx.z * sA;
    const float* Bb = Bm + (long long)blockIdx.z * sB;
    float* Cb = C + (long long)blockIdx.z * sC;

    const int bm = blockIdx.y * 128;
    const int bn = blockIdx.x * 128;
    const int tid = threadIdx.x;
    const int lane = tid & 31;
    const int warp = tid >> 5;
    const int wm = (warp & 3) * 32;
    const int wn = (warp >> 2) * 64;
    const int gr = lane >> 2;
    const int gc = lane & 3;

    float acc[2][8][4];
#pragma unroll
    for (int i = 0; i < 2; ++i)
#pragma unroll
        for (int j = 0; j < 8; ++j)
#pragma unroll
            for (int r = 0; r < 4; ++r) acc[i][j][r] = 0.f;

    const int ldrow = tid >> 3;
    const int ldcol = (tid & 7) << 2;
    const int nrow = tid >> 5;
    const int ncol = (tid & 31) << 2;

    const int nk = K >> 5;

    auto load_tile = [&](int kt, int stage) {
        float* sAp = smem + stage * STAGE_FLOATS;
        float* sBp = sAp + 4608;
        const int k0g = kt << 5;
#pragma unroll
        for (int p = 0; p < 4; ++p) {
            const int r = ldrow + p * 32;
            cp_async16(sAp + r * 36 + ldcol, Ab + (size_t)(bm + r) * ldA + (k0g + ldcol));
        }
        if (TRANS_B) {
#pragma unroll
            for (int p = 0; p < 4; ++p) {
                const int r = ldrow + p * 32;
                cp_async16(sBp + r * 36 + ldcol, Bb + (size_t)(bn + r) * K + (k0g + ldcol));
            }
        } else {
#pragma unroll
            for (int p = 0; p < 4; ++p) {
                const int r = nrow + p * 8;
                cp_async16(sBp + r * 136 + ncol, Bb + (size_t)(k0g + r) * N + (bn + ncol));
            }
        }
    };

#pragma unroll
    for (int s = 0; s < STAGES - 1; ++s) {
        if (s < nk) load_tile(s, s);
        cp_commit();
    }

    for (int kt = 0; kt < nk; ++kt) {
        const int stage = kt & (STAGES - 1);
        cp_wait<STAGES - 2>();
        __syncthreads();

        const int pf = kt + STAGES - 1;
        if (pf < nk) load_tile(pf, pf & (STAGES - 1));
        cp_commit();

        const float* sAp = smem + stage * STAGE_FLOATS;
        const float* sBp = sAp + 4608;

#pragma unroll
        for (int k0 = 0; k0 < 32; k0 += 8) {
            uint32_t a[2][4];
#pragma unroll
            for (int i = 0; i < 2; ++i) {
                const int r = wm + i * 16 + gr;
                a[i][0] = f2tf32(sAp[(size_t)r * 36 + k0 + gc]);
                a[i][1] = f2tf32(sAp[(size_t)(r + 8) * 36 + k0 + gc]);
                a[i][2] = f2tf32(sAp[(size_t)r * 36 + k0 + gc + 4]);
                a[i][3] = f2tf32(sAp[(size_t)(r + 8) * 36 + k0 + gc + 4]);
            }
            uint32_t b[8][2];
            if (TRANS_B) {
#pragma unroll
                for (int j = 0; j < 8; ++j) {
                    const int cn = wn + j * 8 + gr;
                    b[j][0] = f2tf32(sBp[(size_t)cn * 36 + k0 + gc]);
                    b[j][1] = f2tf32(sBp[(size_t)cn * 36 + k0 + gc + 4]);
                }
            } else {
#pragma unroll
                for (int j = 0; j < 8; ++j) {
                    const int cn = wn + j * 8 + gr;
                    b[j][0] = f2tf32(sBp[(size_t)(k0 + gc) * 136 + cn]);
                    b[j][1] = f2tf32(sBp[(size_t)(k0 + gc + 4) * 136 + cn]);
                }
            }
#pragma unroll
            for (int i = 0; i < 2; ++i)
#pragma unroll
                for (int j = 0; j < 8; ++j) mma_tf32(acc[i][j], a[i], b[j]);
        }
        __syncthreads();
    }

    const float* rv = (EPI != 0) ? rowv + (long long)blockIdx.z * sRow : nullptr;
    const float* cv = (EPI != 0) ? colv + (long long)blockIdx.z * sCol : nullptr;

#pragma unroll
    for (int i = 0; i < 2; ++i) {
#pragma unroll
        for (int j = 0; j < 8; ++j) {
            const int row = bm + wm + i * 16 + gr;
            const int col = bn + wn + j * 8 + gc * 2;
            float v0 = acc[i][j][0], v1 = acc[i][j][1];
            float v2 = acc[i][j][2], v3 = acc[i][j][3];
            if (EPI == 0) {
                v0 *= alpha; v1 *= alpha; v2 *= alpha; v3 *= alpha;
            } else if (EPI == 1) {
                const float u0 = rv[row], u8 = rv[row + 8];
                const float w0 = cv[col], w1 = cv[col + 1];
                v0 = (v0 + u0 + w0) * alpha;
                v1 = (v1 + u0 + w1) * alpha;
                v2 = (v2 + u8 + w0) * alpha;
                v3 = (v3 + u8 + w1) * alpha;
            } else {
                const float r0 = rv[row], r8 = rv[row + 8];
                const float w0 = cv[col], w1 = cv[col + 1];
                const float b0 = bias[col], b1 = bias[col + 1];
                v0 = v0 + r0 * w0 + b0;
                v1 = v1 + r0 * w1 + b1;
                v2 = v2 + r8 * w0 + b0;
                v3 = v3 + r8 * w1 + b1;
            }
            Cb[(size_t)row * N + col] = v0;
            Cb[(size_t)row * N + col + 1] = v1;
            Cb[(size_t)(row + 8) * N + col] = v2;
            Cb[(size_t)(row + 8) * N + col + 1] = v3;
        }
    }
}

// Sum NSPLIT partial matrices (deterministic order).
__global__ void reduce_splits(const float4* __restrict__ part, float4* __restrict__ out, int n4)
{
    const int i = blockIdx.x * blockDim.x + threadIdx.x;
    if (i >= n4) return;
    float4 s = part[i];
#pragma unroll
    for (int p = 1; p < NSPLIT; ++p) {
        const float4 v = part[(size_t)p * n4 + i];
        s.x += v.x; s.y += v.y; s.z += v.z; s.w += v.w;
    }
    out[i] = s;
}

// Fused batch-axis softmax + per-(b,t) row sums.
// Block = one t-row (512 threads, thread j owns s4=j => 4 s values, all 8 b).
__global__ __launch_bounds__(512)
void softmax_rows(float* __restrict__ d, float* __restrict__ rs)
{
    __shared__ float red[16][8];
    const int t = blockIdx.x;
    const int j = threadIdx.x;
    const size_t plane4 = (size_t)T_SZ * T_SZ / 4;
    float4* p = reinterpret_cast<float4*>(d);
    const size_t base = (size_t)t * (T_SZ / 4) + j;

    float4 v[B_SZ];
    float4 m = make_float4(-1e30f, -1e30f, -1e30f, -1e30f);
#pragma unroll
    for (int b = 0; b < B_SZ; ++b) {
        v[b] = p[(size_t)b * plane4 + base];
        m.x = fmaxf(m.x, v[b].x); m.y = fmaxf(m.y, v[b].y);
        m.z = fmaxf(m.z, v[b].z); m.w = fmaxf(m.w, v[b].w);
    }
    float4 s = make_float4(0.f, 0.f, 0.f, 0.f);
#pragma unroll
    for (int b = 0; b < B_SZ; ++b) {
        v[b].x = __expf(v[b].x - m.x); s.x += v[b].x;
        v[b].y = __expf(v[b].y - m.y); s.y += v[b].y;
        v[b].z = __expf(v[b].z - m.z); s.z += v[b].z;
        v[b].w = __expf(v[b].w - m.w); s.w += v[b].w;
    }
    s.x = 1.f / s.x; s.y = 1.f / s.y; s.z = 1.f / s.z; s.w = 1.f / s.w;

    float bsum[B_SZ];
#pragma unroll
    for (int b = 0; b < B_SZ; ++b) {
        v[b].x *= s.x; v[b].y *= s.y; v[b].z *= s.z; v[b].w *= s.w;
        p[(size_t)b * plane4 + base] = v[b];
        bsum[b] = (v[b].x + v[b].y) + (v[b].z + v[b].w);
    }
    // warp reduce each bsum, then cross-warp via smem
#pragma unroll
    for (int b = 0; b < B_SZ; ++b) {
#pragma unroll
        for (int o = 16; o; o >>= 1) bsum[b] += __shfl_xor_sync(0xffffffffu, bsum[b], o);
    }
    const int wid = j >> 5;
    if ((j & 31) == 0) {
#pragma unroll
        for (int b = 0; b < B_SZ; ++b) red[wid][b] = bsum[b];
    }
    __syncthreads();
    if (j < B_SZ) {
        float acc = 0.f;
#pragma unroll
        for (int w2 = 0; w2 < 16; ++w2) acc += red[w2][j];
        rs[(size_t)j * T_SZ + t] = acc;
    }
}

// Plain 32x32 tiled transpose.
__global__ void transpose32(const float* __restrict__ in, float* __restrict__ outT,
                            int R, int Cc)
{
    __shared__ float sm[32][33];
    const int r0 = blockIdx.x * 32;
    const int c0 = blockIdx.y * 32;
    const int tx = threadIdx.x, ty = threadIdx.y;
#pragma unroll
    for (int q = 0; q < 4; ++q)
        sm[ty + q * 8][tx] = in[(size_t)(r0 + ty + q * 8) * Cc + c0 + tx];
    __syncthreads();
#pragma unroll
    for (int q = 0; q < 4; ++q)
        outT[(size_t)(c0 + ty + q * 8) * R + r0 + tx] = sm[tx][ty + q * 8];
}

// out[e] = sum_h W[h*E + e] * b[h]
__global__ void colvec(const float* __restrict__ W, const float* __restrict__ b,
                       float* __restrict__ out)
{
    const int e = blockIdx.x * blockDim.x + threadIdx.x;
    if (e >= E_SZ) return;
    float s0 = 0.f, s1 = 0.f, s2 = 0.f, s3 = 0.f;
    for (int h = 0; h < HE_SZ; h += 4) {
        s0 += W[(size_t)h * E_SZ + e] * b[h];
        s1 += W[(size_t)(h + 1) * E_SZ + e] * b[h + 1];
        s2 += W[(size_t)(h + 2) * E_SZ + e] * b[h + 2];
        s3 += W[(size_t)(h + 3) * E_SZ + e] * b[h + 3];
    }
    out[e] = (s0 + s1) + (s2 + s3);
}

// wv[e] = Wo[e,:] . bv   (warp per row)
__global__ void rowvec(const float* __restrict__ Wo, const float* __restrict__ bv,
                       float* __restrict__ out)
{
    const int wid = threadIdx.x >> 5;
    const int lane = threadIdx.x & 31;
    const int e = blockIdx.x * 8 + wid;
    const float4* r = reinterpret_cast<const float4*>(Wo + (size_t)e * HE_SZ);
    const float4* b4 = reinterpret_cast<const float4*>(bv);
    float s = 0.f;
#pragma unroll
    for (int i = 0; i < 32; ++i) {
        const float4 a = r[lane + i * 32];
        const float4 b = b4[lane + i * 32];
        s += a.x * b.x + a.y * b.y + a.z * b.z + a.w * b.w;
    }
#pragma unroll
    for (int o = 16; o; o >>= 1) s += __shfl_xor_sync(0xffffffffu, s, o);
    if (lane == 0) out[e] = s;
}

__global__ void dotscalar(const float* __restrict__ a, const float* __restrict__ b,
                          float* __restrict__ out)
{
    __shared__ float red[256];
    float s = 0.f;
    for (int i = threadIdx.x; i < HE_SZ; i += 256) s += a[i] * b[i];
    red[threadIdx.x] = s;
    __syncthreads();
    for (int o = 128; o; o >>= 1) {
        if (threadIdx.x < o) red[threadIdx.x] += red[threadIdx.x + o];
        __syncthreads();
    }
    if (threadIdx.x == 0) out[0] = red[0];
}

// out[r] = in[r,:] . vec (+ cptr[0] if ADD_C). Rows length E_SZ, warp/row.
template <bool ADD_C>
__global__ void dotvec(const float* __restrict__ in, const float* __restrict__ vec,
                       const float* __restrict__ cptr, float* __restrict__ out)
{
    const int wid = threadIdx.x >> 5;
    const int lane = threadIdx.x & 31;
    const int r = blockIdx.x * 8 + wid;
    const float4* p = reinterpret_cast<const float4*>(in + (size_t)r * E_SZ);
    const float4* v4 = reinterpret_cast<const float4*>(vec);
    float s = 0.f;
#pragma unroll
    for (int i = 0; i < 4; ++i) {
        const float4 a = p[lane + i * 32];
        const float4 b = v4[lane + i * 32];
        s += a.x * b.x + a.y * b.y + a.z * b.z + a.w * b.w;
    }
#pragma unroll
    for (int o = 16; o; o >>= 1) s += __shfl_xor_sync(0xffffffffu, s, o);
    if (lane == 0) out[r] = ADD_C ? s + cptr[0] : s;
}

extern "C" void kernel_launch(void* const* d_in, const int* in_sizes, int n_in,
                              void* d_out, int out_size)
{
    (void)in_sizes; (void)n_in; (void)out_size;
    const float* key   = (const float*)d_in[0];
    const float* value = (const float*)d_in[1];
    const float* query = (const float*)d_in[2];
    const float* Wk = (const float*)d_in[3];
    const float* bk = (const float*)d_in[4];
    const float* Wv = (const float*)d_in[5];
    const float* bv = (const float*)d_in[6];
    const float* Wq = (const float*)d_in[7];
    const float* bq = (const float*)d_in[8];
    const float* Wo = (const float*)d_in[9];
    const float* bo = (const float*)d_in[10];
    float* out = (float*)d_out;

    float *att, *vpT, *qM, *WqT, *Mm, *Pm, *part, *a1, *a2, *wv, *cs, *u, *w, *rs;
    cudaGetSymbolAddress((void**)&att, g_att);
    cudaGetSymbolAddress((void**)&vpT, g_vpT);
    cudaGetSymbolAddress((void**)&qM, g_qM);
    cudaGetSymbolAddress((void**)&WqT, g_WqT);
    cudaGetSymbolAddress((void**)&Mm, g_M);
    cudaGetSymbolAddress((void**)&Pm, g_P);
    cudaGetSymbolAddress((void**)&part, g_part);
    cudaGetSymbolAddress((void**)&a1, g_a1);
    cudaGetSymbolAddress((void**)&a2, g_a2);
    cudaGetSymbolAddress((void**)&wv, g_wv);
    cudaGetSymbolAddress((void**)&cs, g_c);
    cudaGetSymbolAddress((void**)&u, g_u);
    cudaGetSymbolAddress((void**)&w, g_w);
    cudaGetSymbolAddress((void**)&rs, g_rs);

    cudaFuncSetAttribute((const void*)gemm_tf32<true, 0>,
                         cudaFuncAttributeMaxDynamicSharedMemorySize, SMEM_BYTES);
    cudaFuncSetAttribute((const void*)gemm_tf32<true, 1>,
                         cudaFuncAttributeMaxDynamicSharedMemorySize, SMEM_BYTES);
    cudaFuncSetAttribute((const void*)gemm_tf32<true, 2>,
                         cudaFuncAttributeMaxDynamicSharedMemorySize, SMEM_BYTES);
    cudaFuncSetAttribute((const void*)gemm_tf32<false, 0>,
                         cudaFuncAttributeMaxDynamicSharedMemorySize, SMEM_BYTES);

    const int MT = B_SZ * T_SZ;  // 16384
    const dim3 blk(256);
    const long long sTE = (long long)T_SZ * E_SZ;
    const long long sTT = (long long)T_SZ * T_SZ;
    const long long sET = (long long)E_SZ * T_SZ;
    const long long sEE = (long long)E_SZ * E_SZ;
    const int KC = HE_SZ / NSPLIT;  // 512

    // --- small precomputations ---
    transpose32<<<dim3(HE_SZ / 32, E_SZ / 32), dim3(32, 8)>>>(Wq, WqT, HE_SZ, E_SZ);
    colvec<<<E_SZ / 128, 128>>>(Wq, bk, a1);
    colvec<<<E_SZ / 128, 128>>>(Wk, bq, a2);
    rowvec<<<E_SZ / 8, 256>>>(Wo, bv, wv);
    dotscalar<<<1, 256>>>(bq, bk, cs);
    dotvec<false><<<MT / 8, 256>>>(query, a1, nullptr, u);
    dotvec<true><<<MT / 8, 256>>>(key, a2, cs, w);

    // M = WqT @ Wk  via split-K (z = K chunk): A chunk offset KC, B chunk KC rows
    gemm_tf32<false, 0><<<dim3(E_SZ / 128, E_SZ / 128, NSPLIT), blk, SMEM_BYTES>>>(
        WqT, Wk, nullptr, nullptr, nullptr, part, E_SZ, E_SZ, KC, HE_SZ, 1.f,
        KC, (long long)KC * E_SZ, sEE, 0, 0);
    reduce_splits<<<(E_SZ * E_SZ / 4 + 255) / 256, 256>>>((float4*)part, (float4*)Mm, E_SZ * E_SZ / 4);
    // P = Wo @ Wv  via split-K
    gemm_tf32<false, 0><<<dim3(E_SZ / 128, E_SZ / 128, NSPLIT), blk, SMEM_BYTES>>>(
        Wo, Wv, nullptr, nullptr, nullptr, part, E_SZ, E_SZ, KC, HE_SZ, 1.f,
        KC, (long long)KC * E_SZ, sEE, 0, 0);
    reduce_splits<<<(E_SZ * E_SZ / 4 + 255) / 256, 256>>>((float4*)part, (float4*)Pm, E_SZ * E_SZ / 4);

    // qM = query @ M (NN): [16384,512]@[512,512]
    gemm_tf32<false, 0><<<dim3(E_SZ / 128, MT / 128, 1), blk, SMEM_BYTES>>>(
        query, Mm, nullptr, nullptr, nullptr, qM, MT, E_SZ, E_SZ, E_SZ, 1.f, 0, 0, 0, 0, 0);
    // vpT = P @ value^T per batch (TRANS): C[E,T]
    gemm_tf32<true, 0><<<dim3(T_SZ / 128, E_SZ / 128, B_SZ), blk, SMEM_BYTES>>>(
        Pm, value, nullptr, nullptr, nullptr, vpT, E_SZ, T_SZ, E_SZ, E_SZ, 1.f,
        0, sTE, sET, 0, 0);
    // logits: att = SCALE*(qM @ key^T + u + w) per batch
    gemm_tf32<true, 1><<<dim3(T_SZ / 128, T_SZ / 128, B_SZ), blk, SMEM_BYTES>>>(
        qM, key, u, w, nullptr, att, T_SZ, T_SZ, E_SZ, E_SZ, SCALE_F,
        sTE, sTE, sTT, T_SZ, T_SZ);
    // fused batch-axis softmax + row sums
    softmax_rows<<<T_SZ, 512>>>(att, rs);
    // out = att @ vpT^T + rs (x) wv + bo   per batch
    gemm_tf32<true, 2><<<dim3(E_SZ / 128, T_SZ / 128, B_SZ), blk, SMEM_BYTES>>>(
        att, vpT, rs, wv, bo, out, T_SZ, E_SZ, T_SZ, T_SZ, 1.f,
        sTT, sET, sTE, T_SZ, 0);
}

// round 7
// speedup vs baseline: 7.9284x; 1.5309x over previous
#include <cuda_runtime.h>
#include <cstdint>
#include <cstddef>

// ---------------------------------------------------------------------------
// MultiheadedAttention2 (batch-axis softmax) — v7:
//   v6 algebra + high-intensity GEMM: 128x256 CTA tile, 8 warps of 64x64
//   (125 B smem traffic per MMA vs 192 -> tensor-bound ~70% instead of
//   smem-bound ~50%). Split-K for M/P, fused softmax+rowsum, faster
//   colvec/rowvec precomputations.
// ---------------------------------------------------------------------------

#define B_SZ 8
#define T_SZ 2048
#define E_SZ 512
#define HE_SZ 4096
#define SCALE_F 0.04419417382415922f  // 512^-0.5

#define STAGES 4
#define STAGE_FLOATS 13824            // A: 128*36 = 4608, B: 9216 (256*36 or 32*264)
#define SMEM_BYTES (STAGES * STAGE_FLOATS * 4)  // 221184
#define NSPLIT 8
#define NCH 8                         // colvec h-chunks

// Scratch (device globals; allocation-free rule)
__device__ float g_att[(size_t)B_SZ * T_SZ * T_SZ];
__device__ float g_vpT[(size_t)B_SZ * E_SZ * T_SZ];
__device__ float g_qM[(size_t)B_SZ * T_SZ * E_SZ];
__device__ float g_WqT[(size_t)E_SZ * HE_SZ];
__device__ float g_M[(size_t)E_SZ * E_SZ];
__device__ float g_P[(size_t)E_SZ * E_SZ];
__device__ float g_part[(size_t)NSPLIT * E_SZ * E_SZ];
__device__ float g_cpart[(size_t)NCH * E_SZ];
__device__ float g_a1[E_SZ];
__device__ float g_a2[E_SZ];
__device__ float g_wv[E_SZ];
__device__ float g_c[1];
__device__ float g_u[(size_t)B_SZ * T_SZ];
__device__ float g_w[(size_t)B_SZ * T_SZ];
__device__ float g_rs[(size_t)B_SZ * T_SZ];

static __device__ __forceinline__ uint32_t f2tf32(float x) {
    uint32_t u;
    asm volatile("cvt.rna.tf32.f32 %0, %1;" : "=r"(u) : "f"(x));
    return u;
}

static __device__ __forceinline__ void mma_tf32(float* c, const uint32_t* a, const uint32_t* b) {
    asm volatile(
        "mma.sync.aligned.m16n8k8.row.col.f32.tf32.tf32.f32 "
        "{%0,%1,%2,%3}, {%4,%5,%6,%7}, {%8,%9}, {%0,%1,%2,%3};\n"
        : "+f"(c[0]), "+f"(c[1]), "+f"(c[2]), "+f"(c[3])
        : "r"(a[0]), "r"(a[1]), "r"(a[2]), "r"(a[3]), "r"(b[0]), "r"(b[1]));
}

static __device__ __forceinline__ void cp_async16(float* smem_dst, const float* gptr) {
    uint32_t s = (uint32_t)__cvta_generic_to_shared(smem_dst);
    asm volatile("cp.async.cg.shared.global [%0], [%1], 16;\n" :: "r"(s), "l"(gptr));
}
static __device__ __forceinline__ void cp_commit() {
    asm volatile("cp.async.commit_group;\n");
}
template <int N>
static __device__ __forceinline__ void cp_wait() {
    asm volatile("cp.async.wait_group %0;\n" :: "n"(N));
}

// ---------------------------------------------------------------------------
// GEMM: C[M,N] = f(A @ opB).  CTA tile 128x256, 256 thr, 8 warps of 64x64.
//   A row-major, row stride ldA, k-loop bound K.
//   TRANS_B: B [N,K] row stride K; else B [K,N] row stride N.
// EPI=0: C = alpha*acc
// EPI=1: C = alpha*(acc + rowv[row] + colv[col])
// EPI=2: C = acc + rowv[row]*colv[col] + bias[col]
// ---------------------------------------------------------------------------
template <bool TRANS_B, int EPI>
__global__ __launch_bounds__(256, 1)
void gemm_tf32(const float* __restrict__ A, const float* __restrict__ Bm,
               const float* __restrict__ rowv, const float* __restrict__ colv,
               const float* __restrict__ bias, float* __restrict__ C,
               int M, int N, int K, long long ldA, float alpha,
               long long sA, long long sB, long long sC,
               long long sRow, long long sCol)
{
    extern __shared__ float smem[];

    const float* Ab = A + (long long)blockIdx.z * sA;
    const float* Bb = Bm + (long long)blockIdx.z * sB;
    float* Cb = C + (long long)blockIdx.z * sC;

    const int bm = blockIdx.y * 128;
    const int bn = blockIdx.x * 256;
    const int tid = threadIdx.x;
    const int lane = tid & 31;
    const int warp = tid >> 5;          // 0..7
    const int wm = (warp & 1) * 64;     // 2 warps down M
    const int wn = (warp >> 1) * 64;    // 4 warps across N
    const int gr = lane >> 2;           // 0..7
    const int gc = lane & 3;            // 0..3

    float acc[4][8][4];
#pragma unroll
    for (int i = 0; i < 4; ++i)
#pragma unroll
        for (int j = 0; j < 8; ++j)
#pragma unroll
            for (int r = 0; r < 4; ++r) acc[i][j][r] = 0.f;

    const int ldrow = tid >> 3;          // 0..31
    const int ldcol = (tid & 7) << 2;    // 0..28
    const int nrow = tid >> 5;           // 0..7   (NN B)
    const int ncol = (tid & 31) << 3;    // 0..248 (NN B, two float4)

    const int nk = K >> 5;

    auto load_tile = [&](int kt, int stage) {
        float* sAp = smem + stage * STAGE_FLOATS;
        float* sBp = sAp + 4608;
        const int k0g = kt << 5;
#pragma unroll
        for (int p = 0; p < 4; ++p) {
            const int r = ldrow + p * 32;
            cp_async16(sAp + r * 36 + ldcol, Ab + (size_t)(bm + r) * ldA + (k0g + ldcol));
        }
        if (TRANS_B) {
#pragma unroll
            for (int p = 0; p < 8; ++p) {
                const int r = ldrow + p * 32;
                cp_async16(sBp + r * 36 + ldcol, Bb + (size_t)(bn + r) * K + (k0g + ldcol));
            }
        } else {
#pragma unroll
            for (int p = 0; p < 4; ++p) {
                const int r = nrow + p * 8;   // k within tile
                const float* gp = Bb + (size_t)(k0g + r) * N + (bn + ncol);
                cp_async16(sBp + r * 264 + ncol, gp);
                cp_async16(sBp + r * 264 + ncol + 4, gp + 4);
            }
        }
    };

#pragma unroll
    for (int s = 0; s < STAGES - 1; ++s) {
        if (s < nk) load_tile(s, s);
        cp_commit();
    }

    for (int kt = 0; kt < nk; ++kt) {
        const int stage = kt & (STAGES - 1);
        cp_wait<STAGES - 2>();
        __syncthreads();

        const int pf = kt + STAGES - 1;
        if (pf < nk) load_tile(pf, pf & (STAGES - 1));
        cp_commit();

        const float* sAp = smem + stage * STAGE_FLOATS;
        const float* sBp = sAp + 4608;

#pragma unroll
        for (int k0 = 0; k0 < 32; k0 += 8) {
            uint32_t a[4][4];
#pragma unroll
            for (int i = 0; i < 4; ++i) {
                const int r = wm + i * 16 + gr;
                a[i][0] = f2tf32(sAp[(size_t)r * 36 + k0 + gc]);
                a[i][1] = f2tf32(sAp[(size_t)(r + 8) * 36 + k0 + gc]);
                a[i][2] = f2tf32(sAp[(size_t)r * 36 + k0 + gc + 4]);
                a[i][3] = f2tf32(sAp[(size_t)(r + 8) * 36 + k0 + gc + 4]);
            }
            uint32_t b[8][2];
            if (TRANS_B) {
#pragma unroll
                for (int j = 0; j < 8; ++j) {
                    const int cn = wn + j * 8 + gr;
                    b[j][0] = f2tf32(sBp[(size_t)cn * 36 + k0 + gc]);
                    b[j][1] = f2tf32(sBp[(size_t)cn * 36 + k0 + gc + 4]);
                }
            } else {
#pragma unroll
                for (int j = 0; j < 8; ++j) {
                    const int cn = wn + j * 8 + gr;
                    b[j][0] = f2tf32(sBp[(size_t)(k0 + gc) * 264 + cn]);
                    b[j][1] = f2tf32(sBp[(size_t)(k0 + gc + 4) * 264 + cn]);
                }
            }
#pragma unroll
            for (int i = 0; i < 4; ++i)
#pragma unroll
                for (int j = 0; j < 8; ++j) mma_tf32(acc[i][j], a[i], b[j]);
        }
        __syncthreads();
    }

    const float* rv = (EPI != 0) ? rowv + (long long)blockIdx.z * sRow : nullptr;
    const float* cv = (EPI != 0) ? colv + (long long)blockIdx.z * sCol : nullptr;

#pragma unroll
    for (int i = 0; i < 4; ++i) {
#pragma unroll
        for (int j = 0; j < 8; ++j) {
            const int row = bm + wm + i * 16 + gr;
            const int col = bn + wn + j * 8 + gc * 2;
            float v0 = acc[i][j][0], v1 = acc[i][j][1];
            float v2 = acc[i][j][2], v3 = acc[i][j][3];
            if (EPI == 0) {
                v0 *= alpha; v1 *= alpha; v2 *= alpha; v3 *= alpha;
            } else if (EPI == 1) {
                const float u0 = rv[row], u8 = rv[row + 8];
                const float w0 = cv[col], w1 = cv[col + 1];
                v0 = (v0 + u0 + w0) * alpha;
                v1 = (v1 + u0 + w1) * alpha;
                v2 = (v2 + u8 + w0) * alpha;
                v3 = (v3 + u8 + w1) * alpha;
            } else {
                const float r0 = rv[row], r8 = rv[row + 8];
                const float w0 = cv[col], w1 = cv[col + 1];
                const float b0 = bias[col], b1 = bias[col + 1];
                v0 = v0 + r0 * w0 + b0;
                v1 = v1 + r0 * w1 + b1;
                v2 = v2 + r8 * w0 + b0;
                v3 = v3 + r8 * w1 + b1;
            }
            Cb[(size_t)row * N + col] = v0;
            Cb[(size_t)row * N + col + 1] = v1;
            Cb[(size_t)(row + 8) * N + col] = v2;
            Cb[(size_t)(row + 8) * N + col + 1] = v3;
        }
    }
}

// Sum NSPLIT partial matrices (deterministic order).
__global__ void reduce_splits(const float4* __restrict__ part, float4* __restrict__ out, int n4)
{
    const int i = blockIdx.x * blockDim.x + threadIdx.x;
    if (i >= n4) return;
    float4 s = part[i];
#pragma unroll
    for (int p = 1; p < NSPLIT; ++p) {
        const float4 v = part[(size_t)p * n4 + i];
        s.x += v.x; s.y += v.y; s.z += v.z; s.w += v.w;
    }
    out[i] = s;
}

// Fused batch-axis softmax + per-(b,t) row sums. Block = one t-row.
__global__ __launch_bounds__(512)
void softmax_rows(float* __restrict__ d, float* __restrict__ rs)
{
    __shared__ float red[16][8];
    const int t = blockIdx.x;
    const int j = threadIdx.x;
    const size_t plane4 = (size_t)T_SZ * T_SZ / 4;
    float4* p = reinterpret_cast<float4*>(d);
    const size_t base = (size_t)t * (T_SZ / 4) + j;

    float4 v[B_SZ];
    float4 m = make_float4(-1e30f, -1e30f, -1e30f, -1e30f);
#pragma unroll
    for (int b = 0; b < B_SZ; ++b) {
        v[b] = p[(size_t)b * plane4 + base];
        m.x = fmaxf(m.x, v[b].x); m.y = fmaxf(m.y, v[b].y);
        m.z = fmaxf(m.z, v[b].z); m.w = fmaxf(m.w, v[b].w);
    }
    float4 s = make_float4(0.f, 0.f, 0.f, 0.f);
#pragma unroll
    for (int b = 0; b < B_SZ; ++b) {
        v[b].x = __expf(v[b].x - m.x); s.x += v[b].x;
        v[b].y = __expf(v[b].y - m.y); s.y += v[b].y;
        v[b].z = __expf(v[b].z - m.z); s.z += v[b].z;
        v[b].w = __expf(v[b].w - m.w); s.w += v[b].w;
    }
    s.x = 1.f / s.x; s.y = 1.f / s.y; s.z = 1.f / s.z; s.w = 1.f / s.w;

    float bsum[B_SZ];
#pragma unroll
    for (int b = 0; b < B_SZ; ++b) {
        v[b].x *= s.x; v[b].y *= s.y; v[b].z *= s.z; v[b].w *= s.w;
        p[(size_t)b * plane4 + base] = v[b];
        bsum[b] = (v[b].x + v[b].y) + (v[b].z + v[b].w);
    }
#pragma unroll
    for (int b = 0; b < B_SZ; ++b) {
#pragma unroll
        for (int o = 16; o; o >>= 1) bsum[b] += __shfl_xor_sync(0xffffffffu, bsum[b], o);
    }
    const int wid = j >> 5;
    if ((j & 31) == 0) {
#pragma unroll
        for (int b = 0; b < B_SZ; ++b) red[wid][b] = bsum[b];
    }
    __syncthreads();
    if (j < B_SZ) {
        float acc = 0.f;
#pragma unroll
        for (int w2 = 0; w2 < 16; ++w2) acc += red[w2][j];
        rs[(size_t)j * T_SZ + t] = acc;
    }
}

// Plain 32x32 tiled transpose.
__global__ void transpose32(const float* __restrict__ in, float* __restrict__ outT,
                            int R, int Cc)
{
    __shared__ float sm[32][33];
    const int r0 = blockIdx.x * 32;
    const int c0 = blockIdx.y * 32;
    const int tx = threadIdx.x, ty = threadIdx.y;
#pragma unroll
    for (int q = 0; q < 4; ++q)
        sm[ty + q * 8][tx] = in[(size_t)(r0 + ty + q * 8) * Cc + c0 + tx];
    __syncthreads();
#pragma unroll
    for (int q = 0; q < 4; ++q)
        outT[(size_t)(c0 + ty + q * 8) * R + r0 + tx] = sm[tx][ty + q * 8];
}

// colvec stage 1: part[ch][e] = sum over h-chunk of W[h][e]*b[h]
__global__ void colvec_part(const float* __restrict__ W, const float* __restrict__ b,
                            float* __restrict__ part)
{
    const int e = blockIdx.x * 128 + threadIdx.x;
    const int ch = blockIdx.y;
    const int h0 = ch * (HE_SZ / NCH);
    float s0 = 0.f, s1 = 0.f;
    for (int h = h0; h < h0 + HE_SZ / NCH; h += 2) {
        s0 += W[(size_t)h * E_SZ + e] * b[h];
        s1 += W[(size_t)(h + 1) * E_SZ + e] * b[h + 1];
    }
    part[(size_t)ch * E_SZ + e] = s0 + s1;
}
// colvec stage 2: out[e] = sum_ch part[ch][e]
__global__ void colvec_red(const float* __restrict__ part, float* __restrict__ out)
{
    const int e = blockIdx.x * 128 + threadIdx.x;
    float s = 0.f;
#pragma unroll
    for (int ch = 0; ch < NCH; ++ch) s += part[(size_t)ch * E_SZ + e];
    out[e] = s;
}

// wv[e] = Wo[e,:] . bv  — one block (256 thr) per row, deterministic reduce.
__global__ void rowvec(const float* __restrict__ Wo, const float* __restrict__ bv,
                       float* __restrict__ out)
{
    __shared__ float red[256];
    const int e = blockIdx.x;
    const int t = threadIdx.x;
    const float4* r = reinterpret_cast<const float4*>(Wo + (size_t)e * HE_SZ);
    const float4* b4 = reinterpret_cast<const float4*>(bv);
    float s = 0.f;
#pragma unroll
    for (int i = 0; i < 4; ++i) {
        const float4 a = r[t + i * 256];
        const float4 b = b4[t + i * 256];
        s += a.x * b.x + a.y * b.y + a.z * b.z + a.w * b.w;
    }
    red[t] = s;
    __syncthreads();
    for (int o = 128; o; o >>= 1) {
        if (t < o) red[t] += red[t + o];
        __syncthreads();
    }
    if (t == 0) out[e] = red[0];
}

__global__ void dotscalar(const float* __restrict__ a, const float* __restrict__ b,
                          float* __restrict__ out)
{
    __shared__ float red[256];
    float s = 0.f;
    for (int i = threadIdx.x; i < HE_SZ; i += 256) s += a[i] * b[i];
    red[threadIdx.x] = s;
    __syncthreads();
    for (int o = 128; o; o >>= 1) {
        if (threadIdx.x < o) red[threadIdx.x] += red[threadIdx.x + o];
        __syncthreads();
    }
    if (threadIdx.x == 0) out[0] = red[0];
}

// out[r] = in[r,:] . vec (+ cptr[0] if ADD_C). Rows length E_SZ, warp/row.
template <bool ADD_C>
__global__ void dotvec(const float* __restrict__ in, const float* __restrict__ vec,
                       const float* __restrict__ cptr, float* __restrict__ out)
{
    const int wid = threadIdx.x >> 5;
    const int lane = threadIdx.x & 31;
    const int r = blockIdx.x * 8 + wid;
    const float4* p = reinterpret_cast<const float4*>(in + (size_t)r * E_SZ);
    const float4* v4 = reinterpret_cast<const float4*>(vec);
    float s = 0.f;
#pragma unroll
    for (int i = 0; i < 4; ++i) {
        const float4 a = p[lane + i * 32];
        const float4 b = v4[lane + i * 32];
        s += a.x * b.x + a.y * b.y + a.z * b.z + a.w * b.w;
    }
#pragma unroll
    for (int o = 16; o; o >>= 1) s += __shfl_xor_sync(0xffffffffu, s, o);
    if (lane == 0) out[r] = ADD_C ? s + cptr[0] : s;
}

extern "C" void kernel_launch(void* const* d_in, const int* in_sizes, int n_in,
                              void* d_out, int out_size)
{
    (void)in_sizes; (void)n_in; (void)out_size;
    const float* key   = (const float*)d_in[0];
    const float* value = (const float*)d_in[1];
    const float* query = (const float*)d_in[2];
    const float* Wk = (const float*)d_in[3];
    const float* bk = (const float*)d_in[4];
    const float* Wv = (const float*)d_in[5];
    const float* bv = (const float*)d_in[6];
    const float* Wq = (const float*)d_in[7];
    const float* bq = (const float*)d_in[8];
    const float* Wo = (const float*)d_in[9];
    const float* bo = (const float*)d_in[10];
    float* out = (float*)d_out;

    float *att, *vpT, *qM, *WqT, *Mm, *Pm, *part, *cpart;
    float *a1, *a2, *wv, *cs, *u, *w, *rs;
    cudaGetSymbolAddress((void**)&att, g_att);
    cudaGetSymbolAddress((void**)&vpT, g_vpT);
    cudaGetSymbolAddress((void**)&qM, g_qM);
    cudaGetSymbolAddress((void**)&WqT, g_WqT);
    cudaGetSymbolAddress((void**)&Mm, g_M);
    cudaGetSymbolAddress((void**)&Pm, g_P);
    cudaGetSymbolAddress((void**)&part, g_part);
    cudaGetSymbolAddress((void**)&cpart, g_cpart);
    cudaGetSymbolAddress((void**)&a1, g_a1);
    cudaGetSymbolAddress((void**)&a2, g_a2);
    cudaGetSymbolAddress((void**)&wv, g_wv);
    cudaGetSymbolAddress((void**)&cs, g_c);
    cudaGetSymbolAddress((void**)&u, g_u);
    cudaGetSymbolAddress((void**)&w, g_w);
    cudaGetSymbolAddress((void**)&rs, g_rs);

    cudaFuncSetAttribute((const void*)gemm_tf32<true, 0>,
                         cudaFuncAttributeMaxDynamicSharedMemorySize, SMEM_BYTES);
    cudaFuncSetAttribute((const void*)gemm_tf32<true, 1>,
                         cudaFuncAttributeMaxDynamicSharedMemorySize, SMEM_BYTES);
    cudaFuncSetAttribute((const void*)gemm_tf32<true, 2>,
                         cudaFuncAttributeMaxDynamicSharedMemorySize, SMEM_BYTES);
    cudaFuncSetAttribute((const void*)gemm_tf32<false, 0>,
                         cudaFuncAttributeMaxDynamicSharedMemorySize, SMEM_BYTES);

    const int MT = B_SZ * T_SZ;  // 16384
    const dim3 blk(256);
    const long long sTE = (long long)T_SZ * E_SZ;
    const long long sTT = (long long)T_SZ * T_SZ;
    const long long sET = (long long)E_SZ * T_SZ;
    const long long sEE = (long long)E_SZ * E_SZ;
    const int KC = HE_SZ / NSPLIT;  // 512

    // --- small precomputations ---
    transpose32<<<dim3(HE_SZ / 32, E_SZ / 32), dim3(32, 8)>>>(Wq, WqT, HE_SZ, E_SZ);
    colvec_part<<<dim3(E_SZ / 128, NCH), 128>>>(Wq, bk, cpart);
    colvec_red<<<E_SZ / 128, 128>>>(cpart, a1);
    colvec_part<<<dim3(E_SZ / 128, NCH), 128>>>(Wk, bq, cpart);
    colvec_red<<<E_SZ / 128, 128>>>(cpart, a2);
    rowvec<<<E_SZ, 256>>>(Wo, bv, wv);
    dotscalar<<<1, 256>>>(bq, bk, cs);
    dotvec<false><<<MT / 8, 256>>>(query, a1, nullptr, u);
    dotvec<true><<<MT / 8, 256>>>(key, a2, cs, w);

    // M = WqT @ Wk  via split-K (z = K chunk)
    gemm_tf32<false, 0><<<dim3(E_SZ / 256, E_SZ / 128, NSPLIT), blk, SMEM_BYTES>>>(
        WqT, Wk, nullptr, nullptr, nullptr, part, E_SZ, E_SZ, KC, HE_SZ, 1.f,
        KC, (long long)KC * E_SZ, sEE, 0, 0);
    reduce_splits<<<(E_SZ * E_SZ / 4 + 255) / 256, 256>>>((float4*)part, (float4*)Mm, E_SZ * E_SZ / 4);
    // P = Wo @ Wv  via split-K
    gemm_tf32<false, 0><<<dim3(E_SZ / 256, E_SZ / 128, NSPLIT), blk, SMEM_BYTES>>>(
        Wo, Wv, nullptr, nullptr, nullptr, part, E_SZ, E_SZ, KC, HE_SZ, 1.f,
        KC, (long long)KC * E_SZ, sEE, 0, 0);
    reduce_splits<<<(E_SZ * E_SZ / 4 + 255) / 256, 256>>>((float4*)part, (float4*)Pm, E_SZ * E_SZ / 4);

    // qM = query @ M (NN): [16384,512]@[512,512]
    gemm_tf32<false, 0><<<dim3(E_SZ / 256, MT / 128, 1), blk, SMEM_BYTES>>>(
        query, Mm, nullptr, nullptr, nullptr, qM, MT, E_SZ, E_SZ, E_SZ, 1.f, 0, 0, 0, 0, 0);
    // vpT = P @ value^T per batch (TRANS): C[E,T]
    gemm_tf32<true, 0><<<dim3(T_SZ / 256, E_SZ / 128, B_SZ), blk, SMEM_BYTES>>>(
        Pm, value, nullptr, nullptr, nullptr, vpT, E_SZ, T_SZ, E_SZ, E_SZ, 1.f,
        0, sTE, sET, 0, 0);
    // logits: att = SCALE*(qM @ key^T + u + w) per batch
    gemm_tf32<true, 1><<<dim3(T_SZ / 256, T_SZ / 128, B_SZ), blk, SMEM_BYTES>>>(
        qM, key, u, w, nullptr, att, T_SZ, T_SZ, E_SZ, E_SZ, SCALE_F,
        sTE, sTE, sTT, T_SZ, T_SZ);
    // fused batch-axis softmax + row sums
    softmax_rows<<<T_SZ, 512>>>(att, rs);
    // out = att @ vpT^T + rs (x) wv + bo   per batch
    gemm_tf32<true, 2><<<dim3(E_SZ / 256, T_SZ / 128, B_SZ), blk, SMEM_BYTES>>>(
        att, vpT, rs, wv, bo, out, T_SZ, E_SZ, T_SZ, T_SZ, 1.f,
        sTT, sET, sTE, T_SZ, 0);
}

// round 8
// speedup vs baseline: 8.5329x; 1.0762x over previous
#include <cuda_runtime.h>
#include <cstdint>
#include <cstddef>

// ---------------------------------------------------------------------------
// MultiheadedAttention2 (batch-axis softmax) — v8:
//   v7 + parallelized colvec (64 h-chunks, fused Wq/Wk launch) and fused
//   dotvec(u,w) launch. GEMM core unchanged (128x256 CTA, 8 warps of 64x64).
// ---------------------------------------------------------------------------

#define B_SZ 8
#define T_SZ 2048
#define E_SZ 512
#define HE_SZ 4096
#define SCALE_F 0.04419417382415922f  // 512^-0.5

#define STAGES 4
#define STAGE_FLOATS 13824            // A: 128*36 = 4608, B: 9216 (256*36 or 32*264)
#define SMEM_BYTES (STAGES * STAGE_FLOATS * 4)  // 221184
#define NSPLIT 8
#define NCH 64                        // colvec h-chunks

// Scratch (device globals; allocation-free rule)
__device__ float g_att[(size_t)B_SZ * T_SZ * T_SZ];
__device__ float g_vpT[(size_t)B_SZ * E_SZ * T_SZ];
__device__ float g_qM[(size_t)B_SZ * T_SZ * E_SZ];
__device__ float g_WqT[(size_t)E_SZ * HE_SZ];
__device__ float g_M[(size_t)E_SZ * E_SZ];
__device__ float g_P[(size_t)E_SZ * E_SZ];
__device__ float g_part[(size_t)NSPLIT * E_SZ * E_SZ];
__device__ float g_cpart[(size_t)2 * NCH * E_SZ];
__device__ float g_a1[E_SZ];
__device__ float g_a2[E_SZ];
__device__ float g_wv[E_SZ];
__device__ float g_c[1];
__device__ float g_u[(size_t)B_SZ * T_SZ];
__device__ float g_w[(size_t)B_SZ * T_SZ];
__device__ float g_rs[(size_t)B_SZ * T_SZ];

static __device__ __forceinline__ uint32_t f2tf32(float x) {
    uint32_t u;
    asm volatile("cvt.rna.tf32.f32 %0, %1;" : "=r"(u) : "f"(x));
    return u;
}

static __device__ __forceinline__ void mma_tf32(float* c, const uint32_t* a, const uint32_t* b) {
    asm volatile(
        "mma.sync.aligned.m16n8k8.row.col.f32.tf32.tf32.f32 "
        "{%0,%1,%2,%3}, {%4,%5,%6,%7}, {%8,%9}, {%0,%1,%2,%3};\n"
        : "+f"(c[0]), "+f"(c[1]), "+f"(c[2]), "+f"(c[3])
        : "r"(a[0]), "r"(a[1]), "r"(a[2]), "r"(a[3]), "r"(b[0]), "r"(b[1]));
}

static __device__ __forceinline__ void cp_async16(float* smem_dst, const float* gptr) {
    uint32_t s = (uint32_t)__cvta_generic_to_shared(smem_dst);
    asm volatile("cp.async.cg.shared.global [%0], [%1], 16;\n" :: "r"(s), "l"(gptr));
}
static __device__ __forceinline__ void cp_commit() {
    asm volatile("cp.async.commit_group;\n");
}
template <int N>
static __device__ __forceinline__ void cp_wait() {
    asm volatile("cp.async.wait_group %0;\n" :: "n"(N));
}

// ---------------------------------------------------------------------------
// GEMM: C[M,N] = f(A @ opB).  CTA tile 128x256, 256 thr, 8 warps of 64x64.
//   A row-major, row stride ldA, k-loop bound K.
//   TRANS_B: B [N,K] row stride K; else B [K,N] row stride N.
// EPI=0: C = alpha*acc
// EPI=1: C = alpha*(acc + rowv[row] + colv[col])
// EPI=2: C = acc + rowv[row]*colv[col] + bias[col]
// ---------------------------------------------------------------------------
template <bool TRANS_B, int EPI>
__global__ __launch_bounds__(256, 1)
void gemm_tf32(const float* __restrict__ A, const float* __restrict__ Bm,
               const float* __restrict__ rowv, const float* __restrict__ colv,
               const float* __restrict__ bias, float* __restrict__ C,
               int M, int N, int K, long long ldA, float alpha,
               long long sA, long long sB, long long sC,
               long long sRow, long long sCol)
{
    extern __shared__ float smem[];

    const float* Ab = A + (long long)blockIdx.z * sA;
    const float* Bb = Bm + (long long)blockIdx.z * sB;
    float* Cb = C + (long long)blockIdx.z * sC;

    const int bm = blockIdx.y * 128;
    const int bn = blockIdx.x * 256;
    const int tid = threadIdx.x;
    const int lane = tid & 31;
    const int warp = tid >> 5;          // 0..7
    const int wm = (warp & 1) * 64;     // 2 warps down M
    const int wn = (warp >> 1) * 64;    // 4 warps across N
    const int gr = lane >> 2;           // 0..7
    const int gc = lane & 3;            // 0..3

    float acc[4][8][4];
#pragma unroll
    for (int i = 0; i < 4; ++i)
#pragma unroll
        for (int j = 0; j < 8; ++j)
#pragma unroll
            for (int r = 0; r < 4; ++r) acc[i][j][r] = 0.f;

    const int ldrow = tid >> 3;          // 0..31
    const int ldcol = (tid & 7) << 2;    // 0..28
    const int nrow = tid >> 5;           // 0..7   (NN B)
    const int ncol = (tid & 31) << 3;    // 0..248 (NN B, two float4)

    const int nk = K >> 5;

    auto load_tile = [&](int kt, int stage) {
        float* sAp = smem + stage * STAGE_FLOATS;
        float* sBp = sAp + 4608;
        const int k0g = kt << 5;
#pragma unroll
        for (int p = 0; p < 4; ++p) {
            const int r = ldrow + p * 32;
            cp_async16(sAp + r * 36 + ldcol, Ab + (size_t)(bm + r) * ldA + (k0g + ldcol));
        }
        if (TRANS_B) {
#pragma unroll
            for (int p = 0; p < 8; ++p) {
                const int r = ldrow + p * 32;
                cp_async16(sBp + r * 36 + ldcol, Bb + (size_t)(bn + r) * K + (k0g + ldcol));
            }
        } else {
#pragma unroll
            for (int p = 0; p < 4; ++p) {
                const int r = nrow + p * 8;   // k within tile
                const float* gp = Bb + (size_t)(k0g + r) * N + (bn + ncol);
                cp_async16(sBp + r * 264 + ncol, gp);
                cp_async16(sBp + r * 264 + ncol + 4, gp + 4);
            }
        }
    };

#pragma unroll
    for (int s = 0; s < STAGES - 1; ++s) {
        if (s < nk) load_tile(s, s);
        cp_commit();
    }

    for (int kt = 0; kt < nk; ++kt) {
        const int stage = kt & (STAGES - 1);
        cp_wait<STAGES - 2>();
        __syncthreads();

        const int pf = kt + STAGES - 1;
        if (pf < nk) load_tile(pf, pf & (STAGES - 1));
        cp_commit();

        const float* sAp = smem + stage * STAGE_FLOATS;
        const float* sBp = sAp + 4608;

#pragma unroll
        for (int k0 = 0; k0 < 32; k0 += 8) {
            uint32_t a[4][4];
#pragma unroll
            for (int i = 0; i < 4; ++i) {
                const int r = wm + i * 16 + gr;
                a[i][0] = f2tf32(sAp[(size_t)r * 36 + k0 + gc]);
                a[i][1] = f2tf32(sAp[(size_t)(r + 8) * 36 + k0 + gc]);
                a[i][2] = f2tf32(sAp[(size_t)r * 36 + k0 + gc + 4]);
                a[i][3] = f2tf32(sAp[(size_t)(r + 8) * 36 + k0 + gc + 4]);
            }
            uint32_t b[8][2];
            if (TRANS_B) {
#pragma unroll
                for (int j = 0; j < 8; ++j) {
                    const int cn = wn + j * 8 + gr;
                    b[j][0] = f2tf32(sBp[(size_t)cn * 36 + k0 + gc]);
                    b[j][1] = f2tf32(sBp[(size_t)cn * 36 + k0 + gc + 4]);
                }
            } else {
#pragma unroll
                for (int j = 0; j < 8; ++j) {
                    const int cn = wn + j * 8 + gr;
                    b[j][0] = f2tf32(sBp[(size_t)(k0 + gc) * 264 + cn]);
                    b[j][1] = f2tf32(sBp[(size_t)(k0 + gc + 4) * 264 + cn]);
                }
            }
#pragma unroll
            for (int i = 0; i < 4; ++i)
#pragma unroll
                for (int j = 0; j < 8; ++j) mma_tf32(acc[i][j], a[i], b[j]);
        }
        __syncthreads();
    }

    const float* rv = (EPI != 0) ? rowv + (long long)blockIdx.z * sRow : nullptr;
    const float* cv = (EPI != 0) ? colv + (long long)blockIdx.z * sCol : nullptr;

#pragma unroll
    for (int i = 0; i < 4; ++i) {
#pragma unroll
        for (int j = 0; j < 8; ++j) {
            const int row = bm + wm + i * 16 + gr;
            const int col = bn + wn + j * 8 + gc * 2;
            float v0 = acc[i][j][0], v1 = acc[i][j][1];
            float v2 = acc[i][j][2], v3 = acc[i][j][3];
            if (EPI == 0) {
                v0 *= alpha; v1 *= alpha; v2 *= alpha; v3 *= alpha;
            } else if (EPI == 1) {
                const float u0 = rv[row], u8 = rv[row + 8];
                const float w0 = cv[col], w1 = cv[col + 1];
                v0 = (v0 + u0 + w0) * alpha;
                v1 = (v1 + u0 + w1) * alpha;
                v2 = (v2 + u8 + w0) * alpha;
                v3 = (v3 + u8 + w1) * alpha;
            } else {
                const float r0 = rv[row], r8 = rv[row + 8];
                const float w0 = cv[col], w1 = cv[col + 1];
                const float b0 = bias[col], b1 = bias[col + 1];
                v0 = v0 + r0 * w0 + b0;
                v1 = v1 + r0 * w1 + b1;
                v2 = v2 + r8 * w0 + b0;
                v3 = v3 + r8 * w1 + b1;
            }
            Cb[(size_t)row * N + col] = v0;
            Cb[(size_t)row * N + col + 1] = v1;
            Cb[(size_t)(row + 8) * N + col] = v2;
            Cb[(size_t)(row + 8) * N + col + 1] = v3;
        }
    }
}

// Sum NSPLIT partial matrices (deterministic order).
__global__ void reduce_splits(const float4* __restrict__ part, float4* __restrict__ out, int n4)
{
    const int i = blockIdx.x * blockDim.x + threadIdx.x;
    if (i >= n4) return;
    float4 s = part[i];
#pragma unroll
    for (int p = 1; p < NSPLIT; ++p) {
        const float4 v = part[(size_t)p * n4 + i];
        s.x += v.x; s.y += v.y; s.z += v.z; s.w += v.w;
    }
    out[i] = s;
}

// Fused batch-axis softmax + per-(b,t) row sums. Block = one t-row.
__global__ __launch_bounds__(512)
void softmax_rows(float* __restrict__ d, float* __restrict__ rs)
{
    __shared__ float red[16][8];
    const int t = blockIdx.x;
    const int j = threadIdx.x;
    const size_t plane4 = (size_t)T_SZ * T_SZ / 4;
    float4* p = reinterpret_cast<float4*>(d);
    const size_t base = (size_t)t * (T_SZ / 4) + j;

    float4 v[B_SZ];
    float4 m = make_float4(-1e30f, -1e30f, -1e30f, -1e30f);
#pragma unroll
    for (int b = 0; b < B_SZ; ++b) {
        v[b] = p[(size_t)b * plane4 + base];
        m.x = fmaxf(m.x, v[b].x); m.y = fmaxf(m.y, v[b].y);
        m.z = fmaxf(m.z, v[b].z); m.w = fmaxf(m.w, v[b].w);
    }
    float4 s = make_float4(0.f, 0.f, 0.f, 0.f);
#pragma unroll
    for (int b = 0; b < B_SZ; ++b) {
        v[b].x = __expf(v[b].x - m.x); s.x += v[b].x;
        v[b].y = __expf(v[b].y - m.y); s.y += v[b].y;
        v[b].z = __expf(v[b].z - m.z); s.z += v[b].z;
        v[b].w = __expf(v[b].w - m.w); s.w += v[b].w;
    }
    s.x = 1.f / s.x; s.y = 1.f / s.y; s.z = 1.f / s.z; s.w = 1.f / s.w;

    float bsum[B_SZ];
#pragma unroll
    for (int b = 0; b < B_SZ; ++b) {
        v[b].x *= s.x; v[b].y *= s.y; v[b].z *= s.z; v[b].w *= s.w;
        p[(size_t)b * plane4 + base] = v[b];
        bsum[b] = (v[b].x + v[b].y) + (v[b].z + v[b].w);
    }
#pragma unroll
    for (int b = 0; b < B_SZ; ++b) {
#pragma unroll
        for (int o = 16; o; o >>= 1) bsum[b] += __shfl_xor_sync(0xffffffffu, bsum[b], o);
    }
    const int wid = j >> 5;
    if ((j & 31) == 0) {
#pragma unroll
        for (int b = 0; b < B_SZ; ++b) red[wid][b] = bsum[b];
    }
    __syncthreads();
    if (j < B_SZ) {
        float acc = 0.f;
#pragma unroll
        for (int w2 = 0; w2 < 16; ++w2) acc += red[w2][j];
        rs[(size_t)j * T_SZ + t] = acc;
    }
}

// Plain 32x32 tiled transpose.
__global__ void transpose32(const float* __restrict__ in, float* __restrict__ outT,
                            int R, int Cc)
{
    __shared__ float sm[32][33];
    const int r0 = blockIdx.x * 32;
    const int c0 = blockIdx.y * 32;
    const int tx = threadIdx.x, ty = threadIdx.y;
#pragma unroll
    for (int q = 0; q < 4; ++q)
        sm[ty + q * 8][tx] = in[(size_t)(r0 + ty + q * 8) * Cc + c0 + tx];
    __syncthreads();
#pragma unroll
    for (int q = 0; q < 4; ++q)
        outT[(size_t)(c0 + ty + q * 8) * R + r0 + tx] = sm[tx][ty + q * 8];
}

// colvec stage 1, both weight matrices in one launch.
// grid (E/128, NCH, 2): z selects (Wq,bk) or (Wk,bq).
// part[z][ch][e] = sum over h-chunk of W[h][e]*b[h]
__global__ void colvec_part(const float* __restrict__ W1, const float* __restrict__ b1,
                            const float* __restrict__ W2, const float* __restrict__ b2,
                            float* __restrict__ part)
{
    const float* W = blockIdx.z ? W2 : W1;
    const float* b = blockIdx.z ? b2 : b1;
    const int e = blockIdx.x * 128 + threadIdx.x;
    const int ch = blockIdx.y;
    const int h0 = ch * (HE_SZ / NCH);
    float s0 = 0.f, s1 = 0.f;
#pragma unroll
    for (int h = h0; h < h0 + HE_SZ / NCH; h += 2) {
        s0 += W[(size_t)h * E_SZ + e] * b[h];
        s1 += W[(size_t)(h + 1) * E_SZ + e] * b[h + 1];
    }
    part[((size_t)blockIdx.z * NCH + ch) * E_SZ + e] = s0 + s1;
}
// colvec stage 2: out_z[e] = sum_ch part[z][ch][e]  (grid (E/128, 2))
__global__ void colvec_red(const float* __restrict__ part,
                           float* __restrict__ out1, float* __restrict__ out2)
{
    const int e = blockIdx.x * 128 + threadIdx.x;
    const size_t zb = (size_t)blockIdx.y * NCH * E_SZ;
    float s = 0.f;
#pragma unroll
    for (int ch = 0; ch < NCH; ++ch) s += part[zb + (size_t)ch * E_SZ + e];
    (blockIdx.y ? out2 : out1)[e] = s;
}

// wv[e] = Wo[e,:] . bv  — one block (256 thr) per row, deterministic reduce.
__global__ void rowvec(const float* __restrict__ Wo, const float* __restrict__ bv,
                       float* __restrict__ out)
{
    __shared__ float red[256];
    const int e = blockIdx.x;
    const int t = threadIdx.x;
    const float4* r = reinterpret_cast<const float4*>(Wo + (size_t)e * HE_SZ);
    const float4* b4 = reinterpret_cast<const float4*>(bv);
    float s = 0.f;
#pragma unroll
    for (int i = 0; i < 4; ++i) {
        const float4 a = r[t + i * 256];
        const float4 b = b4[t + i * 256];
        s += a.x * b.x + a.y * b.y + a.z * b.z + a.w * b.w;
    }
    red[t] = s;
    __syncthreads();
    for (int o = 128; o; o >>= 1) {
        if (t < o) red[t] += red[t + o];
        __syncthreads();
    }
    if (t == 0) out[e] = red[0];
}

__global__ void dotscalar(const float* __restrict__ a, const float* __restrict__ b,
                          float* __restrict__ out)
{
    __shared__ float red[256];
    float s = 0.f;
    for (int i = threadIdx.x; i < HE_SZ; i += 256) s += a[i] * b[i];
    red[threadIdx.x] = s;
    __syncthreads();
    for (int o = 128; o; o >>= 1) {
        if (threadIdx.x < o) red[threadIdx.x] += red[threadIdx.x + o];
        __syncthreads();
    }
    if (threadIdx.x == 0) out[0] = red[0];
}

// Fused u/w: z=0: u[r] = query[r,:].a1 ; z=1: w[r] = key[r,:].a2 + c
__global__ void dotvec2(const float* __restrict__ query, const float* __restrict__ key,
                        const float* __restrict__ a1, const float* __restrict__ a2,
                        const float* __restrict__ cptr,
                        float* __restrict__ u, float* __restrict__ w)
{
    const int wid = threadIdx.x >> 5;
    const int lane = threadIdx.x & 31;
    const int r = blockIdx.x * 8 + wid;
    const bool isw = blockIdx.y != 0;
    const float* in = isw ? key : query;
    const float* vec = isw ? a2 : a1;
    const float4* p = reinterpret_cast<const float4*>(in + (size_t)r * E_SZ);
    const float4* v4 = reinterpret_cast<const float4*>(vec);
    float s = 0.f;
#pragma unroll
    for (int i = 0; i < 4; ++i) {
        const float4 a = p[lane + i * 32];
        const float4 b = v4[lane + i * 32];
        s += a.x * b.x + a.y * b.y + a.z * b.z + a.w * b.w;
    }
#pragma unroll
    for (int o = 16; o; o >>= 1) s += __shfl_xor_sync(0xffffffffu, s, o);
    if (lane == 0) {
        if (isw) w[r] = s + cptr[0];
        else u[r] = s;
    }
}

extern "C" void kernel_launch(void* const* d_in, const int* in_sizes, int n_in,
                              void* d_out, int out_size)
{
    (void)in_sizes; (void)n_in; (void)out_size;
    const float* key   = (const float*)d_in[0];
    const float* value = (const float*)d_in[1];
    const float* query = (const float*)d_in[2];
    const float* Wk = (const float*)d_in[3];
    const float* bk = (const float*)d_in[4];
    const float* Wv = (const float*)d_in[5];
    const float* bv = (const float*)d_in[6];
    const float* Wq = (const float*)d_in[7];
    const float* bq = (const float*)d_in[8];
    const float* Wo = (const float*)d_in[9];
    const float* bo = (const float*)d_in[10];
    float* out = (float*)d_out;

    float *att, *vpT, *qM, *WqT, *Mm, *Pm, *part, *cpart;
    float *a1, *a2, *wv, *cs, *u, *w, *rs;
    cudaGetSymbolAddress((void**)&att, g_att);
    cudaGetSymbolAddress((void**)&vpT, g_vpT);
    cudaGetSymbolAddress((void**)&qM, g_qM);
    cudaGetSymbolAddress((void**)&WqT, g_WqT);
    cudaGetSymbolAddress((void**)&Mm, g_M);
    cudaGetSymbolAddress((void**)&Pm, g_P);
    cudaGetSymbolAddress((void**)&part, g_part);
    cudaGetSymbolAddress((void**)&cpart, g_cpart);
    cudaGetSymbolAddress((void**)&a1, g_a1);
    cudaGetSymbolAddress((void**)&a2, g_a2);
    cudaGetSymbolAddress((void**)&wv, g_wv);
    cudaGetSymbolAddress((void**)&cs, g_c);
    cudaGetSymbolAddress((void**)&u, g_u);
    cudaGetSymbolAddress((void**)&w, g_w);
    cudaGetSymbolAddress((void**)&rs, g_rs);

    cudaFuncSetAttribute((const void*)gemm_tf32<true, 0>,
                         cudaFuncAttributeMaxDynamicSharedMemorySize, SMEM_BYTES);
    cudaFuncSetAttribute((const void*)gemm_tf32<true, 1>,
                         cudaFuncAttributeMaxDynamicSharedMemorySize, SMEM_BYTES);
    cudaFuncSetAttribute((const void*)gemm_tf32<true, 2>,
                         cudaFuncAttributeMaxDynamicSharedMemorySize, SMEM_BYTES);
    cudaFuncSetAttribute((const void*)gemm_tf32<false, 0>,
                         cudaFuncAttributeMaxDynamicSharedMemorySize, SMEM_BYTES);

    const int MT = B_SZ * T_SZ;  // 16384
    const dim3 blk(256);
    const long long sTE = (long long)T_SZ * E_SZ;
    const long long sTT = (long long)T_SZ * T_SZ;
    const long long sET = (long long)E_SZ * T_SZ;
    const long long sEE = (long long)E_SZ * E_SZ;
    const int KC = HE_SZ / NSPLIT;  // 512

    // --- small precomputations ---
    transpose32<<<dim3(HE_SZ / 32, E_SZ / 32), dim3(32, 8)>>>(Wq, WqT, HE_SZ, E_SZ);
    colvec_part<<<dim3(E_SZ / 128, NCH, 2), 128>>>(Wq, bk, Wk, bq, cpart);
    colvec_red<<<dim3(E_SZ / 128, 2), 128>>>(cpart, a1, a2);
    rowvec<<<E_SZ, 256>>>(Wo, bv, wv);
    dotscalar<<<1, 256>>>(bq, bk, cs);
    dotvec2<<<dim3(MT / 8, 2), 256>>>(query, key, a1, a2, cs, u, w);

    // M = WqT @ Wk  via split-K (z = K chunk)
    gemm_tf32<false, 0><<<dim3(E_SZ / 256, E_SZ / 128, NSPLIT), blk, SMEM_BYTES>>>(
        WqT, Wk, nullptr, nullptr, nullptr, part, E_SZ, E_SZ, KC, HE_SZ, 1.f,
        KC, (long long)KC * E_SZ, sEE, 0, 0);
    reduce_splits<<<(E_SZ * E_SZ / 4 + 255) / 256, 256>>>((float4*)part, (float4*)Mm, E_SZ * E_SZ / 4);
    // P = Wo @ Wv  via split-K
    gemm_tf32<false, 0><<<dim3(E_SZ / 256, E_SZ / 128, NSPLIT), blk, SMEM_BYTES>>>(
        Wo, Wv, nullptr, nullptr, nullptr, part, E_SZ, E_SZ, KC, HE_SZ, 1.f,
        KC, (long long)KC * E_SZ, sEE, 0, 0);
    reduce_splits<<<(E_SZ * E_SZ / 4 + 255) / 256, 256>>>((float4*)part, (float4*)Pm, E_SZ * E_SZ / 4);

    // qM = query @ M (NN): [16384,512]@[512,512]
    gemm_tf32<false, 0><<<dim3(E_SZ / 256, MT / 128, 1), blk, SMEM_BYTES>>>(
        query, Mm, nullptr, nullptr, nullptr, qM, MT, E_SZ, E_SZ, E_SZ, 1.f, 0, 0, 0, 0, 0);
    // vpT = P @ value^T per batch (TRANS): C[E,T]
    gemm_tf32<true, 0><<<dim3(T_SZ / 256, E_SZ / 128, B_SZ), blk, SMEM_BYTES>>>(
        Pm, value, nullptr, nullptr, nullptr, vpT, E_SZ, T_SZ, E_SZ, E_SZ, 1.f,
        0, sTE, sET, 0, 0);
    // logits: att = SCALE*(qM @ key^T + u + w) per batch
    gemm_tf32<true, 1><<<dim3(T_SZ / 256, T_SZ / 128, B_SZ), blk, SMEM_BYTES>>>(
        qM, key, u, w, nullptr, att, T_SZ, T_SZ, E_SZ, E_SZ, SCALE_F,
        sTE, sTE, sTT, T_SZ, T_SZ);
    // fused batch-axis softmax + row sums
    softmax_rows<<<T_SZ, 512>>>(att, rs);
    // out = att @ vpT^T + rs (x) wv + bo   per batch
    gemm_tf32<true, 2><<<dim3(E_SZ / 256, T_SZ / 128, B_SZ), blk, SMEM_BYTES>>>(
        att, vpT, rs, wv, bo, out, T_SZ, E_SZ, T_SZ, T_SZ, 1.f,
        sTT, sET, sTE, T_SZ, 0);
}

// round 11
// speedup vs baseline: 14.3207x; 1.6783x over previous
#include <cuda_runtime.h>
#include <cuda_fp16.h>
#include <cstdint>
#include <cstddef>

// ---------------------------------------------------------------------------
// MultiheadedAttention2 (batch-axis softmax) — v10: fp16 mma.sync GEMMs.
//   Same v6-v8 algebra:
//     att = softmax_b( SCALE*(qM@key^T + u + w) ),  qM = query@M, M = Wq^T Wk
//     out = att@vpT^T + rowsum(att) (x) wv + bo,    vpT = P@value^T, P = Wo Wv
//   fp16 operands (11-bit significand == tf32), fp32 accumulation: 2x the
//   tf32 mma.sync instruction rate. All GEMMs A@B^T, CTA 128x256, warp 64x64,
//   TILE_K=64 halves, 4-stage cp.async. Bias terms u/w/c/wv/bo exact fp32.
// ---------------------------------------------------------------------------

#define B_SZ 8
#define T_SZ 2048
#define E_SZ 512
#define HE_SZ 4096
#define SCALE_F 0.04419417382415922f  // 512^-0.5

#define STAGES 4
#define ROWH 72                         // padded row: 72 halves = 144 B
#define A_HALFS (128 * ROWH)            // 9216
#define B_HALFS (256 * ROWH)            // 18432
#define STAGE_HALFS (A_HALFS + B_HALFS) // 27648
#define GSMEM_BYTES (STAGES * STAGE_HALFS * 2)  // 221184
#define NSPLIT 8
#define NCH 64

// Scratch (device globals; allocation-free rule)
__device__ float  g_att[(size_t)B_SZ * T_SZ * T_SZ];    // logits (fp32)
__device__ __half g_atth[(size_t)B_SZ * T_SZ * T_SZ];   // att (fp16)
__device__ __half g_qh[(size_t)B_SZ * T_SZ * E_SZ];
__device__ __half g_kh[(size_t)B_SZ * T_SZ * E_SZ];
__device__ __half g_vh[(size_t)B_SZ * T_SZ * E_SZ];
__device__ __half g_Woh[(size_t)E_SZ * HE_SZ];
__device__ __half g_WqT[(size_t)E_SZ * HE_SZ];
__device__ __half g_WkT[(size_t)E_SZ * HE_SZ];
__device__ __half g_WvT[(size_t)E_SZ * HE_SZ];
__device__ __half g_MTh[(size_t)E_SZ * E_SZ];
__device__ __half g_Ph[(size_t)E_SZ * E_SZ];
__device__ __half g_qMh[(size_t)B_SZ * T_SZ * E_SZ];
__device__ __half g_vpTh[(size_t)B_SZ * E_SZ * T_SZ];
__device__ float  g_part[(size_t)NSPLIT * E_SZ * E_SZ];
__device__ float  g_cpart[(size_t)2 * NCH * E_SZ];
__device__ float  g_a1[E_SZ];
__device__ float  g_a2[E_SZ];
__device__ float  g_wv[E_SZ];
__device__ float  g_c[1];
__device__ float  g_u[(size_t)B_SZ * T_SZ];
__device__ float  g_w[(size_t)B_SZ * T_SZ];
__device__ float  g_rs[(size_t)B_SZ * T_SZ];

static __device__ __forceinline__ void mma_f16(float* c, const uint32_t* a, const uint32_t* b) {
    asm volatile(
        "mma.sync.aligned.m16n8k16.row.col.f32.f16.f16.f32 "
        "{%0,%1,%2,%3}, {%4,%5,%6,%7}, {%8,%9}, {%0,%1,%2,%3};\n"
        : "+f"(c[0]), "+f"(c[1]), "+f"(c[2]), "+f"(c[3])
        : "r"(a[0]), "r"(a[1]), "r"(a[2]), "r"(a[3]), "r"(b[0]), "r"(b[1]));
}

static __device__ __forceinline__ void cp_async16(const __half* smem_dst, const __half* g) {
    uint32_t s = (uint32_t)__cvta_generic_to_shared(smem_dst);
    asm volatile("cp.async.cg.shared.global [%0], [%1], 16;\n" :: "r"(s), "l"(g));
}
static __device__ __forceinline__ void cp_commit() {
    asm volatile("cp.async.commit_group;\n");
}
template <int N>
static __device__ __forceinline__ void cp_wait() {
    asm volatile("cp.async.wait_group %0;\n" :: "n"(N));
}

// ---------------------------------------------------------------------------
// fp16 GEMM: C[M,N] = f(A @ B^T).  A [M,K] halves (row stride ldA), B [N,K]
// halves (row stride ldB). CTA tile 128x256, warp tile 64x64, TILE_K=64.
// EPI=0: v = alpha*acc
// EPI=1: v = alpha*(acc + rowv[row] + colv[col])
// EPI=2: v = acc + rowv[row]*colv[col] + bias[col]
// OUT_HALF: C is __half (round-to-nearest), else float.
// ---------------------------------------------------------------------------
template <int EPI, bool OUT_HALF>
__global__ __launch_bounds__(256, 1)
void gemm_h(const __half* __restrict__ A, const __half* __restrict__ Bm,
            const float* __restrict__ rowv, const float* __restrict__ colv,
            const float* __restrict__ bias, void* __restrict__ Cv,
            int Ndim, int K, long long ldA, long long ldB, float alpha,
            long long sA, long long sB, long long sC,
            long long sRow, long long sCol)
{
    extern __shared__ __half smem[];

    const __half* Ab = A + (long long)blockIdx.z * sA;
    const __half* Bb = Bm + (long long)blockIdx.z * sB;

    const int bm = blockIdx.y * 128;
    const int bn = blockIdx.x * 256;
    const int tid = threadIdx.x;
    const int lane = tid & 31;
    const int warp = tid >> 5;          // 0..7
    const int wm = (warp & 1) * 64;     // 2 warps down M
    const int wn = (warp >> 1) * 64;    // 4 warps across N
    const int gr = lane >> 2;           // 0..7
    const int gc = lane & 3;            // 0..3

    float acc[4][8][4];
#pragma unroll
    for (int i = 0; i < 4; ++i)
#pragma unroll
        for (int j = 0; j < 8; ++j)
#pragma unroll
            for (int r = 0; r < 4; ++r) acc[i][j][r] = 0.f;

    const int nk = K >> 6;

    auto load_tile = [&](int kt) {
        const int stage = kt & (STAGES - 1);
        __half* sAh = smem + stage * STAGE_HALFS;
        __half* sBh = sAh + A_HALFS;
        const int k0g = kt << 6;
#pragma unroll
        for (int i = 0; i < 4; ++i) {
            const int ci = tid + i * 256;
            const int row = ci >> 3;
            const int ch = (ci & 7) * 8;
            cp_async16(sAh + row * ROWH + ch, Ab + (size_t)(bm + row) * ldA + k0g + ch);
        }
#pragma unroll
        for (int i = 0; i < 8; ++i) {
            const int ci = tid + i * 256;
            const int row = ci >> 3;
            const int ch = (ci & 7) * 8;
            cp_async16(sBh + row * ROWH + ch, Bb + (size_t)(bn + row) * ldB + k0g + ch);
        }
    };

#pragma unroll
    for (int s = 0; s < STAGES - 1; ++s) {
        load_tile(s);
        cp_commit();
    }

    for (int kt = 0; kt < nk; ++kt) {
        const int stage = kt & (STAGES - 1);
        cp_wait<STAGES - 2>();
        __syncthreads();

        const int pf = kt + STAGES - 1;
        if (pf < nk) load_tile(pf);
        cp_commit();

        const __half* sAh = smem + stage * STAGE_HALFS;
        const __half* sBh = sAh + A_HALFS;

#pragma unroll
        for (int k0 = 0; k0 < 64; k0 += 16) {
            uint32_t a[4][4];
#pragma unroll
            for (int i = 0; i < 4; ++i) {
                const int r = wm + i * 16 + gr;
                a[i][0] = *reinterpret_cast<const uint32_t*>(sAh + (size_t)r * ROWH + k0 + 2 * gc);
                a[i][1] = *reinterpret_cast<const uint32_t*>(sAh + (size_t)(r + 8) * ROWH + k0 + 2 * gc);
                a[i][2] = *reinterpret_cast<const uint32_t*>(sAh + (size_t)r * ROWH + k0 + 2 * gc + 8);
                a[i][3] = *reinterpret_cast<const uint32_t*>(sAh + (size_t)(r + 8) * ROWH + k0 + 2 * gc + 8);
            }
            uint32_t b[8][2];
#pragma unroll
            for (int j = 0; j < 8; ++j) {
                const int cn = wn + j * 8 + gr;
                b[j][0] = *reinterpret_cast<const uint32_t*>(sBh + (size_t)cn * ROWH + k0 + 2 * gc);
                b[j][1] = *reinterpret_cast<const uint32_t*>(sBh + (size_t)cn * ROWH + k0 + 2 * gc + 8);
            }
#pragma unroll
            for (int i = 0; i < 4; ++i)
#pragma unroll
                for (int j = 0; j < 8; ++j) mma_f16(acc[i][j], a[i], b[j]);
        }
        __syncthreads();
    }

    const float* rv = (EPI != 0) ? rowv + (long long)blockIdx.z * sRow : nullptr;
    const float* cv = (EPI != 0) ? colv + (long long)blockIdx.z * sCol : nullptr;

    float* Cf = (float*)Cv + (long long)blockIdx.z * sC;
    __half* Ch = (__half*)Cv + (long long)blockIdx.z * sC;

#pragma unroll
    for (int i = 0; i < 4; ++i) {
#pragma unroll
        for (int j = 0; j < 8; ++j) {
            const int row = bm + wm + i * 16 + gr;
            const int col = bn + wn + j * 8 + gc * 2;
            float v0 = acc[i][j][0], v1 = acc[i][j][1];
            float v2 = acc[i][j][2], v3 = acc[i][j][3];
            if (EPI == 0) {
                v0 *= alpha; v1 *= alpha; v2 *= alpha; v3 *= alpha;
            } else if (EPI == 1) {
                const float u0 = rv[row], u8 = rv[row + 8];
                const float w0 = cv[col], w1 = cv[col + 1];
                v0 = (v0 + u0 + w0) * alpha;
                v1 = (v1 + u0 + w1) * alpha;
                v2 = (v2 + u8 + w0) * alpha;
                v3 = (v3 + u8 + w1) * alpha;
            } else {
                const float r0 = rv[row], r8 = rv[row + 8];
                const float w0 = cv[col], w1 = cv[col + 1];
                const float b0 = bias[col], b1 = bias[col + 1];
                v0 = v0 + r0 * w0 + b0;
                v1 = v1 + r0 * w1 + b1;
                v2 = v2 + r8 * w0 + b0;
                v3 = v3 + r8 * w1 + b1;
            }
            if (OUT_HALF) {
                *reinterpret_cast<__half2*>(Ch + (size_t)row * Ndim + col) =
                    __floats2half2_rn(v0, v1);
                *reinterpret_cast<__half2*>(Ch + (size_t)(row + 8) * Ndim + col) =
                    __floats2half2_rn(v2, v3);
            } else {
                Cf[(size_t)row * Ndim + col] = v0;
                Cf[(size_t)row * Ndim + col + 1] = v1;
                Cf[(size_t)(row + 8) * Ndim + col] = v2;
                Cf[(size_t)(row + 8) * Ndim + col + 1] = v3;
            }
        }
    }
}

// float -> half copy, up to 3 tensors per launch (grid.y selects).
__global__ void copy_f2h3(const float4* __restrict__ i0, __half* __restrict__ o0,
                          const float4* __restrict__ i1, __half* __restrict__ o1,
                          const float4* __restrict__ i2, __half* __restrict__ o2,
                          int n4)
{
    const int i = blockIdx.x * 256 + threadIdx.x;
    if (i >= n4) return;
    const float4* in = (blockIdx.y == 0) ? i0 : (blockIdx.y == 1) ? i1 : i2;
    __half* out = (blockIdx.y == 0) ? o0 : (blockIdx.y == 1) ? o1 : o2;
    const float4 v = in[i];
    const __half2 h01 = __floats2half2_rn(v.x, v.y);
    const __half2 h23 = __floats2half2_rn(v.z, v.w);
    uint2 pk;
    pk.x = *reinterpret_cast<const uint32_t*>(&h01);
    pk.y = *reinterpret_cast<const uint32_t*>(&h23);
    *reinterpret_cast<uint2*>(out + (size_t)i * 4) = pk;
}

// 32x32 tiled transpose, float in -> half out: outT[c][r] = h(in[r][c]).
__global__ void transpose32h(const float* __restrict__ in, __half* __restrict__ outT,
                             int R, int Cc)
{
    __shared__ float sm[32][33];
    const int r0 = blockIdx.x * 32;
    const int c0 = blockIdx.y * 32;
    const int tx = threadIdx.x, ty = threadIdx.y;
#pragma unroll
    for (int q = 0; q < 4; ++q)
        sm[ty + q * 8][tx] = in[(size_t)(r0 + ty + q * 8) * Cc + c0 + tx];
    __syncthreads();
#pragma unroll
    for (int q = 0; q < 4; ++q)
        outT[(size_t)(c0 + ty + q * 8) * R + r0 + tx] = __float2half_rn(sm[tx][ty + q * 8]);
}

// Sum NSPLIT partial matrices (deterministic), emit half.
__global__ void reduce_splits_h(const float4* __restrict__ part, __half* __restrict__ out,
                                int n4)
{
    const int i = blockIdx.x * blockDim.x + threadIdx.x;
    if (i >= n4) return;
    float4 s = part[i];
#pragma unroll
    for (int p = 1; p < NSPLIT; ++p) {
        const float4 v = part[(size_t)p * n4 + i];
        s.x += v.x; s.y += v.y; s.z += v.z; s.w += v.w;
    }
    const __half2 h01 = __floats2half2_rn(s.x, s.y);
    const __half2 h23 = __floats2half2_rn(s.z, s.w);
    uint2 pk;
    pk.x = *reinterpret_cast<const uint32_t*>(&h01);
    pk.y = *reinterpret_cast<const uint32_t*>(&h23);
    *reinterpret_cast<uint2*>(out + (size_t)i * 4) = pk;
}

// Fused batch-axis softmax + per-(b,t) row sums. fp32 in, fp16 att out.
__global__ __launch_bounds__(512)
void softmax_rows(const float* __restrict__ d, __half* __restrict__ atth,
                  float* __restrict__ rs)
{
    __shared__ float red[16][8];
    const int t = blockIdx.x;
    const int j = threadIdx.x;
    const size_t plane4 = (size_t)T_SZ * T_SZ / 4;
    const float4* p = reinterpret_cast<const float4*>(d);
    const size_t base = (size_t)t * (T_SZ / 4) + j;

    float4 v[B_SZ];
    float4 m = make_float4(-1e30f, -1e30f, -1e30f, -1e30f);
#pragma unroll
    for (int b = 0; b < B_SZ; ++b) {
        v[b] = p[(size_t)b * plane4 + base];
        m.x = fmaxf(m.x, v[b].x); m.y = fmaxf(m.y, v[b].y);
        m.z = fmaxf(m.z, v[b].z); m.w = fmaxf(m.w, v[b].w);
    }
    float4 s = make_float4(0.f, 0.f, 0.f, 0.f);
#pragma unroll
    for (int b = 0; b < B_SZ; ++b) {
        v[b].x = __expf(v[b].x - m.x); s.x += v[b].x;
        v[b].y = __expf(v[b].y - m.y); s.y += v[b].y;
        v[b].z = __expf(v[b].z - m.z); s.z += v[b].z;
        v[b].w = __expf(v[b].w - m.w); s.w += v[b].w;
    }
    s.x = 1.f / s.x; s.y = 1.f / s.y; s.z = 1.f / s.z; s.w = 1.f / s.w;

    float bsum[B_SZ];
#pragma unroll
    for (int b = 0; b < B_SZ; ++b) {
        v[b].x *= s.x; v[b].y *= s.y; v[b].z *= s.z; v[b].w *= s.w;
        const __half2 h01 = __floats2half2_rn(v[b].x, v[b].y);
        const __half2 h23 = __floats2half2_rn(v[b].z, v[b].w);
        // half-rounded values feed attend; use them for the row sum too so
        // rs matches what the GEMM actually sums (consistency, not accuracy).
        const float hx = __half2float(__low2half(h01)), hy = __half2float(__high2half(h01));
        const float hz = __half2float(__low2half(h23)), hw = __half2float(__high2half(h23));
        uint2 pk;
        pk.x = *reinterpret_cast<const uint32_t*>(&h01);
        pk.y = *reinterpret_cast<const uint32_t*>(&h23);
        *reinterpret_cast<uint2*>(atth + (size_t)b * T_SZ * T_SZ + (size_t)t * T_SZ + j * 4) = pk;
        bsum[b] = (hx + hy) + (hz + hw);
    }
#pragma unroll
    for (int b = 0; b < B_SZ; ++b) {
#pragma unroll
        for (int o = 16; o; o >>= 1) bsum[b] += __shfl_xor_sync(0xffffffffu, bsum[b], o);
    }
    const int wid = j >> 5;
    if ((j & 31) == 0) {
#pragma unroll
        for (int b = 0; b < B_SZ; ++b) red[wid][b] = bsum[b];
    }
    __syncthreads();
    if (j < B_SZ) {
        float acc = 0.f;
#pragma unroll
        for (int w2 = 0; w2 < 16; ++w2) acc += red[w2][j];
        rs[(size_t)j * T_SZ + t] = acc;
    }
}

// colvec stage 1 (both weights, grid z in {0,1}).
__global__ void colvec_part(const float* __restrict__ W1, const float* __restrict__ b1,
                            const float* __restrict__ W2, const float* __restrict__ b2,
                            float* __restrict__ part)
{
    const float* W = blockIdx.z ? W2 : W1;
    const float* b = blockIdx.z ? b2 : b1;
    const int e = blockIdx.x * 128 + threadIdx.x;
    const int ch = blockIdx.y;
    const int h0 = ch * (HE_SZ / NCH);
    float s0 = 0.f, s1 = 0.f;
#pragma unroll
    for (int h = h0; h < h0 + HE_SZ / NCH; h += 2) {
        s0 += W[(size_t)h * E_SZ + e] * b[h];
        s1 += W[(size_t)(h + 1) * E_SZ + e] * b[h + 1];
    }
    part[((size_t)blockIdx.z * NCH + ch) * E_SZ + e] = s0 + s1;
}
__global__ void colvec_red(const float* __restrict__ part,
                           float* __restrict__ out1, float* __restrict__ out2)
{
    const int e = blockIdx.x * 128 + threadIdx.x;
    const size_t zb = (size_t)blockIdx.y * NCH * E_SZ;
    float s = 0.f;
#pragma unroll
    for (int ch = 0; ch < NCH; ++ch) s += part[zb + (size_t)ch * E_SZ + e];
    (blockIdx.y ? out2 : out1)[e] = s;
}

// wv[e] = Wo[e,:] . bv
__global__ void rowvec(const float* __restrict__ Wo, const float* __restrict__ bv,
                       float* __restrict__ out)
{
    __shared__ float red[256];
    const int e = blockIdx.x;
    const int t = threadIdx.x;
    const float4* r = reinterpret_cast<const float4*>(Wo + (size_t)e * HE_SZ);
    const float4* b4 = reinterpret_cast<const float4*>(bv);
    float s = 0.f;
#pragma unroll
    for (int i = 0; i < 4; ++i) {
        const float4 a = r[t + i * 256];
        const float4 b = b4[t + i * 256];
        s += a.x * b.x + a.y * b.y + a.z * b.z + a.w * b.w;
    }
    red[t] = s;
    __syncthreads();
    for (int o = 128; o; o >>= 1) {
        if (t < o) red[t] += red[t + o];
        __syncthreads();
    }
    if (t == 0) out[e] = red[0];
}

__global__ void dotscalar(const float* __restrict__ a, const float* __restrict__ b,
                          float* __restrict__ out)
{
    __shared__ float red[256];
    float s = 0.f;
    for (int i = threadIdx.x; i < HE_SZ; i += 256) s += a[i] * b[i];
    red[threadIdx.x] = s;
    __syncthreads();
    for (int o = 128; o; o >>= 1) {
        if (threadIdx.x < o) red[threadIdx.x] += red[threadIdx.x + o];
        __syncthreads();
    }
    if (threadIdx.x == 0) out[0] = red[0];
}

// Fused u/w: y=0: u[r] = query[r,:].a1 ; y=1: w[r] = key[r,:].a2 + c
__global__ void dotvec2(const float* __restrict__ query, const float* __restrict__ key,
                        const float* __restrict__ a1, const float* __restrict__ a2,
                        const float* __restrict__ cptr,
                        float* __restrict__ u, float* __restrict__ w)
{
    const int wid = threadIdx.x >> 5;
    const int lane = threadIdx.x & 31;
    const int r = blockIdx.x * 8 + wid;
    const bool isw = blockIdx.y != 0;
    const float* in = isw ? key : query;
    const float* vec = isw ? a2 : a1;
    const float4* p = reinterpret_cast<const float4*>(in + (size_t)r * E_SZ);
    const float4* v4 = reinterpret_cast<const float4*>(vec);
    float s = 0.f;
#pragma unroll
    for (int i = 0; i < 4; ++i) {
        const float4 a = p[lane + i * 32];
        const float4 b = v4[lane + i * 32];
        s += a.x * b.x + a.y * b.y + a.z * b.z + a.w * b.w;
    }
#pragma unroll
    for (int o = 16; o; o >>= 1) s += __shfl_xor_sync(0xffffffffu, s, o);
    if (lane == 0) {
        if (isw) w[r] = s + cptr[0];
        else u[r] = s;
    }
}

extern "C" void kernel_launch(void* const* d_in, const int* in_sizes, int n_in,
                              void* d_out, int out_size)
{
    (void)in_sizes; (void)n_in; (void)out_size;
    const float* key   = (const float*)d_in[0];
    const float* value = (const float*)d_in[1];
    const float* query = (const float*)d_in[2];
    const float* Wk = (const float*)d_in[3];
    const float* bk = (const float*)d_in[4];
    const float* Wv = (const float*)d_in[5];
    const float* bv = (const float*)d_in[6];
    const float* Wq = (const float*)d_in[7];
    const float* bq = (const float*)d_in[8];
    const float* Wo = (const float*)d_in[9];
    const float* bo = (const float*)d_in[10];
    float* out = (float*)d_out;

    float *att, *part, *cpart, *a1, *a2, *wv, *cs, *u, *w, *rs;
    __half *atth, *qh, *kh, *vh, *Woh, *WqT, *WkT, *WvT, *MTh, *Ph, *qMh, *vpTh;
    cudaGetSymbolAddress((void**)&att, g_att);
    cudaGetSymbolAddress((void**)&atth, g_atth);
    cudaGetSymbolAddress((void**)&qh, g_qh);
    cudaGetSymbolAddress((void**)&kh, g_kh);
    cudaGetSymbolAddress((void**)&vh, g_vh);
    cudaGetSymbolAddress((void**)&Woh, g_Woh);
    cudaGetSymbolAddress((void**)&WqT, g_WqT);
    cudaGetSymbolAddress((void**)&WkT, g_WkT);
    cudaGetSymbolAddress((void**)&WvT, g_WvT);
    cudaGetSymbolAddress((void**)&MTh, g_MTh);
    cudaGetSymbolAddress((void**)&Ph, g_Ph);
    cudaGetSymbolAddress((void**)&qMh, g_qMh);
    cudaGetSymbolAddress((void**)&vpTh, g_vpTh);
    cudaGetSymbolAddress((void**)&part, g_part);
    cudaGetSymbolAddress((void**)&cpart, g_cpart);
    cudaGetSymbolAddress((void**)&a1, g_a1);
    cudaGetSymbolAddress((void**)&a2, g_a2);
    cudaGetSymbolAddress((void**)&wv, g_wv);
    cudaGetSymbolAddress((void**)&cs, g_c);
    cudaGetSymbolAddress((void**)&u, g_u);
    cudaGetSymbolAddress((void**)&w, g_w);
    cudaGetSymbolAddress((void**)&rs, g_rs);

    cudaFuncSetAttribute((const void*)gemm_h<0, false>,
                         cudaFuncAttributeMaxDynamicSharedMemorySize, GSMEM_BYTES);
    cudaFuncSetAttribute((const void*)gemm_h<0, true>,
                         cudaFuncAttributeMaxDynamicSharedMemorySize, GSMEM_BYTES);
    cudaFuncSetAttribute((const void*)gemm_h<1, false>,
                         cudaFuncAttributeMaxDynamicSharedMemorySize, GSMEM_BYTES);
    cudaFuncSetAttribute((const void*)gemm_h<2, false>,
                         cudaFuncAttributeMaxDynamicSharedMemorySize, GSMEM_BYTES);

    const int MT_ROWS = B_SZ * T_SZ;  // 16384
    const dim3 blk(256);
    const long long sTE = (long long)T_SZ * E_SZ;
    const long long sTT = (long long)T_SZ * T_SZ;
    const long long sET = (long long)E_SZ * T_SZ;
    const long long sEE = (long long)E_SZ * E_SZ;
    const int KC = HE_SZ / NSPLIT;  // 512

    // --- pre-pass ---
    {
        const int nin4 = MT_ROWS * E_SZ / 4;
        copy_f2h3<<<dim3((nin4 + 255) / 256, 3), 256>>>(
            (const float4*)query, qh, (const float4*)key, kh, (const float4*)value, vh, nin4);
        const int nw4 = E_SZ * HE_SZ / 4;
        copy_f2h3<<<dim3((nw4 + 255) / 256, 1), 256>>>(
            (const float4*)Wo, Woh, nullptr, nullptr, nullptr, nullptr, nw4);
        transpose32h<<<dim3(HE_SZ / 32, E_SZ / 32), dim3(32, 8)>>>(Wq, WqT, HE_SZ, E_SZ);
        transpose32h<<<dim3(HE_SZ / 32, E_SZ / 32), dim3(32, 8)>>>(Wk, WkT, HE_SZ, E_SZ);
        transpose32h<<<dim3(HE_SZ / 32, E_SZ / 32), dim3(32, 8)>>>(Wv, WvT, HE_SZ, E_SZ);
        colvec_part<<<dim3(E_SZ / 128, NCH, 2), 128>>>(Wq, bk, Wk, bq, cpart);
        colvec_red<<<dim3(E_SZ / 128, 2), 128>>>(cpart, a1, a2);
        rowvec<<<E_SZ, 256>>>(Wo, bv, wv);
        dotscalar<<<1, 256>>>(bq, bk, cs);
        dotvec2<<<dim3(MT_ROWS / 8, 2), 256>>>(query, key, a1, a2, cs, u, w);
    }

    // M^T = WkT @ WqT^T  (split-K over HE) -> part -> half MTh
    gemm_h<0, false><<<dim3(E_SZ / 256, E_SZ / 128, NSPLIT), blk, GSMEM_BYTES>>>(
        WkT, WqT, nullptr, nullptr, nullptr, part, E_SZ, KC, HE_SZ, HE_SZ, 1.f,
        KC, KC, sEE, 0, 0);
    reduce_splits_h<<<(E_SZ * E_SZ / 4 + 255) / 256, 256>>>((float4*)part, MTh,
                                                            E_SZ * E_SZ / 4);
    // P = Woh @ WvT^T -> part -> half Ph
    gemm_h<0, false><<<dim3(E_SZ / 256, E_SZ / 128, NSPLIT), blk, GSMEM_BYTES>>>(
        Woh, WvT, nullptr, nullptr, nullptr, part, E_SZ, KC, HE_SZ, HE_SZ, 1.f,
        KC, KC, sEE, 0, 0);
    reduce_splits_h<<<(E_SZ * E_SZ / 4 + 255) / 256, 256>>>((float4*)part, Ph,
                                                            E_SZ * E_SZ / 4);

    // qM = qh @ MTh^T   [16384,512] (half out)
    gemm_h<0, true><<<dim3(E_SZ / 256, MT_ROWS / 128, 1), blk, GSMEM_BYTES>>>(
        qh, MTh, nullptr, nullptr, nullptr, qMh, E_SZ, E_SZ, E_SZ, E_SZ, 1.f,
        0, 0, 0, 0, 0);
    // vpT = Ph @ vh^T per batch  [512,2048] (half out)
    gemm_h<0, true><<<dim3(T_SZ / 256, E_SZ / 128, B_SZ), blk, GSMEM_BYTES>>>(
        Ph, vh, nullptr, nullptr, nullptr, vpTh, T_SZ, E_SZ, E_SZ, E_SZ, 1.f,
        0, sTE, sET, 0, 0);
    // logits: att = SCALE*(qMh @ kh^T + u + w) per batch (float out)
    gemm_h<1, false><<<dim3(T_SZ / 256, T_SZ / 128, B_SZ), blk, GSMEM_BYTES>>>(
        qMh, kh, u, w, nullptr, att, T_SZ, E_SZ, E_SZ, E_SZ, SCALE_F,
        sTE, sTE, sTT, T_SZ, T_SZ);
    // batch-axis softmax -> half att + row sums
    softmax_rows<<<T_SZ, 512>>>(att, atth, rs);
    // out = atth @ vpTh^T + rs (x) wv + bo per batch (float out)
    gemm_h<2, false><<<dim3(E_SZ / 256, T_SZ / 128, B_SZ), blk, GSMEM_BYTES>>>(
        atth, vpTh, rs, wv, bo, out, E_SZ, T_SZ, T_SZ, T_SZ, 1.f,
        sTT, sET, sTE, T_SZ, 0);
}

// round 12
// speedup vs baseline: 15.1414x; 1.0573x over previous
#include <cuda_runtime.h>
#include <cuda_fp16.h>
#include <cstdint>
#include <cstddef>

// ---------------------------------------------------------------------------
// MultiheadedAttention2 (batch-axis softmax) — v12: fp16 mma.sync GEMMs,
// fp16 logits buffer with in-place batch softmax.
//   att = softmax_b( SCALE*(qM@key^T + u + w) ),  qM = query@M, M = Wq^T Wk
//   out = att@vpT^T + rowsum(att) (x) wv + bo,    vpT = P@value^T, P = Wo Wv
// fp16 operands / fp32 accum; bias terms u/w/c/wv/bo exact fp32.
// ---------------------------------------------------------------------------

#define B_SZ 8
#define T_SZ 2048
#define E_SZ 512
#define HE_SZ 4096
#define SCALE_F 0.04419417382415922f  // 512^-0.5

#define STAGES 4
#define ROWH 72                         // padded row: 72 halves = 144 B
#define A_HALFS (128 * ROWH)            // 9216
#define B_HALFS (256 * ROWH)            // 18432
#define STAGE_HALFS (A_HALFS + B_HALFS) // 27648
#define GSMEM_BYTES (STAGES * STAGE_HALFS * 2)  // 221184
#define NSPLIT 8
#define NCH 64

// Scratch (device globals; allocation-free rule)
__device__ __half g_atth[(size_t)B_SZ * T_SZ * T_SZ];   // logits -> att (fp16)
__device__ __half g_qh[(size_t)B_SZ * T_SZ * E_SZ];
__device__ __half g_kh[(size_t)B_SZ * T_SZ * E_SZ];
__device__ __half g_vh[(size_t)B_SZ * T_SZ * E_SZ];
__device__ __half g_Woh[(size_t)E_SZ * HE_SZ];
__device__ __half g_WqT[(size_t)E_SZ * HE_SZ];
__device__ __half g_WkT[(size_t)E_SZ * HE_SZ];
__device__ __half g_WvT[(size_t)E_SZ * HE_SZ];
__device__ __half g_MTh[(size_t)E_SZ * E_SZ];
__device__ __half g_Ph[(size_t)E_SZ * E_SZ];
__device__ __half g_qMh[(size_t)B_SZ * T_SZ * E_SZ];
__device__ __half g_vpTh[(size_t)B_SZ * E_SZ * T_SZ];
__device__ float  g_part[(size_t)NSPLIT * E_SZ * E_SZ];
__device__ float  g_cpart[(size_t)2 * NCH * E_SZ];
__device__ float  g_a1[E_SZ];
__device__ float  g_a2[E_SZ];
__device__ float  g_wv[E_SZ];
__device__ float  g_c[1];
__device__ float  g_u[(size_t)B_SZ * T_SZ];
__device__ float  g_w[(size_t)B_SZ * T_SZ];
__device__ float  g_rs[(size_t)B_SZ * T_SZ];

static __device__ __forceinline__ void mma_f16(float* c, const uint32_t* a, const uint32_t* b) {
    asm volatile(
        "mma.sync.aligned.m16n8k16.row.col.f32.f16.f16.f32 "
        "{%0,%1,%2,%3}, {%4,%5,%6,%7}, {%8,%9}, {%0,%1,%2,%3};\n"
        : "+f"(c[0]), "+f"(c[1]), "+f"(c[2]), "+f"(c[3])
        : "r"(a[0]), "r"(a[1]), "r"(a[2]), "r"(a[3]), "r"(b[0]), "r"(b[1]));
}

static __device__ __forceinline__ void cp_async16(const __half* smem_dst, const __half* g) {
    uint32_t s = (uint32_t)__cvta_generic_to_shared(smem_dst);
    asm volatile("cp.async.cg.shared.global [%0], [%1], 16;\n" :: "r"(s), "l"(g));
}
static __device__ __forceinline__ void cp_commit() {
    asm volatile("cp.async.commit_group;\n");
}
template <int N>
static __device__ __forceinline__ void cp_wait() {
    asm volatile("cp.async.wait_group %0;\n" :: "n"(N));
}

// ---------------------------------------------------------------------------
// fp16 GEMM: C[M,N] = f(A @ B^T).  A [M,K] halves (row stride ldA), B [N,K]
// halves (row stride ldB). CTA tile 128x256, warp tile 64x64, TILE_K=64.
// EPI=0: v = alpha*acc
// EPI=1: v = alpha*(acc + rowv[row] + colv[col])
// EPI=2: v = acc + rowv[row]*colv[col] + bias[col]
// OUT_HALF: C is __half (round-to-nearest), else float.
// ---------------------------------------------------------------------------
template <int EPI, bool OUT_HALF>
__global__ __launch_bounds__(256, 1)
void gemm_h(const __half* __restrict__ A, const __half* __restrict__ Bm,
            const float* __restrict__ rowv, const float* __restrict__ colv,
            const float* __restrict__ bias, void* __restrict__ Cv,
            int Ndim, int K, long long ldA, long long ldB, float alpha,
            long long sA, long long sB, long long sC,
            long long sRow, long long sCol)
{
    extern __shared__ __half smem[];

    const __half* Ab = A + (long long)blockIdx.z * sA;
    const __half* Bb = Bm + (long long)blockIdx.z * sB;

    const int bm = blockIdx.y * 128;
    const int bn = blockIdx.x * 256;
    const int tid = threadIdx.x;
    const int lane = tid & 31;
    const int warp = tid >> 5;          // 0..7
    const int wm = (warp & 1) * 64;     // 2 warps down M
    const int wn = (warp >> 1) * 64;    // 4 warps across N
    const int gr = lane >> 2;           // 0..7
    const int gc = lane & 3;            // 0..3

    float acc[4][8][4];
#pragma unroll
    for (int i = 0; i < 4; ++i)
#pragma unroll
        for (int j = 0; j < 8; ++j)
#pragma unroll
            for (int r = 0; r < 4; ++r) acc[i][j][r] = 0.f;

    const int nk = K >> 6;

    auto load_tile = [&](int kt) {
        const int stage = kt & (STAGES - 1);
        __half* sAh = smem + stage * STAGE_HALFS;
        __half* sBh = sAh + A_HALFS;
        const int k0g = kt << 6;
#pragma unroll
        for (int i = 0; i < 4; ++i) {
            const int ci = tid + i * 256;
            const int row = ci >> 3;
            const int ch = (ci & 7) * 8;
            cp_async16(sAh + row * ROWH + ch, Ab + (size_t)(bm + row) * ldA + k0g + ch);
        }
#pragma unroll
        for (int i = 0; i < 8; ++i) {
            const int ci = tid + i * 256;
            const int row = ci >> 3;
            const int ch = (ci & 7) * 8;
            cp_async16(sBh + row * ROWH + ch, Bb + (size_t)(bn + row) * ldB + k0g + ch);
        }
    };

#pragma unroll
    for (int s = 0; s < STAGES - 1; ++s) {
        load_tile(s);
        cp_commit();
    }

    for (int kt = 0; kt < nk; ++kt) {
        const int stage = kt & (STAGES - 1);
        cp_wait<STAGES - 2>();
        __syncthreads();

        const int pf = kt + STAGES - 1;
        if (pf < nk) load_tile(pf);
        cp_commit();

        const __half* sAh = smem + stage * STAGE_HALFS;
        const __half* sBh = sAh + A_HALFS;

#pragma unroll
        for (int k0 = 0; k0 < 64; k0 += 16) {
            uint32_t a[4][4];
#pragma unroll
            for (int i = 0; i < 4; ++i) {
                const int r = wm + i * 16 + gr;
                a[i][0] = *reinterpret_cast<const uint32_t*>(sAh + (size_t)r * ROWH + k0 + 2 * gc);
                a[i][1] = *reinterpret_cast<const uint32_t*>(sAh + (size_t)(r + 8) * ROWH + k0 + 2 * gc);
                a[i][2] = *reinterpret_cast<const uint32_t*>(sAh + (size_t)r * ROWH + k0 + 2 * gc + 8);
                a[i][3] = *reinterpret_cast<const uint32_t*>(sAh + (size_t)(r + 8) * ROWH + k0 + 2 * gc + 8);
            }
            uint32_t b[8][2];
#pragma unroll
            for (int j = 0; j < 8; ++j) {
                const int cn = wn + j * 8 + gr;
                b[j][0] = *reinterpret_cast<const uint32_t*>(sBh + (size_t)cn * ROWH + k0 + 2 * gc);
                b[j][1] = *reinterpret_cast<const uint32_t*>(sBh + (size_t)cn * ROWH + k0 + 2 * gc + 8);
            }
#pragma unroll
            for (int i = 0; i < 4; ++i)
#pragma unroll
                for (int j = 0; j < 8; ++j) mma_f16(acc[i][j], a[i], b[j]);
        }
        __syncthreads();
    }

    const float* rv = (EPI != 0) ? rowv + (long long)blockIdx.z * sRow : nullptr;
    const float* cv = (EPI != 0) ? colv + (long long)blockIdx.z * sCol : nullptr;

    float* Cf = (float*)Cv + (long long)blockIdx.z * sC;
    __half* Ch = (__half*)Cv + (long long)blockIdx.z * sC;

#pragma unroll
    for (int i = 0; i < 4; ++i) {
#pragma unroll
        for (int j = 0; j < 8; ++j) {
            const int row = bm + wm + i * 16 + gr;
            const int col = bn + wn + j * 8 + gc * 2;
            float v0 = acc[i][j][0], v1 = acc[i][j][1];
            float v2 = acc[i][j][2], v3 = acc[i][j][3];
            if (EPI == 0) {
                v0 *= alpha; v1 *= alpha; v2 *= alpha; v3 *= alpha;
            } else if (EPI == 1) {
                const float u0 = rv[row], u8 = rv[row + 8];
                const float w0 = cv[col], w1 = cv[col + 1];
                v0 = (v0 + u0 + w0) * alpha;
                v1 = (v1 + u0 + w1) * alpha;
                v2 = (v2 + u8 + w0) * alpha;
                v3 = (v3 + u8 + w1) * alpha;
            } else {
                const float r0 = rv[row], r8 = rv[row + 8];
                const float w0 = cv[col], w1 = cv[col + 1];
                const float b0 = bias[col], b1 = bias[col + 1];
                v0 = v0 + r0 * w0 + b0;
                v1 = v1 + r0 * w1 + b1;
                v2 = v2 + r8 * w0 + b0;
                v3 = v3 + r8 * w1 + b1;
            }
            if (OUT_HALF) {
                *reinterpret_cast<__half2*>(Ch + (size_t)row * Ndim + col) =
                    __floats2half2_rn(v0, v1);
                *reinterpret_cast<__half2*>(Ch + (size_t)(row + 8) * Ndim + col) =
                    __floats2half2_rn(v2, v3);
            } else {
                Cf[(size_t)row * Ndim + col] = v0;
                Cf[(size_t)row * Ndim + col + 1] = v1;
                Cf[(size_t)(row + 8) * Ndim + col] = v2;
                Cf[(size_t)(row + 8) * Ndim + col + 1] = v3;
            }
        }
    }
}

// float -> half copy, 4 tensors per launch (grid.y selects; per-y element count).
__global__ void copy_f2h4(const float4* __restrict__ i0, __half* __restrict__ o0,
                          const float4* __restrict__ i1, __half* __restrict__ o1,
                          const float4* __restrict__ i2, __half* __restrict__ o2,
                          const float4* __restrict__ i3, __half* __restrict__ o3,
                          int n4_abc, int n4_d)
{
    const int i = blockIdx.x * 256 + threadIdx.x;
    const int y = blockIdx.y;
    const int n4 = (y < 3) ? n4_abc : n4_d;
    if (i >= n4) return;
    const float4* in = (y == 0) ? i0 : (y == 1) ? i1 : (y == 2) ? i2 : i3;
    __half* out = (y == 0) ? o0 : (y == 1) ? o1 : (y == 2) ? o2 : o3;
    const float4 v = in[i];
    const __half2 h01 = __floats2half2_rn(v.x, v.y);
    const __half2 h23 = __floats2half2_rn(v.z, v.w);
    uint2 pk;
    pk.x = *reinterpret_cast<const uint32_t*>(&h01);
    pk.y = *reinterpret_cast<const uint32_t*>(&h23);
    *reinterpret_cast<uint2*>(out + (size_t)i * 4) = pk;
}

// Fused 32x32 tiled transposes (float in -> half out), grid.z selects tensor.
__global__ void transpose32h3(const float* __restrict__ in0, __half* __restrict__ out0,
                              const float* __restrict__ in1, __half* __restrict__ out1,
                              const float* __restrict__ in2, __half* __restrict__ out2,
                              int R, int Cc)
{
    __shared__ float sm[32][33];
    const float* in = (blockIdx.z == 0) ? in0 : (blockIdx.z == 1) ? in1 : in2;
    __half* outT = (blockIdx.z == 0) ? out0 : (blockIdx.z == 1) ? out1 : out2;
    const int r0 = blockIdx.x * 32;
    const int c0 = blockIdx.y * 32;
    const int tx = threadIdx.x, ty = threadIdx.y;
#pragma unroll
    for (int q = 0; q < 4; ++q)
        sm[ty + q * 8][tx] = in[(size_t)(r0 + ty + q * 8) * Cc + c0 + tx];
    __syncthreads();
#pragma unroll
    for (int q = 0; q < 4; ++q)
        outT[(size_t)(c0 + ty + q * 8) * R + r0 + tx] = __float2half_rn(sm[tx][ty + q * 8]);
}

// Sum NSPLIT partial matrices (deterministic), emit half.
__global__ void reduce_splits_h(const float4* __restrict__ part, __half* __restrict__ out,
                                int n4)
{
    const int i = blockIdx.x * blockDim.x + threadIdx.x;
    if (i >= n4) return;
    float4 s = part[i];
#pragma unroll
    for (int p = 1; p < NSPLIT; ++p) {
        const float4 v = part[(size_t)p * n4 + i];
        s.x += v.x; s.y += v.y; s.z += v.z; s.w += v.w;
    }
    const __half2 h01 = __floats2half2_rn(s.x, s.y);
    const __half2 h23 = __floats2half2_rn(s.z, s.w);
    uint2 pk;
    pk.x = *reinterpret_cast<const uint32_t*>(&h01);
    pk.y = *reinterpret_cast<const uint32_t*>(&h23);
    *reinterpret_cast<uint2*>(out + (size_t)i * 4) = pk;
}

// Fused batch-axis softmax + per-(b,t) row sums. fp16 logits in-place -> att.
__global__ __launch_bounds__(512)
void softmax_rows(__half* __restrict__ d, float* __restrict__ rs)
{
    __shared__ float red[16][8];
    const int t = blockIdx.x;
    const int j = threadIdx.x;
    const size_t planeH = (size_t)T_SZ * T_SZ;
    // thread j handles 4 s-values (uint2 = 4 halves) per batch
    uint2* p = reinterpret_cast<uint2*>(d);
    const size_t base = ((size_t)t * T_SZ) / 4 + j;

    float4 v[B_SZ];
    float4 m = make_float4(-1e30f, -1e30f, -1e30f, -1e30f);
#pragma unroll
    for (int b = 0; b < B_SZ; ++b) {
        const uint2 pk = p[(size_t)b * (planeH / 4) + base];
        const __half2 h01 = *reinterpret_cast<const __half2*>(&pk.x);
        const __half2 h23 = *reinterpret_cast<const __half2*>(&pk.y);
        v[b].x = __half2float(__low2half(h01));
        v[b].y = __half2float(__high2half(h01));
        v[b].z = __half2float(__low2half(h23));
        v[b].w = __half2float(__high2half(h23));
        m.x = fmaxf(m.x, v[b].x); m.y = fmaxf(m.y, v[b].y);
        m.z = fmaxf(m.z, v[b].z); m.w = fmaxf(m.w, v[b].w);
    }
    float4 s = make_float4(0.f, 0.f, 0.f, 0.f);
#pragma unroll
    for (int b = 0; b < B_SZ; ++b) {
        v[b].x = __expf(v[b].x - m.x); s.x += v[b].x;
        v[b].y = __expf(v[b].y - m.y); s.y += v[b].y;
        v[b].z = __expf(v[b].z - m.z); s.z += v[b].z;
        v[b].w = __expf(v[b].w - m.w); s.w += v[b].w;
    }
    s.x = 1.f / s.x; s.y = 1.f / s.y; s.z = 1.f / s.z; s.w = 1.f / s.w;

    float bsum[B_SZ];
#pragma unroll
    for (int b = 0; b < B_SZ; ++b) {
        v[b].x *= s.x; v[b].y *= s.y; v[b].z *= s.z; v[b].w *= s.w;
        const __half2 h01 = __floats2half2_rn(v[b].x, v[b].y);
        const __half2 h23 = __floats2half2_rn(v[b].z, v[b].w);
        // row sums use the half-rounded att (what the attend GEMM will sum)
        const float hx = __half2float(__low2half(h01)), hy = __half2float(__high2half(h01));
        const float hz = __half2float(__low2half(h23)), hw = __half2float(__high2half(h23));
        uint2 pk;
        pk.x = *reinterpret_cast<const uint32_t*>(&h01);
        pk.y = *reinterpret_cast<const uint32_t*>(&h23);
        p[(size_t)b * (planeH / 4) + base] = pk;
        bsum[b] = (hx + hy) + (hz + hw);
    }
#pragma unroll
    for (int b = 0; b < B_SZ; ++b) {
#pragma unroll
        for (int o = 16; o; o >>= 1) bsum[b] += __shfl_xor_sync(0xffffffffu, bsum[b], o);
    }
    const int wid = j >> 5;
    if ((j & 31) == 0) {
#pragma unroll
        for (int b = 0; b < B_SZ; ++b) red[wid][b] = bsum[b];
    }
    __syncthreads();
    if (j < B_SZ) {
        float acc = 0.f;
#pragma unroll
        for (int w2 = 0; w2 < 16; ++w2) acc += red[w2][j];
        rs[(size_t)j * T_SZ + t] = acc;
    }
}

// colvec stage 1 (both weights, grid z in {0,1}).
__global__ void colvec_part(const float* __restrict__ W1, const float* __restrict__ b1,
                            const float* __restrict__ W2, const float* __restrict__ b2,
                            float* __restrict__ part)
{
    const float* W = blockIdx.z ? W2 : W1;
    const float* b = blockIdx.z ? b2 : b1;
    const int e = blockIdx.x * 128 + threadIdx.x;
    const int ch = blockIdx.y;
    const int h0 = ch * (HE_SZ / NCH);
    float s0 = 0.f, s1 = 0.f;
#pragma unroll
    for (int h = h0; h < h0 + HE_SZ / NCH; h += 2) {
        s0 += W[(size_t)h * E_SZ + e] * b[h];
        s1 += W[(size_t)(h + 1) * E_SZ + e] * b[h + 1];
    }
    part[((size_t)blockIdx.z * NCH + ch) * E_SZ + e] = s0 + s1;
}
__global__ void colvec_red(const float* __restrict__ part,
                           float* __restrict__ out1, float* __restrict__ out2)
{
    const int e = blockIdx.x * 128 + threadIdx.x;
    const size_t zb = (size_t)blockIdx.y * NCH * E_SZ;
    float s = 0.f;
#pragma unroll
    for (int ch = 0; ch < NCH; ++ch) s += part[zb + (size_t)ch * E_SZ + e];
    (blockIdx.y ? out2 : out1)[e] = s;
}

// wv[e] = Wo[e,:] . bv
__global__ void rowvec(const float* __restrict__ Wo, const float* __restrict__ bv,
                       float* __restrict__ out)
{
    __shared__ float red[256];
    const int e = blockIdx.x;
    const int t = threadIdx.x;
    const float4* r = reinterpret_cast<const float4*>(Wo + (size_t)e * HE_SZ);
    const float4* b4 = reinterpret_cast<const float4*>(bv);
    float s = 0.f;
#pragma unroll
    for (int i = 0; i < 4; ++i) {
        const float4 a = r[t + i * 256];
        const float4 b = b4[t + i * 256];
        s += a.x * b.x + a.y * b.y + a.z * b.z + a.w * b.w;
    }
    red[t] = s;
    __syncthreads();
    for (int o = 128; o; o >>= 1) {
        if (t < o) red[t] += red[t + o];
        __syncthreads();
    }
    if (t == 0) out[e] = red[0];
}

__global__ void dotscalar(const float* __restrict__ a, const float* __restrict__ b,
                          float* __restrict__ out)
{
    __shared__ float red[256];
    float s = 0.f;
    for (int i = threadIdx.x; i < HE_SZ; i += 256) s += a[i] * b[i];
    red[threadIdx.x] = s;
    __syncthreads();
    for (int o = 128; o; o >>= 1) {
        if (threadIdx.x < o) red[threadIdx.x] += red[threadIdx.x + o];
        __syncthreads();
    }
    if (threadIdx.x == 0) out[0] = red[0];
}

// Fused u/w: y=0: u[r] = query[r,:].a1 ; y=1: w[r] = key[r,:].a2 + c
__global__ void dotvec2(const float* __restrict__ query, const float* __restrict__ key,
                        const float* __restrict__ a1, const float* __restrict__ a2,
                        const float* __restrict__ cptr,
                        float* __restrict__ u, float* __restrict__ w)
{
    const int wid = threadIdx.x >> 5;
    const int lane = threadIdx.x & 31;
    const int r = blockIdx.x * 8 + wid;
    const bool isw = blockIdx.y != 0;
    const float* in = isw ? key : query;
    const float* vec = isw ? a2 : a1;
    const float4* p = reinterpret_cast<const float4*>(in + (size_t)r * E_SZ);
    const float4* v4 = reinterpret_cast<const float4*>(vec);
    float s = 0.f;
#pragma unroll
    for (int i = 0; i < 4; ++i) {
        const float4 a = p[lane + i * 32];
        const float4 b = v4[lane + i * 32];
        s += a.x * b.x + a.y * b.y + a.z * b.z + a.w * b.w;
    }
#pragma unroll
    for (int o = 16; o; o >>= 1) s += __shfl_xor_sync(0xffffffffu, s, o);
    if (lane == 0) {
        if (isw) w[r] = s + cptr[0];
        else u[r] = s;
    }
}

extern "C" void kernel_launch(void* const* d_in, const int* in_sizes, int n_in,
                              void* d_out, int out_size)
{
    (void)in_sizes; (void)n_in; (void)out_size;
    const float* key   = (const float*)d_in[0];
    const float* value = (const float*)d_in[1];
    const float* query = (const float*)d_in[2];
    const float* Wk = (const float*)d_in[3];
    const float* bk = (const float*)d_in[4];
    const float* Wv = (const float*)d_in[5];
    const float* bv = (const float*)d_in[6];
    const float* Wq = (const float*)d_in[7];
    const float* bq = (const float*)d_in[8];
    const float* Wo = (const float*)d_in[9];
    const float* bo = (const float*)d_in[10];
    float* out = (float*)d_out;

    float *part, *cpart, *a1, *a2, *wv, *cs, *u, *w, *rs;
    __half *atth, *qh, *kh, *vh, *Woh, *WqT, *WkT, *WvT, *MTh, *Ph, *qMh, *vpTh;
    cudaGetSymbolAddress((void**)&atth, g_atth);
    cudaGetSymbolAddress((void**)&qh, g_qh);
    cudaGetSymbolAddress((void**)&kh, g_kh);
    cudaGetSymbolAddress((void**)&vh, g_vh);
    cudaGetSymbolAddress((void**)&Woh, g_Woh);
    cudaGetSymbolAddress((void**)&WqT, g_WqT);
    cudaGetSymbolAddress((void**)&WkT, g_WkT);
    cudaGetSymbolAddress((void**)&WvT, g_WvT);
    cudaGetSymbolAddress((void**)&MTh, g_MTh);
    cudaGetSymbolAddress((void**)&Ph, g_Ph);
    cudaGetSymbolAddress((void**)&qMh, g_qMh);
    cudaGetSymbolAddress((void**)&vpTh, g_vpTh);
    cudaGetSymbolAddress((void**)&part, g_part);
    cudaGetSymbolAddress((void**)&cpart, g_cpart);
    cudaGetSymbolAddress((void**)&a1, g_a1);
    cudaGetSymbolAddress((void**)&a2, g_a2);
    cudaGetSymbolAddress((void**)&wv, g_wv);
    cudaGetSymbolAddress((void**)&cs, g_c);
    cudaGetSymbolAddress((void**)&u, g_u);
    cudaGetSymbolAddress((void**)&w, g_w);
    cudaGetSymbolAddress((void**)&rs, g_rs);

    cudaFuncSetAttribute((const void*)gemm_h<0, false>,
                         cudaFuncAttributeMaxDynamicSharedMemorySize, GSMEM_BYTES);
    cudaFuncSetAttribute((const void*)gemm_h<0, true>,
                         cudaFuncAttributeMaxDynamicSharedMemorySize, GSMEM_BYTES);
    cudaFuncSetAttribute((const void*)gemm_h<1, true>,
                         cudaFuncAttributeMaxDynamicSharedMemorySize, GSMEM_BYTES);
    cudaFuncSetAttribute((const void*)gemm_h<2, false>,
                         cudaFuncAttributeMaxDynamicSharedMemorySize, GSMEM_BYTES);

    const int MT_ROWS = B_SZ * T_SZ;  // 16384
    const dim3 blk(256);
    const long long sTE = (long long)T_SZ * E_SZ;
    const long long sTT = (long long)T_SZ * T_SZ;
    const long long sET = (long long)E_SZ * T_SZ;
    const long long sEE = (long long)E_SZ * E_SZ;
    const int KC = HE_SZ / NSPLIT;  // 512

    // --- pre-pass (fused launches) ---
    {
        const int nin4 = MT_ROWS * E_SZ / 4;      // 2M float4 (q/k/v)
        const int nw4 = E_SZ * HE_SZ / 4;         // 512K float4 (Wo)
        copy_f2h4<<<dim3((nin4 + 255) / 256, 4), 256>>>(
            (const float4*)query, qh, (const float4*)key, kh,
            (const float4*)value, vh, (const float4*)Wo, Woh, nin4, nw4);
        transpose32h3<<<dim3(HE_SZ / 32, E_SZ / 32, 3), dim3(32, 8)>>>(
            Wq, WqT, Wk, WkT, Wv, WvT, HE_SZ, E_SZ);
        colvec_part<<<dim3(E_SZ / 128, NCH, 2), 128>>>(Wq, bk, Wk, bq, cpart);
        colvec_red<<<dim3(E_SZ / 128, 2), 128>>>(cpart, a1, a2);
        rowvec<<<E_SZ, 256>>>(Wo, bv, wv);
        dotscalar<<<1, 256>>>(bq, bk, cs);
        dotvec2<<<dim3(MT_ROWS / 8, 2), 256>>>(query, key, a1, a2, cs, u, w);
    }

    // M^T = WkT @ WqT^T  (split-K over HE) -> part -> half MTh
    gemm_h<0, false><<<dim3(E_SZ / 256, E_SZ / 128, NSPLIT), blk, GSMEM_BYTES>>>(
        WkT, WqT, nullptr, nullptr, nullptr, part, E_SZ, KC, HE_SZ, HE_SZ, 1.f,
        KC, KC, sEE, 0, 0);
    reduce_splits_h<<<(E_SZ * E_SZ / 4 + 255) / 256, 256>>>((float4*)part, MTh,
                                                            E_SZ * E_SZ / 4);
    // P = Woh @ WvT^T -> part -> half Ph
    gemm_h<0, false><<<dim3(E_SZ / 256, E_SZ / 128, NSPLIT), blk, GSMEM_BYTES>>>(
        Woh, WvT, nullptr, nullptr, nullptr, part, E_SZ, KC, HE_SZ, HE_SZ, 1.f,
        KC, KC, sEE, 0, 0);
    reduce_splits_h<<<(E_SZ * E_SZ / 4 + 255) / 256, 256>>>((float4*)part, Ph,
                                                            E_SZ * E_SZ / 4);

    // qM = qh @ MTh^T   [16384,512] (half out)
    gemm_h<0, true><<<dim3(E_SZ / 256, MT_ROWS / 128, 1), blk, GSMEM_BYTES>>>(
        qh, MTh, nullptr, nullptr, nullptr, qMh, E_SZ, E_SZ, E_SZ, E_SZ, 1.f,
        0, 0, 0, 0, 0);
    // vpT = Ph @ vh^T per batch  [512,2048] (half out)
    gemm_h<0, true><<<dim3(T_SZ / 256, E_SZ / 128, B_SZ), blk, GSMEM_BYTES>>>(
        Ph, vh, nullptr, nullptr, nullptr, vpTh, T_SZ, E_SZ, E_SZ, E_SZ, 1.f,
        0, sTE, sET, 0, 0);
    // logits: atth = h( SCALE*(qMh @ kh^T + u + w) ) per batch (HALF out)
    gemm_h<1, true><<<dim3(T_SZ / 256, T_SZ / 128, B_SZ), blk, GSMEM_BYTES>>>(
        qMh, kh, u, w, nullptr, atth, T_SZ, E_SZ, E_SZ, E_SZ, SCALE_F,
        sTE, sTE, sTT, T_SZ, T_SZ);
    // batch-axis softmax in place on atth + row sums
    softmax_rows<<<T_SZ, 512>>>(atth, rs);
    // out = atth @ vpTh^T + rs (x) wv + bo per batch (float out)
    gemm_h<2, false><<<dim3(E_SZ / 256, T_SZ / 128, B_SZ), blk, GSMEM_BYTES>>>(
        atth, vpTh, rs, wv, bo, out, E_SZ, T_SZ, T_SZ, T_SZ, 1.f,
        sTT, sET, sTE, T_SZ, 0);
}

// round 13
// speedup vs baseline: 15.1424x; 1.0001x over previous
#include <cuda_runtime.h>
#include <cuda_fp16.h>
#include <cstdint>
#include <cstddef>

// ---------------------------------------------------------------------------
// MultiheadedAttention2 (batch-axis softmax) — v12: fp16 mma.sync GEMMs,
// fp16 logits buffer with in-place batch softmax.
//   att = softmax_b( SCALE*(qM@key^T + u + w) ),  qM = query@M, M = Wq^T Wk
//   out = att@vpT^T + rowsum(att) (x) wv + bo,    vpT = P@value^T, P = Wo Wv
// fp16 operands / fp32 accum; bias terms u/w/c/wv/bo exact fp32.
// ---------------------------------------------------------------------------

#define B_SZ 8
#define T_SZ 2048
#define E_SZ 512
#define HE_SZ 4096
#define SCALE_F 0.04419417382415922f  // 512^-0.5

#define STAGES 4
#define ROWH 72                         // padded row: 72 halves = 144 B
#define A_HALFS (128 * ROWH)            // 9216
#define B_HALFS (256 * ROWH)            // 18432
#define STAGE_HALFS (A_HALFS + B_HALFS) // 27648
#define GSMEM_BYTES (STAGES * STAGE_HALFS * 2)  // 221184
#define NSPLIT 8
#define NCH 64

// Scratch (device globals; allocation-free rule)
__device__ __half g_atth[(size_t)B_SZ * T_SZ * T_SZ];   // logits -> att (fp16)
__device__ __half g_qh[(size_t)B_SZ * T_SZ * E_SZ];
__device__ __half g_kh[(size_t)B_SZ * T_SZ * E_SZ];
__device__ __half g_vh[(size_t)B_SZ * T_SZ * E_SZ];
__device__ __half g_Woh[(size_t)E_SZ * HE_SZ];
__device__ __half g_WqT[(size_t)E_SZ * HE_SZ];
__device__ __half g_WkT[(size_t)E_SZ * HE_SZ];
__device__ __half g_WvT[(size_t)E_SZ * HE_SZ];
__device__ __half g_MTh[(size_t)E_SZ * E_SZ];
__device__ __half g_Ph[(size_t)E_SZ * E_SZ];
__device__ __half g_qMh[(size_t)B_SZ * T_SZ * E_SZ];
__device__ __half g_vpTh[(size_t)B_SZ * E_SZ * T_SZ];
__device__ float  g_part[(size_t)NSPLIT * E_SZ * E_SZ];
__device__ float  g_cpart[(size_t)2 * NCH * E_SZ];
__device__ float  g_a1[E_SZ];
__device__ float  g_a2[E_SZ];
__device__ float  g_wv[E_SZ];
__device__ float  g_c[1];
__device__ float  g_u[(size_t)B_SZ * T_SZ];
__device__ float  g_w[(size_t)B_SZ * T_SZ];
__device__ float  g_rs[(size_t)B_SZ * T_SZ];

static __device__ __forceinline__ void mma_f16(float* c, const uint32_t* a, const uint32_t* b) {
    asm volatile(
        "mma.sync.aligned.m16n8k16.row.col.f32.f16.f16.f32 "
        "{%0,%1,%2,%3}, {%4,%5,%6,%7}, {%8,%9}, {%0,%1,%2,%3};\n"
        : "+f"(c[0]), "+f"(c[1]), "+f"(c[2]), "+f"(c[3])
        : "r"(a[0]), "r"(a[1]), "r"(a[2]), "r"(a[3]), "r"(b[0]), "r"(b[1]));
}

static __device__ __forceinline__ void cp_async16(const __half* smem_dst, const __half* g) {
    uint32_t s = (uint32_t)__cvta_generic_to_shared(smem_dst);
    asm volatile("cp.async.cg.shared.global [%0], [%1], 16;\n" :: "r"(s), "l"(g));
}
static __device__ __forceinline__ void cp_commit() {
    asm volatile("cp.async.commit_group;\n");
}
template <int N>
static __device__ __forceinline__ void cp_wait() {
    asm volatile("cp.async.wait_group %0;\n" :: "n"(N));
}

// ---------------------------------------------------------------------------
// fp16 GEMM: C[M,N] = f(A @ B^T).  A [M,K] halves (row stride ldA), B [N,K]
// halves (row stride ldB). CTA tile 128x256, warp tile 64x64, TILE_K=64.
// EPI=0: v = alpha*acc
// EPI=1: v = alpha*(acc + rowv[row] + colv[col])
// EPI=2: v = acc + rowv[row]*colv[col] + bias[col]
// OUT_HALF: C is __half (round-to-nearest), else float.
// ---------------------------------------------------------------------------
template <int EPI, bool OUT_HALF>
__global__ __launch_bounds__(256, 1)
void gemm_h(const __half* __restrict__ A, const __half* __restrict__ Bm,
            const float* __restrict__ rowv, const float* __restrict__ colv,
            const float* __restrict__ bias, void* __restrict__ Cv,
            int Ndim, int K, long long ldA, long long ldB, float alpha,
            long long sA, long long sB, long long sC,
            long long sRow, long long sCol)
{
    extern __shared__ __half smem[];

    const __half* Ab = A + (long long)blockIdx.z * sA;
    const __half* Bb = Bm + (long long)blockIdx.z * sB;

    const int bm = blockIdx.y * 128;
    const int bn = blockIdx.x * 256;
    const int tid = threadIdx.x;
    const int lane = tid & 31;
    const int warp = tid >> 5;          // 0..7
    const int wm = (warp & 1) * 64;     // 2 warps down M
    const int wn = (warp >> 1) * 64;    // 4 warps across N
    const int gr = lane >> 2;           // 0..7
    const int gc = lane & 3;            // 0..3

    float acc[4][8][4];
#pragma unroll
    for (int i = 0; i < 4; ++i)
#pragma unroll
        for (int j = 0; j < 8; ++j)
#pragma unroll
            for (int r = 0; r < 4; ++r) acc[i][j][r] = 0.f;

    const int nk = K >> 6;

    auto load_tile = [&](int kt) {
        const int stage = kt & (STAGES - 1);
        __half* sAh = smem + stage * STAGE_HALFS;
        __half* sBh = sAh + A_HALFS;
        const int k0g = kt << 6;
#pragma unroll
        for (int i = 0; i < 4; ++i) {
            const int ci = tid + i * 256;
            const int row = ci >> 3;
            const int ch = (ci & 7) * 8;
            cp_async16(sAh + row * ROWH + ch, Ab + (size_t)(bm + row) * ldA + k0g + ch);
        }
#pragma unroll
        for (int i = 0; i < 8; ++i) {
            const int ci = tid + i * 256;
            const int row = ci >> 3;
            const int ch = (ci & 7) * 8;
            cp_async16(sBh + row * ROWH + ch, Bb + (size_t)(bn + row) * ldB + k0g + ch);
        }
    };

#pragma unroll
    for (int s = 0; s < STAGES - 1; ++s) {
        load_tile(s);
        cp_commit();
    }

    for (int kt = 0; kt < nk; ++kt) {
        const int stage = kt & (STAGES - 1);
        cp_wait<STAGES - 2>();
        __syncthreads();

        const int pf = kt + STAGES - 1;
        if (pf < nk) load_tile(pf);
        cp_commit();

        const __half* sAh = smem + stage * STAGE_HALFS;
        const __half* sBh = sAh + A_HALFS;

#pragma unroll
        for (int k0 = 0; k0 < 64; k0 += 16) {
            uint32_t a[4][4];
#pragma unroll
            for (int i = 0; i < 4; ++i) {
                const int r = wm + i * 16 + gr;
                a[i][0] = *reinterpret_cast<const uint32_t*>(sAh + (size_t)r * ROWH + k0 + 2 * gc);
                a[i][1] = *reinterpret_cast<const uint32_t*>(sAh + (size_t)(r + 8) * ROWH + k0 + 2 * gc);
                a[i][2] = *reinterpret_cast<const uint32_t*>(sAh + (size_t)r * ROWH + k0 + 2 * gc + 8);
                a[i][3] = *reinterpret_cast<const uint32_t*>(sAh + (size_t)(r + 8) * ROWH + k0 + 2 * gc + 8);
            }
            uint32_t b[8][2];
#pragma unroll
            for (int j = 0; j < 8; ++j) {
                const int cn = wn + j * 8 + gr;
                b[j][0] = *reinterpret_cast<const uint32_t*>(sBh + (size_t)cn * ROWH + k0 + 2 * gc);
                b[j][1] = *reinterpret_cast<const uint32_t*>(sBh + (size_t)cn * ROWH + k0 + 2 * gc + 8);
            }
#pragma unroll
            for (int i = 0; i < 4; ++i)
#pragma unroll
                for (int j = 0; j < 8; ++j) mma_f16(acc[i][j], a[i], b[j]);
        }
        __syncthreads();
    }

    const float* rv = (EPI != 0) ? rowv + (long long)blockIdx.z * sRow : nullptr;
    const float* cv = (EPI != 0) ? colv + (long long)blockIdx.z * sCol : nullptr;

    float* Cf = (float*)Cv + (long long)blockIdx.z * sC;
    __half* Ch = (__half*)Cv + (long long)blockIdx.z * sC;

#pragma unroll
    for (int i = 0; i < 4; ++i) {
#pragma unroll
        for (int j = 0; j < 8; ++j) {
            const int row = bm + wm + i * 16 + gr;
            const int col = bn + wn + j * 8 + gc * 2;
            float v0 = acc[i][j][0], v1 = acc[i][j][1];
            float v2 = acc[i][j][2], v3 = acc[i][j][3];
            if (EPI == 0) {
                v0 *= alpha; v1 *= alpha; v2 *= alpha; v3 *= alpha;
            } else if (EPI == 1) {
                const float u0 = rv[row], u8 = rv[row + 8];
                const float w0 = cv[col], w1 = cv[col + 1];
                v0 = (v0 + u0 + w0) * alpha;
                v1 = (v1 + u0 + w1) * alpha;
                v2 = (v2 + u8 + w0) * alpha;
                v3 = (v3 + u8 + w1) * alpha;
            } else {
                const float r0 = rv[row], r8 = rv[row + 8];
                const float w0 = cv[col], w1 = cv[col + 1];
                const float b0 = bias[col], b1 = bias[col + 1];
                v0 = v0 + r0 * w0 + b0;
                v1 = v1 + r0 * w1 + b1;
                v2 = v2 + r8 * w0 + b0;
                v3 = v3 + r8 * w1 + b1;
            }
            if (OUT_HALF) {
                *reinterpret_cast<__half2*>(Ch + (size_t)row * Ndim + col) =
                    __floats2half2_rn(v0, v1);
                *reinterpret_cast<__half2*>(Ch + (size_t)(row + 8) * Ndim + col) =
                    __floats2half2_rn(v2, v3);
            } else {
                Cf[(size_t)row * Ndim + col] = v0;
                Cf[(size_t)row * Ndim + col + 1] = v1;
                Cf[(size_t)(row + 8) * Ndim + col] = v2;
                Cf[(size_t)(row + 8) * Ndim + col + 1] = v3;
            }
        }
    }
}

// float -> half copy, 4 tensors per launch (grid.y selects; per-y element count).
__global__ void copy_f2h4(const float4* __restrict__ i0, __half* __restrict__ o0,
                          const float4* __restrict__ i1, __half* __restrict__ o1,
                          const float4* __restrict__ i2, __half* __restrict__ o2,
                          const float4* __restrict__ i3, __half* __restrict__ o3,
                          int n4_abc, int n4_d)
{
    const int i = blockIdx.x * 256 + threadIdx.x;
    const int y = blockIdx.y;
    const int n4 = (y < 3) ? n4_abc : n4_d;
    if (i >= n4) return;
    const float4* in = (y == 0) ? i0 : (y == 1) ? i1 : (y == 2) ? i2 : i3;
    __half* out = (y == 0) ? o0 : (y == 1) ? o1 : (y == 2) ? o2 : o3;
    const float4 v = in[i];
    const __half2 h01 = __floats2half2_rn(v.x, v.y);
    const __half2 h23 = __floats2half2_rn(v.z, v.w);
    uint2 pk;
    pk.x = *reinterpret_cast<const uint32_t*>(&h01);
    pk.y = *reinterpret_cast<const uint32_t*>(&h23);
    *reinterpret_cast<uint2*>(out + (size_t)i * 4) = pk;
}

// Fused 32x32 tiled transposes (float in -> half out), grid.z selects tensor.
__global__ void transpose32h3(const float* __restrict__ in0, __half* __restrict__ out0,
                              const float* __restrict__ in1, __half* __restrict__ out1,
                              const float* __restrict__ in2, __half* __restrict__ out2,
                              int R, int Cc)
{
    __shared__ float sm[32][33];
    const float* in = (blockIdx.z == 0) ? in0 : (blockIdx.z == 1) ? in1 : in2;
    __half* outT = (blockIdx.z == 0) ? out0 : (blockIdx.z == 1) ? out1 : out2;
    const int r0 = blockIdx.x * 32;
    const int c0 = blockIdx.y * 32;
    const int tx = threadIdx.x, ty = threadIdx.y;
#pragma unroll
    for (int q = 0; q < 4; ++q)
        sm[ty + q * 8][tx] = in[(size_t)(r0 + ty + q * 8) * Cc + c0 + tx];
    __syncthreads();
#pragma unroll
    for (int q = 0; q < 4; ++q)
        outT[(size_t)(c0 + ty + q * 8) * R + r0 + tx] = __float2half_rn(sm[tx][ty + q * 8]);
}

// Sum NSPLIT partial matrices (deterministic), emit half.
__global__ void reduce_splits_h(const float4* __restrict__ part, __half* __restrict__ out,
                                int n4)
{
    const int i = blockIdx.x * blockDim.x + threadIdx.x;
    if (i >= n4) return;
    float4 s = part[i];
#pragma unroll
    for (int p = 1; p < NSPLIT; ++p) {
        const float4 v = part[(size_t)p * n4 + i];
        s.x += v.x; s.y += v.y; s.z += v.z; s.w += v.w;
    }
    const __half2 h01 = __floats2half2_rn(s.x, s.y);
    const __half2 h23 = __floats2half2_rn(s.z, s.w);
    uint2 pk;
    pk.x = *reinterpret_cast<const uint32_t*>(&h01);
    pk.y = *reinterpret_cast<const uint32_t*>(&h23);
    *reinterpret_cast<uint2*>(out + (size_t)i * 4) = pk;
}

// Fused batch-axis softmax + per-(b,t) row sums. fp16 logits in-place -> att.
__global__ __launch_bounds__(512)
void softmax_rows(__half* __restrict__ d, float* __restrict__ rs)
{
    __shared__ float red[16][8];
    const int t = blockIdx.x;
    const int j = threadIdx.x;
    const size_t planeH = (size_t)T_SZ * T_SZ;
    // thread j handles 4 s-values (uint2 = 4 halves) per batch
    uint2* p = reinterpret_cast<uint2*>(d);
    const size_t base = ((size_t)t * T_SZ) / 4 + j;

    float4 v[B_SZ];
    float4 m = make_float4(-1e30f, -1e30f, -1e30f, -1e30f);
#pragma unroll
    for (int b = 0; b < B_SZ; ++b) {
        const uint2 pk = p[(size_t)b * (planeH / 4) + base];
        const __half2 h01 = *reinterpret_cast<const __half2*>(&pk.x);
        const __half2 h23 = *reinterpret_cast<const __half2*>(&pk.y);
        v[b].x = __half2float(__low2half(h01));
        v[b].y = __half2float(__high2half(h01));
        v[b].z = __half2float(__low2half(h23));
        v[b].w = __half2float(__high2half(h23));
        m.x = fmaxf(m.x, v[b].x); m.y = fmaxf(m.y, v[b].y);
        m.z = fmaxf(m.z, v[b].z); m.w = fmaxf(m.w, v[b].w);
    }
    float4 s = make_float4(0.f, 0.f, 0.f, 0.f);
#pragma unroll
    for (int b = 0; b < B_SZ; ++b) {
        v[b].x = __expf(v[b].x - m.x); s.x += v[b].x;
        v[b].y = __expf(v[b].y - m.y); s.y += v[b].y;
        v[b].z = __expf(v[b].z - m.z); s.z += v[b].z;
        v[b].w = __expf(v[b].w - m.w); s.w += v[b].w;
    }
    s.x = 1.f / s.x; s.y = 1.f / s.y; s.z = 1.f / s.z; s.w = 1.f / s.w;

    float bsum[B_SZ];
#pragma unroll
    for (int b = 0; b < B_SZ; ++b) {
        v[b].x *= s.x; v[b].y *= s.y; v[b].z *= s.z; v[b].w *= s.w;
        const __half2 h01 = __floats2half2_rn(v[b].x, v[b].y);
        const __half2 h23 = __floats2half2_rn(v[b].z, v[b].w);
        // row sums use the half-rounded att (what the attend GEMM will sum)
        const float hx = __half2float(__low2half(h01)), hy = __half2float(__high2half(h01));
        const float hz = __half2float(__low2half(h23)), hw = __half2float(__high2half(h23));
        uint2 pk;
        pk.x = *reinterpret_cast<const uint32_t*>(&h01);
        pk.y = *reinterpret_cast<const uint32_t*>(&h23);
        p[(size_t)b * (planeH / 4) + base] = pk;
        bsum[b] = (hx + hy) + (hz + hw);
    }
#pragma unroll
    for (int b = 0; b < B_SZ; ++b) {
#pragma unroll
        for (int o = 16; o; o >>= 1) bsum[b] += __shfl_xor_sync(0xffffffffu, bsum[b], o);
    }
    const int wid = j >> 5;
    if ((j & 31) == 0) {
#pragma unroll
        for (int b = 0; b < B_SZ; ++b) red[wid][b] = bsum[b];
    }
    __syncthreads();
    if (j < B_SZ) {
        float acc = 0.f;
#pragma unroll
        for (int w2 = 0; w2 < 16; ++w2) acc += red[w2][j];
        rs[(size_t)j * T_SZ + t] = acc;
    }
}

// colvec stage 1 (both weights, grid z in {0,1}).
__global__ void colvec_part(const float* __restrict__ W1, const float* __restrict__ b1,
                            const float* __restrict__ W2, const float* __restrict__ b2,
                            float* __restrict__ part)
{
    const float* W = blockIdx.z ? W2 : W1;
    const float* b = blockIdx.z ? b2 : b1;
    const int e = blockIdx.x * 128 + threadIdx.x;
    const int ch = blockIdx.y;
    const int h0 = ch * (HE_SZ / NCH);
    float s0 = 0.f, s1 = 0.f;
#pragma unroll
    for (int h = h0; h < h0 + HE_SZ / NCH; h += 2) {
        s0 += W[(size_t)h * E_SZ + e] * b[h];
        s1 += W[(size_t)(h + 1) * E_SZ + e] * b[h + 1];
    }
    part[((size_t)blockIdx.z * NCH + ch) * E_SZ + e] = s0 + s1;
}
__global__ void colvec_red(const float* __restrict__ part,
                           float* __restrict__ out1, float* __restrict__ out2)
{
    const int e = blockIdx.x * 128 + threadIdx.x;
    const size_t zb = (size_t)blockIdx.y * NCH * E_SZ;
    float s = 0.f;
#pragma unroll
    for (int ch = 0; ch < NCH; ++ch) s += part[zb + (size_t)ch * E_SZ + e];
    (blockIdx.y ? out2 : out1)[e] = s;
}

// wv[e] = Wo[e,:] . bv
__global__ void rowvec(const float* __restrict__ Wo, const float* __restrict__ bv,
                       float* __restrict__ out)
{
    __shared__ float red[256];
    const int e = blockIdx.x;
    const int t = threadIdx.x;
    const float4* r = reinterpret_cast<const float4*>(Wo + (size_t)e * HE_SZ);
    const float4* b4 = reinterpret_cast<const float4*>(bv);
    float s = 0.f;
#pragma unroll
    for (int i = 0; i < 4; ++i) {
        const float4 a = r[t + i * 256];
        const float4 b = b4[t + i * 256];
        s += a.x * b.x + a.y * b.y + a.z * b.z + a.w * b.w;
    }
    red[t] = s;
    __syncthreads();
    for (int o = 128; o; o >>= 1) {
        if (t < o) red[t] += red[t + o];
        __syncthreads();
    }
    if (t == 0) out[e] = red[0];
}

__global__ void dotscalar(const float* __restrict__ a, const float* __restrict__ b,
                          float* __restrict__ out)
{
    __shared__ float red[256];
    float s = 0.f;
    for (int i = threadIdx.x; i < HE_SZ; i += 256) s += a[i] * b[i];
    red[threadIdx.x] = s;
    __syncthreads();
    for (int o = 128; o; o >>= 1) {
        if (threadIdx.x < o) red[threadIdx.x] += red[threadIdx.x + o];
        __syncthreads();
    }
    if (threadIdx.x == 0) out[0] = red[0];
}

// Fused u/w: y=0: u[r] = query[r,:].a1 ; y=1: w[r] = key[r,:].a2 + c
__global__ void dotvec2(const float* __restrict__ query, const float* __restrict__ key,
                        const float* __restrict__ a1, const float* __restrict__ a2,
                        const float* __restrict__ cptr,
                        float* __restrict__ u, float* __restrict__ w)
{
    const int wid = threadIdx.x >> 5;
    const int lane = threadIdx.x & 31;
    const int r = blockIdx.x * 8 + wid;
    const bool isw = blockIdx.y != 0;
    const float* in = isw ? key : query;
    const float* vec = isw ? a2 : a1;
    const float4* p = reinterpret_cast<const float4*>(in + (size_t)r * E_SZ);
    const float4* v4 = reinterpret_cast<const float4*>(vec);
    float s = 0.f;
#pragma unroll
    for (int i = 0; i < 4; ++i) {
        const float4 a = p[lane + i * 32];
        const float4 b = v4[lane + i * 32];
        s += a.x * b.x + a.y * b.y + a.z * b.z + a.w * b.w;
    }
#pragma unroll
    for (int o = 16; o; o >>= 1) s += __shfl_xor_sync(0xffffffffu, s, o);
    if (lane == 0) {
        if (isw) w[r] = s + cptr[0];
        else u[r] = s;
    }
}

extern "C" void kernel_launch(void* const* d_in, const int* in_sizes, int n_in,
                              void* d_out, int out_size)
{
    (void)in_sizes; (void)n_in; (void)out_size;
    const float* key   = (const float*)d_in[0];
    const float* value = (const float*)d_in[1];
    const float* query = (const float*)d_in[2];
    const float* Wk = (const float*)d_in[3];
    const float* bk = (const float*)d_in[4];
    const float* Wv = (const float*)d_in[5];
    const float* bv = (const float*)d_in[6];
    const float* Wq = (const float*)d_in[7];
    const float* bq = (const float*)d_in[8];
    const float* Wo = (const float*)d_in[9];
    const float* bo = (const float*)d_in[10];
    float* out = (float*)d_out;

    float *part, *cpart, *a1, *a2, *wv, *cs, *u, *w, *rs;
    __half *atth, *qh, *kh, *vh, *Woh, *WqT, *WkT, *WvT, *MTh, *Ph, *qMh, *vpTh;
    cudaGetSymbolAddress((void**)&atth, g_atth);
    cudaGetSymbolAddress((void**)&qh, g_qh);
    cudaGetSymbolAddress((void**)&kh, g_kh);
    cudaGetSymbolAddress((void**)&vh, g_vh);
    cudaGetSymbolAddress((void**)&Woh, g_Woh);
    cudaGetSymbolAddress((void**)&WqT, g_WqT);
    cudaGetSymbolAddress((void**)&WkT, g_WkT);
    cudaGetSymbolAddress((void**)&WvT, g_WvT);
    cudaGetSymbolAddress((void**)&MTh, g_MTh);
    cudaGetSymbolAddress((void**)&Ph, g_Ph);
    cudaGetSymbolAddress((void**)&qMh, g_qMh);
    cudaGetSymbolAddress((void**)&vpTh, g_vpTh);
    cudaGetSymbolAddress((void**)&part, g_part);
    cudaGetSymbolAddress((void**)&cpart, g_cpart);
    cudaGetSymbolAddress((void**)&a1, g_a1);
    cudaGetSymbolAddress((void**)&a2, g_a2);
    cudaGetSymbolAddress((void**)&wv, g_wv);
    cudaGetSymbolAddress((void**)&cs, g_c);
    cudaGetSymbolAddress((void**)&u, g_u);
    cudaGetSymbolAddress((void**)&w, g_w);
    cudaGetSymbolAddress((void**)&rs, g_rs);

    cudaFuncSetAttribute((const void*)gemm_h<0, false>,
                         cudaFuncAttributeMaxDynamicSharedMemorySize, GSMEM_BYTES);
    cudaFuncSetAttribute((const void*)gemm_h<0, true>,
                         cudaFuncAttributeMaxDynamicSharedMemorySize, GSMEM_BYTES);
    cudaFuncSetAttribute((const void*)gemm_h<1, true>,
                         cudaFuncAttributeMaxDynamicSharedMemorySize, GSMEM_BYTES);
    cudaFuncSetAttribute((const void*)gemm_h<2, false>,
                         cudaFuncAttributeMaxDynamicSharedMemorySize, GSMEM_BYTES);

    const int MT_ROWS = B_SZ * T_SZ;  // 16384
    const dim3 blk(256);
    const long long sTE = (long long)T_SZ * E_SZ;
    const long long sTT = (long long)T_SZ * T_SZ;
    const long long sET = (long long)E_SZ * T_SZ;
    const long long sEE = (long long)E_SZ * E_SZ;
    const int KC = HE_SZ / NSPLIT;  // 512

    // --- pre-pass (fused launches) ---
    {
        const int nin4 = MT_ROWS * E_SZ / 4;      // 2M float4 (q/k/v)
        const int nw4 = E_SZ * HE_SZ / 4;         // 512K float4 (Wo)
        copy_f2h4<<<dim3((nin4 + 255) / 256, 4), 256>>>(
            (const float4*)query, qh, (const float4*)key, kh,
            (const float4*)value, vh, (const float4*)Wo, Woh, nin4, nw4);
        transpose32h3<<<dim3(HE_SZ / 32, E_SZ / 32, 3), dim3(32, 8)>>>(
            Wq, WqT, Wk, WkT, Wv, WvT, HE_SZ, E_SZ);
        colvec_part<<<dim3(E_SZ / 128, NCH, 2), 128>>>(Wq, bk, Wk, bq, cpart);
        colvec_red<<<dim3(E_SZ / 128, 2), 128>>>(cpart, a1, a2);
        rowvec<<<E_SZ, 256>>>(Wo, bv, wv);
        dotscalar<<<1, 256>>>(bq, bk, cs);
        dotvec2<<<dim3(MT_ROWS / 8, 2), 256>>>(query, key, a1, a2, cs, u, w);
    }

    // M^T = WkT @ WqT^T  (split-K over HE) -> part -> half MTh
    gemm_h<0, false><<<dim3(E_SZ / 256, E_SZ / 128, NSPLIT), blk, GSMEM_BYTES>>>(
        WkT, WqT, nullptr, nullptr, nullptr, part, E_SZ, KC, HE_SZ, HE_SZ, 1.f,
        KC, KC, sEE, 0, 0);
    reduce_splits_h<<<(E_SZ * E_SZ / 4 + 255) / 256, 256>>>((float4*)part, MTh,
                                                            E_SZ * E_SZ / 4);
    // P = Woh @ WvT^T -> part -> half Ph
    gemm_h<0, false><<<dim3(E_SZ / 256, E_SZ / 128, NSPLIT), blk, GSMEM_BYTES>>>(
        Woh, WvT, nullptr, nullptr, nullptr, part, E_SZ, KC, HE_SZ, HE_SZ, 1.f,
        KC, KC, sEE, 0, 0);
    reduce_splits_h<<<(E_SZ * E_SZ / 4 + 255) / 256, 256>>>((float4*)part, Ph,
                                                            E_SZ * E_SZ / 4);

    // qM = qh @ MTh^T   [16384,512] (half out)
    gemm_h<0, true><<<dim3(E_SZ / 256, MT_ROWS / 128, 1), blk, GSMEM_BYTES>>>(
        qh, MTh, nullptr, nullptr, nullptr, qMh, E_SZ, E_SZ, E_SZ, E_SZ, 1.f,
        0, 0, 0, 0, 0);
    // vpT = Ph @ vh^T per batch  [512,2048] (half out)
    gemm_h<0, true><<<dim3(T_SZ / 256, E_SZ / 128, B_SZ), blk, GSMEM_BYTES>>>(
        Ph, vh, nullptr, nullptr, nullptr, vpTh, T_SZ, E_SZ, E_SZ, E_SZ, 1.f,
        0, sTE, sET, 0, 0);
    // logits: atth = h( SCALE*(qMh @ kh^T + u + w) ) per batch (HALF out)
    gemm_h<1, true><<<dim3(T_SZ / 256, T_SZ / 128, B_SZ), blk, GSMEM_BYTES>>>(
        qMh, kh, u, w, nullptr, atth, T_SZ, E_SZ, E_SZ, E_SZ, SCALE_F,
        sTE, sTE, sTT, T_SZ, T_SZ);
    // batch-axis softmax in place on atth + row sums
    softmax_rows<<<T_SZ, 512>>>(atth, rs);
    // out = atth @ vpTh^T + rs (x) wv + bo per batch (float out)
    gemm_h<2, false><<<dim3(E_SZ / 256, T_SZ / 128, B_SZ), blk, GSMEM_BYTES>>>(
        atth, vpTh, rs, wv, bo, out, E_SZ, T_SZ, T_SZ, T_SZ, 1.f,
        sTT, sET, sTE, T_SZ, 0);
}

// round 14
// speedup vs baseline: 15.1511x; 1.0006x over previous
#include <cuda_runtime.h>
#include <cuda_fp16.h>
#include <cstdint>
#include <cstddef>

// ---------------------------------------------------------------------------
// MultiheadedAttention2 (batch-axis softmax) — v12: fp16 mma.sync GEMMs,
// fp16 logits buffer with in-place batch softmax.
//   att = softmax_b( SCALE*(qM@key^T + u + w) ),  qM = query@M, M = Wq^T Wk
//   out = att@vpT^T + rowsum(att) (x) wv + bo,    vpT = P@value^T, P = Wo Wv
// fp16 operands / fp32 accum; bias terms u/w/c/wv/bo exact fp32.
// ---------------------------------------------------------------------------

#define B_SZ 8
#define T_SZ 2048
#define E_SZ 512
#define HE_SZ 4096
#define SCALE_F 0.04419417382415922f  // 512^-0.5

#define STAGES 4
#define ROWH 72                         // padded row: 72 halves = 144 B
#define A_HALFS (128 * ROWH)            // 9216
#define B_HALFS (256 * ROWH)            // 18432
#define STAGE_HALFS (A_HALFS + B_HALFS) // 27648
#define GSMEM_BYTES (STAGES * STAGE_HALFS * 2)  // 221184
#define NSPLIT 8
#define NCH 64

// Scratch (device globals; allocation-free rule)
__device__ __half g_atth[(size_t)B_SZ * T_SZ * T_SZ];   // logits -> att (fp16)
__device__ __half g_qh[(size_t)B_SZ * T_SZ * E_SZ];
__device__ __half g_kh[(size_t)B_SZ * T_SZ * E_SZ];
__device__ __half g_vh[(size_t)B_SZ * T_SZ * E_SZ];
__device__ __half g_Woh[(size_t)E_SZ * HE_SZ];
__device__ __half g_WqT[(size_t)E_SZ * HE_SZ];
__device__ __half g_WkT[(size_t)E_SZ * HE_SZ];
__device__ __half g_WvT[(size_t)E_SZ * HE_SZ];
__device__ __half g_MTh[(size_t)E_SZ * E_SZ];
__device__ __half g_Ph[(size_t)E_SZ * E_SZ];
__device__ __half g_qMh[(size_t)B_SZ * T_SZ * E_SZ];
__device__ __half g_vpTh[(size_t)B_SZ * E_SZ * T_SZ];
__device__ float  g_part[(size_t)NSPLIT * E_SZ * E_SZ];
__device__ float  g_cpart[(size_t)2 * NCH * E_SZ];
__device__ float  g_a1[E_SZ];
__device__ float  g_a2[E_SZ];
__device__ float  g_wv[E_SZ];
__device__ float  g_c[1];
__device__ float  g_u[(size_t)B_SZ * T_SZ];
__device__ float  g_w[(size_t)B_SZ * T_SZ];
__device__ float  g_rs[(size_t)B_SZ * T_SZ];

static __device__ __forceinline__ void mma_f16(float* c, const uint32_t* a, const uint32_t* b) {
    asm volatile(
        "mma.sync.aligned.m16n8k16.row.col.f32.f16.f16.f32 "
        "{%0,%1,%2,%3}, {%4,%5,%6,%7}, {%8,%9}, {%0,%1,%2,%3};\n"
        : "+f"(c[0]), "+f"(c[1]), "+f"(c[2]), "+f"(c[3])
        : "r"(a[0]), "r"(a[1]), "r"(a[2]), "r"(a[3]), "r"(b[0]), "r"(b[1]));
}

static __device__ __forceinline__ void cp_async16(const __half* smem_dst, const __half* g) {
    uint32_t s = (uint32_t)__cvta_generic_to_shared(smem_dst);
    asm volatile("cp.async.cg.shared.global [%0], [%1], 16;\n" :: "r"(s), "l"(g));
}
static __device__ __forceinline__ void cp_commit() {
    asm volatile("cp.async.commit_group;\n");
}
template <int N>
static __device__ __forceinline__ void cp_wait() {
    asm volatile("cp.async.wait_group %0;\n" :: "n"(N));
}

// ---------------------------------------------------------------------------
// fp16 GEMM: C[M,N] = f(A @ B^T).  A [M,K] halves (row stride ldA), B [N,K]
// halves (row stride ldB). CTA tile 128x256, warp tile 64x64, TILE_K=64.
// EPI=0: v = alpha*acc
// EPI=1: v = alpha*(acc + rowv[row] + colv[col])
// EPI=2: v = acc + rowv[row]*colv[col] + bias[col]
// OUT_HALF: C is __half (round-to-nearest), else float.
// ---------------------------------------------------------------------------
template <int EPI, bool OUT_HALF>
__global__ __launch_bounds__(256, 1)
void gemm_h(const __half* __restrict__ A, const __half* __restrict__ Bm,
            const float* __restrict__ rowv, const float* __restrict__ colv,
            const float* __restrict__ bias, void* __restrict__ Cv,
            int Ndim, int K, long long ldA, long long ldB, float alpha,
            long long sA, long long sB, long long sC,
            long long sRow, long long sCol)
{
    extern __shared__ __half smem[];

    const __half* Ab = A + (long long)blockIdx.z * sA;
    const __half* Bb = Bm + (long long)blockIdx.z * sB;

    const int bm = blockIdx.y * 128;
    const int bn = blockIdx.x * 256;
    const int tid = threadIdx.x;
    const int lane = tid & 31;
    const int warp = tid >> 5;          // 0..7
    const int wm = (warp & 1) * 64;     // 2 warps down M
    const int wn = (warp >> 1) * 64;    // 4 warps across N
    const int gr = lane >> 2;           // 0..7
    const int gc = lane & 3;            // 0..3

    float acc[4][8][4];
#pragma unroll
    for (int i = 0; i < 4; ++i)
#pragma unroll
        for (int j = 0; j < 8; ++j)
#pragma unroll
            for (int r = 0; r < 4; ++r) acc[i][j][r] = 0.f;

    const int nk = K >> 6;

    auto load_tile = [&](int kt) {
        const int stage = kt & (STAGES - 1);
        __half* sAh = smem + stage * STAGE_HALFS;
        __half* sBh = sAh + A_HALFS;
        const int k0g = kt << 6;
#pragma unroll
        for (int i = 0; i < 4; ++i) {
            const int ci = tid + i * 256;
            const int row = ci >> 3;
            const int ch = (ci & 7) * 8;
            cp_async16(sAh + row * ROWH + ch, Ab + (size_t)(bm + row) * ldA + k0g + ch);
        }
#pragma unroll
        for (int i = 0; i < 8; ++i) {
            const int ci = tid + i * 256;
            const int row = ci >> 3;
            const int ch = (ci & 7) * 8;
            cp_async16(sBh + row * ROWH + ch, Bb + (size_t)(bn + row) * ldB + k0g + ch);
        }
    };

#pragma unroll
    for (int s = 0; s < STAGES - 1; ++s) {
        load_tile(s);
        cp_commit();
    }

    for (int kt = 0; kt < nk; ++kt) {
        const int stage = kt & (STAGES - 1);
        cp_wait<STAGES - 2>();
        __syncthreads();

        const int pf = kt + STAGES - 1;
        if (pf < nk) load_tile(pf);
        cp_commit();

        const __half* sAh = smem + stage * STAGE_HALFS;
        const __half* sBh = sAh + A_HALFS;

#pragma unroll
        for (int k0 = 0; k0 < 64; k0 += 16) {
            uint32_t a[4][4];
#pragma unroll
            for (int i = 0; i < 4; ++i) {
                const int r = wm + i * 16 + gr;
                a[i][0] = *reinterpret_cast<const uint32_t*>(sAh + (size_t)r * ROWH + k0 + 2 * gc);
                a[i][1] = *reinterpret_cast<const uint32_t*>(sAh + (size_t)(r + 8) * ROWH + k0 + 2 * gc);
                a[i][2] = *reinterpret_cast<const uint32_t*>(sAh + (size_t)r * ROWH + k0 + 2 * gc + 8);
                a[i][3] = *reinterpret_cast<const uint32_t*>(sAh + (size_t)(r + 8) * ROWH + k0 + 2 * gc + 8);
            }
            uint32_t b[8][2];
#pragma unroll
            for (int j = 0; j < 8; ++j) {
                const int cn = wn + j * 8 + gr;
                b[j][0] = *reinterpret_cast<const uint32_t*>(sBh + (size_t)cn * ROWH + k0 + 2 * gc);
                b[j][1] = *reinterpret_cast<const uint32_t*>(sBh + (size_t)cn * ROWH + k0 + 2 * gc + 8);
            }
#pragma unroll
            for (int i = 0; i < 4; ++i)
#pragma unroll
                for (int j = 0; j < 8; ++j) mma_f16(acc[i][j], a[i], b[j]);
        }
        __syncthreads();
    }

    const float* rv = (EPI != 0) ? rowv + (long long)blockIdx.z * sRow : nullptr;
    const float* cv = (EPI != 0) ? colv + (long long)blockIdx.z * sCol : nullptr;

    float* Cf = (float*)Cv + (long long)blockIdx.z * sC;
    __half* Ch = (__half*)Cv + (long long)blockIdx.z * sC;

#pragma unroll
    for (int i = 0; i < 4; ++i) {
#pragma unroll
        for (int j = 0; j < 8; ++j) {
            const int row = bm + wm + i * 16 + gr;
            const int col = bn + wn + j * 8 + gc * 2;
            float v0 = acc[i][j][0], v1 = acc[i][j][1];
            float v2 = acc[i][j][2], v3 = acc[i][j][3];
            if (EPI == 0) {
                v0 *= alpha; v1 *= alpha; v2 *= alpha; v3 *= alpha;
            } else if (EPI == 1) {
                const float u0 = rv[row], u8 = rv[row + 8];
                const float w0 = cv[col], w1 = cv[col + 1];
                v0 = (v0 + u0 + w0) * alpha;
                v1 = (v1 + u0 + w1) * alpha;
                v2 = (v2 + u8 + w0) * alpha;
                v3 = (v3 + u8 + w1) * alpha;
            } else {
                const float r0 = rv[row], r8 = rv[row + 8];
                const float w0 = cv[col], w1 = cv[col + 1];
                const float b0 = bias[col], b1 = bias[col + 1];
                v0 = v0 + r0 * w0 + b0;
                v1 = v1 + r0 * w1 + b1;
                v2 = v2 + r8 * w0 + b0;
                v3 = v3 + r8 * w1 + b1;
            }
            if (OUT_HALF) {
                *reinterpret_cast<__half2*>(Ch + (size_t)row * Ndim + col) =
                    __floats2half2_rn(v0, v1);
                *reinterpret_cast<__half2*>(Ch + (size_t)(row + 8) * Ndim + col) =
                    __floats2half2_rn(v2, v3);
            } else {
                Cf[(size_t)row * Ndim + col] = v0;
                Cf[(size_t)row * Ndim + col + 1] = v1;
                Cf[(size_t)(row + 8) * Ndim + col] = v2;
                Cf[(size_t)(row + 8) * Ndim + col + 1] = v3;
            }
        }
    }
}

// float -> half copy, 4 tensors per launch (grid.y selects; per-y element count).
__global__ void copy_f2h4(const float4* __restrict__ i0, __half* __restrict__ o0,
                          const float4* __restrict__ i1, __half* __restrict__ o1,
                          const float4* __restrict__ i2, __half* __restrict__ o2,
                          const float4* __restrict__ i3, __half* __restrict__ o3,
                          int n4_abc, int n4_d)
{
    const int i = blockIdx.x * 256 + threadIdx.x;
    const int y = blockIdx.y;
    const int n4 = (y < 3) ? n4_abc : n4_d;
    if (i >= n4) return;
    const float4* in = (y == 0) ? i0 : (y == 1) ? i1 : (y == 2) ? i2 : i3;
    __half* out = (y == 0) ? o0 : (y == 1) ? o1 : (y == 2) ? o2 : o3;
    const float4 v = in[i];
    const __half2 h01 = __floats2half2_rn(v.x, v.y);
    const __half2 h23 = __floats2half2_rn(v.z, v.w);
    uint2 pk;
    pk.x = *reinterpret_cast<const uint32_t*>(&h01);
    pk.y = *reinterpret_cast<const uint32_t*>(&h23);
    *reinterpret_cast<uint2*>(out + (size_t)i * 4) = pk;
}

// Fused 32x32 tiled transposes (float in -> half out), grid.z selects tensor.
__global__ void transpose32h3(const float* __restrict__ in0, __half* __restrict__ out0,
                              const float* __restrict__ in1, __half* __restrict__ out1,
                              const float* __restrict__ in2, __half* __restrict__ out2,
                              int R, int Cc)
{
    __shared__ float sm[32][33];
    const float* in = (blockIdx.z == 0) ? in0 : (blockIdx.z == 1) ? in1 : in2;
    __half* outT = (blockIdx.z == 0) ? out0 : (blockIdx.z == 1) ? out1 : out2;
    const int r0 = blockIdx.x * 32;
    const int c0 = blockIdx.y * 32;
    const int tx = threadIdx.x, ty = threadIdx.y;
#pragma unroll
    for (int q = 0; q < 4; ++q)
        sm[ty + q * 8][tx] = in[(size_t)(r0 + ty + q * 8) * Cc + c0 + tx];
    __syncthreads();
#pragma unroll
    for (int q = 0; q < 4; ++q)
        outT[(size_t)(c0 + ty + q * 8) * R + r0 + tx] = __float2half_rn(sm[tx][ty + q * 8]);
}

// Sum NSPLIT partial matrices (deterministic), emit half.
__global__ void reduce_splits_h(const float4* __restrict__ part, __half* __restrict__ out,
                                int n4)
{
    const int i = blockIdx.x * blockDim.x + threadIdx.x;
    if (i >= n4) return;
    float4 s = part[i];
#pragma unroll
    for (int p = 1; p < NSPLIT; ++p) {
        const float4 v = part[(size_t)p * n4 + i];
        s.x += v.x; s.y += v.y; s.z += v.z; s.w += v.w;
    }
    const __half2 h01 = __floats2half2_rn(s.x, s.y);
    const __half2 h23 = __floats2half2_rn(s.z, s.w);
    uint2 pk;
    pk.x = *reinterpret_cast<const uint32_t*>(&h01);
    pk.y = *reinterpret_cast<const uint32_t*>(&h23);
    *reinterpret_cast<uint2*>(out + (size_t)i * 4) = pk;
}

// Fused batch-axis softmax + per-(b,t) row sums. fp16 logits in-place -> att.
__global__ __launch_bounds__(512)
void softmax_rows(__half* __restrict__ d, float* __restrict__ rs)
{
    __shared__ float red[16][8];
    const int t = blockIdx.x;
    const int j = threadIdx.x;
    const size_t planeH = (size_t)T_SZ * T_SZ;
    // thread j handles 4 s-values (uint2 = 4 halves) per batch
    uint2* p = reinterpret_cast<uint2*>(d);
    const size_t base = ((size_t)t * T_SZ) / 4 + j;

    float4 v[B_SZ];
    float4 m = make_float4(-1e30f, -1e30f, -1e30f, -1e30f);
#pragma unroll
    for (int b = 0; b < B_SZ; ++b) {
        const uint2 pk = p[(size_t)b * (planeH / 4) + base];
        const __half2 h01 = *reinterpret_cast<const __half2*>(&pk.x);
        const __half2 h23 = *reinterpret_cast<const __half2*>(&pk.y);
        v[b].x = __half2float(__low2half(h01));
        v[b].y = __half2float(__high2half(h01));
        v[b].z = __half2float(__low2half(h23));
        v[b].w = __half2float(__high2half(h23));
        m.x = fmaxf(m.x, v[b].x); m.y = fmaxf(m.y, v[b].y);
        m.z = fmaxf(m.z, v[b].z); m.w = fmaxf(m.w, v[b].w);
    }
    float4 s = make_float4(0.f, 0.f, 0.f, 0.f);
#pragma unroll
    for (int b = 0; b < B_SZ; ++b) {
        v[b].x = __expf(v[b].x - m.x); s.x += v[b].x;
        v[b].y = __expf(v[b].y - m.y); s.y += v[b].y;
        v[b].z = __expf(v[b].z - m.z); s.z += v[b].z;
        v[b].w = __expf(v[b].w - m.w); s.w += v[b].w;
    }
    s.x = 1.f / s.x; s.y = 1.f / s.y; s.z = 1.f / s.z; s.w = 1.f / s.w;

    float bsum[B_SZ];
#pragma unroll
    for (int b = 0; b < B_SZ; ++b) {
        v[b].x *= s.x; v[b].y *= s.y; v[b].z *= s.z; v[b].w *= s.w;
        const __half2 h01 = __floats2half2_rn(v[b].x, v[b].y);
        const __half2 h23 = __floats2half2_rn(v[b].z, v[b].w);
        // row sums use the half-rounded att (what the attend GEMM will sum)
        const float hx = __half2float(__low2half(h01)), hy = __half2float(__high2half(h01));
        const float hz = __half2float(__low2half(h23)), hw = __half2float(__high2half(h23));
        uint2 pk;
        pk.x = *reinterpret_cast<const uint32_t*>(&h01);
        pk.y = *reinterpret_cast<const uint32_t*>(&h23);
        p[(size_t)b * (planeH / 4) + base] = pk;
        bsum[b] = (hx + hy) + (hz + hw);
    }
#pragma unroll
    for (int b = 0; b < B_SZ; ++b) {
#pragma unroll
        for (int o = 16; o; o >>= 1) bsum[b] += __shfl_xor_sync(0xffffffffu, bsum[b], o);
    }
    const int wid = j >> 5;
    if ((j & 31) == 0) {
#pragma unroll
        for (int b = 0; b < B_SZ; ++b) red[wid][b] = bsum[b];
    }
    __syncthreads();
    if (j < B_SZ) {
        float acc = 0.f;
#pragma unroll
        for (int w2 = 0; w2 < 16; ++w2) acc += red[w2][j];
        rs[(size_t)j * T_SZ + t] = acc;
    }
}

// colvec stage 1 (both weights, grid z in {0,1}).
__global__ void colvec_part(const float* __restrict__ W1, const float* __restrict__ b1,
                            const float* __restrict__ W2, const float* __restrict__ b2,
                            float* __restrict__ part)
{
    const float* W = blockIdx.z ? W2 : W1;
    const float* b = blockIdx.z ? b2 : b1;
    const int e = blockIdx.x * 128 + threadIdx.x;
    const int ch = blockIdx.y;
    const int h0 = ch * (HE_SZ / NCH);
    float s0 = 0.f, s1 = 0.f;
#pragma unroll
    for (int h = h0; h < h0 + HE_SZ / NCH; h += 2) {
        s0 += W[(size_t)h * E_SZ + e] * b[h];
        s1 += W[(size_t)(h + 1) * E_SZ + e] * b[h + 1];
    }
    part[((size_t)blockIdx.z * NCH + ch) * E_SZ + e] = s0 + s1;
}
__global__ void colvec_red(const float* __restrict__ part,
                           float* __restrict__ out1, float* __restrict__ out2)
{
    const int e = blockIdx.x * 128 + threadIdx.x;
    const size_t zb = (size_t)blockIdx.y * NCH * E_SZ;
    float s = 0.f;
#pragma unroll
    for (int ch = 0; ch < NCH; ++ch) s += part[zb + (size_t)ch * E_SZ + e];
    (blockIdx.y ? out2 : out1)[e] = s;
}

// wv[e] = Wo[e,:] . bv
__global__ void rowvec(const float* __restrict__ Wo, const float* __restrict__ bv,
                       float* __restrict__ out)
{
    __shared__ float red[256];
    const int e = blockIdx.x;
    const int t = threadIdx.x;
    const float4* r = reinterpret_cast<const float4*>(Wo + (size_t)e * HE_SZ);
    const float4* b4 = reinterpret_cast<const float4*>(bv);
    float s = 0.f;
#pragma unroll
    for (int i = 0; i < 4; ++i) {
        const float4 a = r[t + i * 256];
        const float4 b = b4[t + i * 256];
        s += a.x * b.x + a.y * b.y + a.z * b.z + a.w * b.w;
    }
    red[t] = s;
    __syncthreads();
    for (int o = 128; o; o >>= 1) {
        if (t < o) red[t] += red[t + o];
        __syncthreads();
    }
    if (t == 0) out[e] = red[0];
}

__global__ void dotscalar(const float* __restrict__ a, const float* __restrict__ b,
                          float* __restrict__ out)
{
    __shared__ float red[256];
    float s = 0.f;
    for (int i = threadIdx.x; i < HE_SZ; i += 256) s += a[i] * b[i];
    red[threadIdx.x] = s;
    __syncthreads();
    for (int o = 128; o; o >>= 1) {
        if (threadIdx.x < o) red[threadIdx.x] += red[threadIdx.x + o];
        __syncthreads();
    }
    if (threadIdx.x == 0) out[0] = red[0];
}

// Fused u/w: y=0: u[r] = query[r,:].a1 ; y=1: w[r] = key[r,:].a2 + c
__global__ void dotvec2(const float* __restrict__ query, const float* __restrict__ key,
                        const float* __restrict__ a1, const float* __restrict__ a2,
                        const float* __restrict__ cptr,
                        float* __restrict__ u, float* __restrict__ w)
{
    const int wid = threadIdx.x >> 5;
    const int lane = threadIdx.x & 31;
    const int r = blockIdx.x * 8 + wid;
    const bool isw = blockIdx.y != 0;
    const float* in = isw ? key : query;
    const float* vec = isw ? a2 : a1;
    const float4* p = reinterpret_cast<const float4*>(in + (size_t)r * E_SZ);
    const float4* v4 = reinterpret_cast<const float4*>(vec);
    float s = 0.f;
#pragma unroll
    for (int i = 0; i < 4; ++i) {
        const float4 a = p[lane + i * 32];
        const float4 b = v4[lane + i * 32];
        s += a.x * b.x + a.y * b.y + a.z * b.z + a.w * b.w;
    }
#pragma unroll
    for (int o = 16; o; o >>= 1) s += __shfl_xor_sync(0xffffffffu, s, o);
    if (lane == 0) {
        if (isw) w[r] = s + cptr[0];
        else u[r] = s;
    }
}

extern "C" void kernel_launch(void* const* d_in, const int* in_sizes, int n_in,
                              void* d_out, int out_size)
{
    (void)in_sizes; (void)n_in; (void)out_size;
    const float* key   = (const float*)d_in[0];
    const float* value = (const float*)d_in[1];
    const float* query = (const float*)d_in[2];
    const float* Wk = (const float*)d_in[3];
    const float* bk = (const float*)d_in[4];
    const float* Wv = (const float*)d_in[5];
    const float* bv = (const float*)d_in[6];
    const float* Wq = (const float*)d_in[7];
    const float* bq = (const float*)d_in[8];
    const float* Wo = (const float*)d_in[9];
    const float* bo = (const float*)d_in[10];
    float* out = (float*)d_out;

    float *part, *cpart, *a1, *a2, *wv, *cs, *u, *w, *rs;
    __half *atth, *qh, *kh, *vh, *Woh, *WqT, *WkT, *WvT, *MTh, *Ph, *qMh, *vpTh;
    cudaGetSymbolAddress((void**)&atth, g_atth);
    cudaGetSymbolAddress((void**)&qh, g_qh);
    cudaGetSymbolAddress((void**)&kh, g_kh);
    cudaGetSymbolAddress((void**)&vh, g_vh);
    cudaGetSymbolAddress((void**)&Woh, g_Woh);
    cudaGetSymbolAddress((void**)&WqT, g_WqT);
    cudaGetSymbolAddress((void**)&WkT, g_WkT);
    cudaGetSymbolAddress((void**)&WvT, g_WvT);
    cudaGetSymbolAddress((void**)&MTh, g_MTh);
    cudaGetSymbolAddress((void**)&Ph, g_Ph);
    cudaGetSymbolAddress((void**)&qMh, g_qMh);
    cudaGetSymbolAddress((void**)&vpTh, g_vpTh);
    cudaGetSymbolAddress((void**)&part, g_part);
    cudaGetSymbolAddress((void**)&cpart, g_cpart);
    cudaGetSymbolAddress((void**)&a1, g_a1);
    cudaGetSymbolAddress((void**)&a2, g_a2);
    cudaGetSymbolAddress((void**)&wv, g_wv);
    cudaGetSymbolAddress((void**)&cs, g_c);
    cudaGetSymbolAddress((void**)&u, g_u);
    cudaGetSymbolAddress((void**)&w, g_w);
    cudaGetSymbolAddress((void**)&rs, g_rs);

    cudaFuncSetAttribute((const void*)gemm_h<0, false>,
                         cudaFuncAttributeMaxDynamicSharedMemorySize, GSMEM_BYTES);
    cudaFuncSetAttribute((const void*)gemm_h<0, true>,
                         cudaFuncAttributeMaxDynamicSharedMemorySize, GSMEM_BYTES);
    cudaFuncSetAttribute((const void*)gemm_h<1, true>,
                         cudaFuncAttributeMaxDynamicSharedMemorySize, GSMEM_BYTES);
    cudaFuncSetAttribute((const void*)gemm_h<2, false>,
                         cudaFuncAttributeMaxDynamicSharedMemorySize, GSMEM_BYTES);

    const int MT_ROWS = B_SZ * T_SZ;  // 16384
    const dim3 blk(256);
    const long long sTE = (long long)T_SZ * E_SZ;
    const long long sTT = (long long)T_SZ * T_SZ;
    const long long sET = (long long)E_SZ * T_SZ;
    const long long sEE = (long long)E_SZ * E_SZ;
    const int KC = HE_SZ / NSPLIT;  // 512

    // --- pre-pass (fused launches) ---
    {
        const int nin4 = MT_ROWS * E_SZ / 4;      // 2M float4 (q/k/v)
        const int nw4 = E_SZ * HE_SZ / 4;         // 512K float4 (Wo)
        copy_f2h4<<<dim3((nin4 + 255) / 256, 4), 256>>>(
            (const float4*)query, qh, (const float4*)key, kh,
            (const float4*)value, vh, (const float4*)Wo, Woh, nin4, nw4);
        transpose32h3<<<dim3(HE_SZ / 32, E_SZ / 32, 3), dim3(32, 8)>>>(
            Wq, WqT, Wk, WkT, Wv, WvT, HE_SZ, E_SZ);
        colvec_part<<<dim3(E_SZ / 128, NCH, 2), 128>>>(Wq, bk, Wk, bq, cpart);
        colvec_red<<<dim3(E_SZ / 128, 2), 128>>>(cpart, a1, a2);
        rowvec<<<E_SZ, 256>>>(Wo, bv, wv);
        dotscalar<<<1, 256>>>(bq, bk, cs);
        dotvec2<<<dim3(MT_ROWS / 8, 2), 256>>>(query, key, a1, a2, cs, u, w);
    }

    // M^T = WkT @ WqT^T  (split-K over HE) -> part -> half MTh
    gemm_h<0, false><<<dim3(E_SZ / 256, E_SZ / 128, NSPLIT), blk, GSMEM_BYTES>>>(
        WkT, WqT, nullptr, nullptr, nullptr, part, E_SZ, KC, HE_SZ, HE_SZ, 1.f,
        KC, KC, sEE, 0, 0);
    reduce_splits_h<<<(E_SZ * E_SZ / 4 + 255) / 256, 256>>>((float4*)part, MTh,
                                                            E_SZ * E_SZ / 4);
    // P = Woh @ WvT^T -> part -> half Ph
    gemm_h<0, false><<<dim3(E_SZ / 256, E_SZ / 128, NSPLIT), blk, GSMEM_BYTES>>>(
        Woh, WvT, nullptr, nullptr, nullptr, part, E_SZ, KC, HE_SZ, HE_SZ, 1.f,
        KC, KC, sEE, 0, 0);
    reduce_splits_h<<<(E_SZ * E_SZ / 4 + 255) / 256, 256>>>((float4*)part, Ph,
                                                            E_SZ * E_SZ / 4);

    // qM = qh @ MTh^T   [16384,512] (half out)
    gemm_h<0, true><<<dim3(E_SZ / 256, MT_ROWS / 128, 1), blk, GSMEM_BYTES>>>(
        qh, MTh, nullptr, nullptr, nullptr, qMh, E_SZ, E_SZ, E_SZ, E_SZ, 1.f,
        0, 0, 0, 0, 0);
    // vpT = Ph @ vh^T per batch  [512,2048] (half out)
    gemm_h<0, true><<<dim3(T_SZ / 256, E_SZ / 128, B_SZ), blk, GSMEM_BYTES>>>(
        Ph, vh, nullptr, nullptr, nullptr, vpTh, T_SZ, E_SZ, E_SZ, E_SZ, 1.f,
        0, sTE, sET, 0, 0);
    // logits: atth = h( SCALE*(qMh @ kh^T + u + w) ) per batch (HALF out)
    gemm_h<1, true><<<dim3(T_SZ / 256, T_SZ / 128, B_SZ), blk, GSMEM_BYTES>>>(
        qMh, kh, u, w, nullptr, atth, T_SZ, E_SZ, E_SZ, E_SZ, SCALE_F,
        sTE, sTE, sTT, T_SZ, T_SZ);
    // batch-axis softmax in place on atth + row sums
    softmax_rows<<<T_SZ, 512>>>(atth, rs);
    // out = atth @ vpTh^T + rs (x) wv + bo per batch (float out)
    gemm_h<2, false><<<dim3(E_SZ / 256, T_SZ / 128, B_SZ), blk, GSMEM_BYTES>>>(
        atth, vpTh, rs, wv, bo, out, E_SZ, T_SZ, T_SZ, T_SZ, 1.f,
        sTT, sET, sTE, T_SZ, 0);
}